// round 1
// baseline (speedup 1.0000x reference)
#include <cuda_runtime.h>
#include <cuda_bf16.h>

#define NN 2048
#define DMODEL 1024
#define NH 16
#define DKH 64
#define LN_EPS 1e-5f

// Scratch (device globals; allocation inside kernel_launch is forbidden)
__device__ float g_q[(size_t)NH * NN * DKH];
__device__ float g_k[(size_t)NH * NN * DKH];
__device__ float g_v[(size_t)NH * NN * DKH];
__device__ float g_concat[(size_t)NN * DMODEL];
__device__ float g_pre[(size_t)NN * DMODEL];

// ---------------------------------------------------------------------------
// QKV projection: out[h][n][k] = sum_d x[n][d] * w[(h*D + d)*DK + k] + bias[h*DK+k]
// Tile: 64 (n) x 64 (dk=all), BK=16, 256 threads, 4x4 per-thread micro-tile.
// ---------------------------------------------------------------------------
__global__ void __launch_bounds__(256) proj_kernel(const float* __restrict__ x,
                                                   const float* __restrict__ w,
                                                   const float* __restrict__ bias,
                                                   float* __restrict__ out)
{
    const int h  = blockIdx.y;
    const int n0 = blockIdx.x * 64;
    const int tid = threadIdx.x;
    const int tx = tid & 15, ty = tid >> 4;

    __shared__ float xsT[16][64];  // [kk][row]
    __shared__ float wsm[16][64];  // [kk][col]

    float acc[4][4] = {};

    for (int d0 = 0; d0 < DMODEL; d0 += 16) {
        #pragma unroll
        for (int i = 0; i < 4; i++) {
            int lin = tid + i * 256;          // 0..1023
            int row = lin >> 4, kk = lin & 15;
            xsT[kk][row] = x[(size_t)(n0 + row) * DMODEL + d0 + kk];
        }
        #pragma unroll
        for (int i = 0; i < 4; i++) {
            int lin = tid + i * 256;
            int kk = lin >> 6, col = lin & 63;
            wsm[kk][col] = w[(size_t)(h * DMODEL + d0 + kk) * DKH + col];
        }
        __syncthreads();
        #pragma unroll
        for (int kk = 0; kk < 16; kk++) {
            float4 av = *(const float4*)&xsT[kk][ty * 4];
            float4 bv = *(const float4*)&wsm[kk][tx * 4];
            float a[4] = {av.x, av.y, av.z, av.w};
            float b[4] = {bv.x, bv.y, bv.z, bv.w};
            #pragma unroll
            for (int i = 0; i < 4; i++)
                #pragma unroll
                for (int j = 0; j < 4; j++)
                    acc[i][j] += a[i] * b[j];
        }
        __syncthreads();
    }

    #pragma unroll
    for (int i = 0; i < 4; i++) {
        int row = n0 + ty * 4 + i;
        #pragma unroll
        for (int j = 0; j < 4; j++) {
            int col = tx * 4 + j;
            out[((size_t)h * NN + row) * DKH + col] = acc[i][j] + bias[h * DKH + col];
        }
    }
}

// ---------------------------------------------------------------------------
// Flash-style attention, one head / 64-query block per CTA.
// Key tile = 32. Online softmax; row reductions via shfl within 16-lane groups.
// concat[n][h*64+k] output layout.
// ---------------------------------------------------------------------------
__global__ void __launch_bounds__(256) attn_kernel(const float* __restrict__ q,
                                                   const float* __restrict__ k,
                                                   const float* __restrict__ v,
                                                   float* __restrict__ concat)
{
    const int h  = blockIdx.y;
    const int n0 = blockIdx.x * 64;
    const int tid = threadIdx.x;
    const int tx = tid & 15, ty = tid >> 4;

    __shared__ float Qs[64][64];
    __shared__ float Ks[32][64];
    __shared__ float Vs[32][64];
    __shared__ float Ps[64][33];

    const float* qh = q + (size_t)h * NN * DKH;
    const float* kh = k + (size_t)h * NN * DKH;
    const float* vh = v + (size_t)h * NN * DKH;

    // Load Q tile, pre-scaled by 1/sqrt(dk)=0.125
    #pragma unroll
    for (int i = 0; i < 16; i++) {
        int lin = tid + i * 256;
        int row = lin >> 6, col = lin & 63;
        Qs[row][col] = qh[(size_t)(n0 + row) * DKH + col] * 0.125f;
    }

    float m[4], l[4], o[4][4];
    #pragma unroll
    for (int i = 0; i < 4; i++) {
        m[i] = -1e30f; l[i] = 0.f;
        #pragma unroll
        for (int j = 0; j < 4; j++) o[i][j] = 0.f;
    }
    __syncthreads();

    for (int t0 = 0; t0 < NN; t0 += 32) {
        #pragma unroll
        for (int i = 0; i < 8; i++) {
            int lin = tid + i * 256;
            int row = lin >> 6, col = lin & 63;
            Ks[row][col] = kh[(size_t)(t0 + row) * DKH + col];
            Vs[row][col] = vh[(size_t)(t0 + row) * DKH + col];
        }
        __syncthreads();

        // S = Q K^T   (rows ty*4+i, key-cols tx*2+j)
        float s[4][2] = {};
        #pragma unroll
        for (int kk = 0; kk < 64; kk += 4) {
            float4 a[4], b[2];
            #pragma unroll
            for (int i = 0; i < 4; i++) a[i] = *(const float4*)&Qs[ty * 4 + i][kk];
            #pragma unroll
            for (int j = 0; j < 2; j++) b[j] = *(const float4*)&Ks[tx * 2 + j][kk];
            #pragma unroll
            for (int i = 0; i < 4; i++)
                #pragma unroll
                for (int j = 0; j < 2; j++)
                    s[i][j] += a[i].x * b[j].x + a[i].y * b[j].y +
                               a[i].z * b[j].z + a[i].w * b[j].w;
        }

        // Online softmax per query row (16 lanes own one row's 32 key cols)
        #pragma unroll
        for (int i = 0; i < 4; i++) {
            float rmax = fmaxf(s[i][0], s[i][1]);
            #pragma unroll
            for (int d = 8; d >= 1; d >>= 1)
                rmax = fmaxf(rmax, __shfl_xor_sync(0xffffffffu, rmax, d));
            float mnew = fmaxf(m[i], rmax);
            float c  = __expf(m[i] - mnew);
            float p0 = __expf(s[i][0] - mnew);
            float p1 = __expf(s[i][1] - mnew);
            Ps[ty * 4 + i][tx * 2 + 0] = p0;
            Ps[ty * 4 + i][tx * 2 + 1] = p1;
            float rsum = p0 + p1;
            #pragma unroll
            for (int d = 8; d >= 1; d >>= 1)
                rsum += __shfl_xor_sync(0xffffffffu, rsum, d);
            l[i] = l[i] * c + rsum;
            m[i] = mnew;
            #pragma unroll
            for (int j = 0; j < 4; j++) o[i][j] *= c;
        }
        __syncwarp();  // Ps rows are produced & consumed within the same warp

        // O += P V   (rows ty*4+i, dk-cols tx*4+j)
        #pragma unroll
        for (int jj = 0; jj < 32; jj++) {
            float4 bv = *(const float4*)&Vs[jj][tx * 4];
            #pragma unroll
            for (int i = 0; i < 4; i++) {
                float p = Ps[ty * 4 + i][jj];
                o[i][0] += p * bv.x; o[i][1] += p * bv.y;
                o[i][2] += p * bv.z; o[i][3] += p * bv.w;
            }
        }
        __syncthreads();  // protect Ks/Vs before next tile's load
    }

    #pragma unroll
    for (int i = 0; i < 4; i++) {
        float inv = 1.0f / l[i];
        int row = n0 + ty * 4 + i;
        #pragma unroll
        for (int j = 0; j < 4; j++)
            concat[(size_t)row * DMODEL + h * DKH + tx * 4 + j] = o[i][j] * inv;
    }
}

// ---------------------------------------------------------------------------
// Out projection + bias + residual: pre[n][d] = concat[n]·wo[:,d] + ob[d] + x[n][d]
// ---------------------------------------------------------------------------
__global__ void __launch_bounds__(256) outproj_kernel(const float* __restrict__ concat,
                                                      const float* __restrict__ x,
                                                      const float* __restrict__ wo,
                                                      const float* __restrict__ ob,
                                                      float* __restrict__ out)
{
    const int n0 = blockIdx.x * 64;
    const int c0 = blockIdx.y * 64;
    const int tid = threadIdx.x;
    const int tx = tid & 15, ty = tid >> 4;

    __shared__ float csT[16][64];  // [kk][row]
    __shared__ float wsm[16][64];  // [kk][col]

    float acc[4][4] = {};

    for (int e0 = 0; e0 < DMODEL; e0 += 16) {
        #pragma unroll
        for (int i = 0; i < 4; i++) {
            int lin = tid + i * 256;
            int row = lin >> 4, kk = lin & 15;
            csT[kk][row] = concat[(size_t)(n0 + row) * DMODEL + e0 + kk];
        }
        #pragma unroll
        for (int i = 0; i < 4; i++) {
            int lin = tid + i * 256;
            int kk = lin >> 6, col = lin & 63;
            wsm[kk][col] = wo[(size_t)(e0 + kk) * DMODEL + c0 + col];
        }
        __syncthreads();
        #pragma unroll
        for (int kk = 0; kk < 16; kk++) {
            float4 av = *(const float4*)&csT[kk][ty * 4];
            float4 bv = *(const float4*)&wsm[kk][tx * 4];
            float a[4] = {av.x, av.y, av.z, av.w};
            float b[4] = {bv.x, bv.y, bv.z, bv.w};
            #pragma unroll
            for (int i = 0; i < 4; i++)
                #pragma unroll
                for (int j = 0; j < 4; j++)
                    acc[i][j] += a[i] * b[j];
        }
        __syncthreads();
    }

    #pragma unroll
    for (int i = 0; i < 4; i++) {
        int row = n0 + ty * 4 + i;
        #pragma unroll
        for (int j = 0; j < 4; j++) {
            int col = c0 + tx * 4 + j;
            out[(size_t)row * DMODEL + col] =
                acc[i][j] + ob[col] + x[(size_t)row * DMODEL + col];
        }
    }
}

// ---------------------------------------------------------------------------
// LayerNorm, one block per row (256 threads x float4 = 1024 elems)
// ---------------------------------------------------------------------------
__global__ void __launch_bounds__(256) ln_kernel(const float* __restrict__ pre,
                                                 const float* __restrict__ alpha,
                                                 const float* __restrict__ beta,
                                                 float* __restrict__ out)
{
    const int row = blockIdx.x;
    const int tid = threadIdx.x;
    const float4 v = ((const float4*)(pre + (size_t)row * DMODEL))[tid];

    float sum = v.x + v.y + v.z + v.w;
    float sq  = v.x * v.x + v.y * v.y + v.z * v.z + v.w * v.w;

    #pragma unroll
    for (int d = 16; d >= 1; d >>= 1) {
        sum += __shfl_xor_sync(0xffffffffu, sum, d);
        sq  += __shfl_xor_sync(0xffffffffu, sq,  d);
    }

    __shared__ float ssum[8], ssq[8];
    __shared__ float s_mu, s_rstd;
    int warp = tid >> 5, lane = tid & 31;
    if (lane == 0) { ssum[warp] = sum; ssq[warp] = sq; }
    __syncthreads();
    if (tid == 0) {
        float ts = 0.f, tq = 0.f;
        #pragma unroll
        for (int i = 0; i < 8; i++) { ts += ssum[i]; tq += ssq[i]; }
        float mu  = ts * (1.0f / DMODEL);
        float var = tq * (1.0f / DMODEL) - mu * mu;
        s_mu = mu;
        s_rstd = rsqrtf(var + LN_EPS);
    }
    __syncthreads();

    const float mu = s_mu, rstd = s_rstd;
    const float4 a4 = ((const float4*)alpha)[tid];
    const float4 b4 = ((const float4*)beta)[tid];
    float4 r;
    r.x = a4.x * (v.x - mu) * rstd + b4.x;
    r.y = a4.y * (v.y - mu) * rstd + b4.y;
    r.z = a4.z * (v.z - mu) * rstd + b4.z;
    r.w = a4.w * (v.w - mu) * rstd + b4.w;
    ((float4*)(out + (size_t)row * DMODEL))[tid] = r;
}

// ---------------------------------------------------------------------------
extern "C" void kernel_launch(void* const* d_in, const int* in_sizes, int n_in,
                              void* d_out, int out_size)
{
    const float* x     = (const float*)d_in[0];
    const float* wq    = (const float*)d_in[1];
    const float* qb    = (const float*)d_in[2];
    const float* wk    = (const float*)d_in[3];
    const float* kb    = (const float*)d_in[4];
    const float* wv    = (const float*)d_in[5];
    const float* vb    = (const float*)d_in[6];
    const float* wo    = (const float*)d_in[7];
    const float* ob    = (const float*)d_in[8];
    const float* alpha = (const float*)d_in[9];
    const float* beta  = (const float*)d_in[10];
    float* out = (float*)d_out;

    float *q, *k, *v, *concat, *pre;
    cudaGetSymbolAddress((void**)&q,      g_q);
    cudaGetSymbolAddress((void**)&k,      g_k);
    cudaGetSymbolAddress((void**)&v,      g_v);
    cudaGetSymbolAddress((void**)&concat, g_concat);
    cudaGetSymbolAddress((void**)&pre,    g_pre);

    dim3 gproj(NN / 64, NH);
    proj_kernel<<<gproj, 256>>>(x, wq, qb, q);
    proj_kernel<<<gproj, 256>>>(x, wk, kb, k);
    proj_kernel<<<gproj, 256>>>(x, wv, vb, v);

    attn_kernel<<<dim3(NN / 64, NH), 256>>>(q, k, v, concat);

    outproj_kernel<<<dim3(NN / 64, DMODEL / 64), 256>>>(concat, x, wo, ob, pre);

    ln_kernel<<<NN, 256>>>(pre, alpha, beta, out);
}

// round 2
// speedup vs baseline: 4.1190x; 4.1190x over previous
#include <cuda_runtime.h>
#include <cstdint>

#define NN 2048
#define DMODEL 1024
#define NH 16
#define DKH 64
#define LN_EPS 1e-5f

// Scratch (device globals; allocation inside kernel_launch is forbidden)
__device__ float g_q[(size_t)NH * NN * DKH];
__device__ float g_k[(size_t)NH * NN * DKH];
__device__ float g_v[(size_t)NH * NN * DKH];
__device__ float g_concat[(size_t)NN * DMODEL];
__device__ float g_pre[(size_t)NN * DMODEL];

// ---------------------------------------------------------------------------
// TF32 helpers
// ---------------------------------------------------------------------------
__device__ __forceinline__ uint32_t cvt_tf32(float x) {
    uint32_t r;
    asm("cvt.rna.tf32.f32 %0, %1;" : "=r"(r) : "f"(x));
    return r;
}
__device__ __forceinline__ void split_tf32(float x, uint32_t& hi, uint32_t& lo) {
    uint32_t h = cvt_tf32(x);
    hi = h;
    lo = cvt_tf32(x - __uint_as_float(h));
}
// D += A * B, m16n8k8 tf32
__device__ __forceinline__ void mma_tf32(float* c, const uint32_t* a, const uint32_t* b) {
    asm volatile(
        "mma.sync.aligned.m16n8k8.row.col.f32.tf32.tf32.f32 "
        "{%0,%1,%2,%3}, {%4,%5,%6,%7}, {%8,%9}, {%0,%1,%2,%3};\n"
        : "+f"(c[0]), "+f"(c[1]), "+f"(c[2]), "+f"(c[3])
        : "r"(a[0]), "r"(a[1]), "r"(a[2]), "r"(a[3]),
          "r"(b[0]), "r"(b[1]));
}

// ---------------------------------------------------------------------------
// QKV projection (tensor-core). One CTA: 128 rows x 64 cols (full dk).
// 8 warps, each warp -> 16 rows x 64 cols via m16n8k8 fragments.
// three!=0 -> 3xTF32 (near-fp32); three==0 -> single TF32.
// smem: Xh/Xl [128][36], Wh/Wl [32][72]  (dynamic, 55296 B)
// ---------------------------------------------------------------------------
#define PROJ_SMEM ((2 * 128 * 36 + 2 * 32 * 72) * 4)

__global__ void __launch_bounds__(256) proj_mma_kernel(const float* __restrict__ x,
                                                       const float* __restrict__ w,
                                                       const float* __restrict__ bias,
                                                       float* __restrict__ out,
                                                       int three)
{
    extern __shared__ uint32_t sm[];
    uint32_t* Xh = sm;                 // 128*36
    uint32_t* Xl = Xh + 128 * 36;
    uint32_t* Wh = Xl + 128 * 36;      // 32*72
    uint32_t* Wl = Wh + 32 * 72;

    const int m0 = blockIdx.x * 128;
    const int h  = blockIdx.y;
    const int tid = threadIdx.x;
    const int wid = tid >> 5, lane = tid & 31, g = lane >> 2, qt = lane & 3;
    const float* wp = w + (size_t)h * DMODEL * DKH;

    float acc[8][4] = {};

    // prefetch chunk 0
    float4 xr[4], wr[2];
    #pragma unroll
    for (int i = 0; i < 4; i++) {
        int fg = tid + i * 256;                 // 0..1023
        int row = fg >> 3, c4 = (fg & 7) * 4;   // [128][32]
        xr[i] = *(const float4*)(x + (size_t)(m0 + row) * DMODEL + c4);
    }
    #pragma unroll
    for (int i = 0; i < 2; i++) {
        int fg = tid + i * 256;                 // 0..511
        int row = fg >> 4, c4 = (fg & 15) * 4;  // [32][64]
        wr[i] = *(const float4*)(wp + (size_t)row * DKH + c4);
    }

    for (int kc = 0; kc < DMODEL; kc += 32) {
        // store current chunk (split hi/lo)
        #pragma unroll
        for (int i = 0; i < 4; i++) {
            int fg = tid + i * 256;
            int row = fg >> 3, c4 = (fg & 7) * 4;
            uint4 hv, lv;
            split_tf32(xr[i].x, hv.x, lv.x);
            split_tf32(xr[i].y, hv.y, lv.y);
            split_tf32(xr[i].z, hv.z, lv.z);
            split_tf32(xr[i].w, hv.w, lv.w);
            *(uint4*)&Xh[row * 36 + c4] = hv;
            *(uint4*)&Xl[row * 36 + c4] = lv;
        }
        #pragma unroll
        for (int i = 0; i < 2; i++) {
            int fg = tid + i * 256;
            int row = fg >> 4, c4 = (fg & 15) * 4;
            uint4 hv, lv;
            split_tf32(wr[i].x, hv.x, lv.x);
            split_tf32(wr[i].y, hv.y, lv.y);
            split_tf32(wr[i].z, hv.z, lv.z);
            split_tf32(wr[i].w, hv.w, lv.w);
            *(uint4*)&Wh[row * 72 + c4] = hv;
            *(uint4*)&Wl[row * 72 + c4] = lv;
        }
        __syncthreads();

        // prefetch next chunk
        if (kc + 32 < DMODEL) {
            #pragma unroll
            for (int i = 0; i < 4; i++) {
                int fg = tid + i * 256;
                int row = fg >> 3, c4 = (fg & 7) * 4;
                xr[i] = *(const float4*)(x + (size_t)(m0 + row) * DMODEL + kc + 32 + c4);
            }
            #pragma unroll
            for (int i = 0; i < 2; i++) {
                int fg = tid + i * 256;
                int row = fg >> 4, c4 = (fg & 15) * 4;
                wr[i] = *(const float4*)(wp + (size_t)(kc + 32 + row) * DKH + c4);
            }
        }

        // compute: 4 k-steps x 8 n-blocks
        #pragma unroll
        for (int ks = 0; ks < 4; ks++) {
            const int r0 = wid * 16 + g, col = ks * 8 + qt;
            uint32_t ah[4], al[4];
            ah[0] = Xh[r0 * 36 + col];       ah[1] = Xh[(r0 + 8) * 36 + col];
            ah[2] = Xh[r0 * 36 + col + 4];   ah[3] = Xh[(r0 + 8) * 36 + col + 4];
            al[0] = Xl[r0 * 36 + col];       al[1] = Xl[(r0 + 8) * 36 + col];
            al[2] = Xl[r0 * 36 + col + 4];   al[3] = Xl[(r0 + 8) * 36 + col + 4];
            #pragma unroll
            for (int nb = 0; nb < 8; nb++) {
                uint32_t bh[2], bl[2];
                const int kr = (ks * 8 + qt) * 72 + nb * 8 + g;
                bh[0] = Wh[kr]; bh[1] = Wh[kr + 4 * 72];
                bl[0] = Wl[kr]; bl[1] = Wl[kr + 4 * 72];
                mma_tf32(acc[nb], ah, bh);
                if (three) {
                    mma_tf32(acc[nb], ah, bl);
                    mma_tf32(acc[nb], al, bh);
                }
            }
        }
        __syncthreads();
    }

    // epilogue: + bias, out[(h*NN + row)*64 + col]
    const int r0 = m0 + wid * 16 + g;
    #pragma unroll
    for (int nb = 0; nb < 8; nb++) {
        int col = nb * 8 + 2 * qt;
        float b0 = bias[h * DKH + col], b1 = bias[h * DKH + col + 1];
        float2 v0 = make_float2(acc[nb][0] + b0, acc[nb][1] + b1);
        float2 v1 = make_float2(acc[nb][2] + b0, acc[nb][3] + b1);
        *(float2*)&out[((size_t)h * NN + r0) * DKH + col]     = v0;
        *(float2*)&out[((size_t)h * NN + r0 + 8) * DKH + col] = v1;
    }
}

// ---------------------------------------------------------------------------
// Flash attention (tensor-core). One CTA: head h, 128 queries.
// 8 warps x 16 rows. Key tile = 32. QK^T in 3xTF32, PV in 1xTF32.
// smem: Qh/Ql [128][68], Kh/Kl [32][68], Vs [32][72]  (dynamic, 96256 B)
// ---------------------------------------------------------------------------
#define ATTN_SMEM ((2 * 128 * 68 + 2 * 32 * 68 + 32 * 72) * 4)

__global__ void __launch_bounds__(256, 2) attn_mma_kernel(const float* __restrict__ q,
                                                          const float* __restrict__ k,
                                                          const float* __restrict__ v,
                                                          float* __restrict__ concat)
{
    extern __shared__ uint32_t sm[];
    uint32_t* Qh = sm;                   // 128*68
    uint32_t* Ql = Qh + 128 * 68;
    uint32_t* Kh = Ql + 128 * 68;        // 32*68
    uint32_t* Kl = Kh + 32 * 68;
    uint32_t* Vs = Kl + 32 * 68;         // 32*72

    const int h  = blockIdx.y;
    const int q0 = blockIdx.x * 128;
    const int tid = threadIdx.x;
    const int wid = tid >> 5, lane = tid & 31, g = lane >> 2, qt = lane & 3;

    const float* qp = q + ((size_t)h * NN + q0) * DKH;
    const float* kp = k + (size_t)h * NN * DKH;
    const float* vp = v + (size_t)h * NN * DKH;

    // Q tile -> smem (hi/lo), pre-scaled by 1/sqrt(dk)=0.125
    #pragma unroll
    for (int i = 0; i < 8; i++) {
        int fg = tid + i * 256;                 // 0..2047
        int row = fg >> 4, c4 = (fg & 15) * 4;  // [128][64]
        float4 xv = *(const float4*)(qp + (size_t)row * DKH + c4);
        xv.x *= 0.125f; xv.y *= 0.125f; xv.z *= 0.125f; xv.w *= 0.125f;
        uint4 hv, lv;
        split_tf32(xv.x, hv.x, lv.x);
        split_tf32(xv.y, hv.y, lv.y);
        split_tf32(xv.z, hv.z, lv.z);
        split_tf32(xv.w, hv.w, lv.w);
        *(uint4*)&Qh[row * 68 + c4] = hv;
        *(uint4*)&Ql[row * 68 + c4] = lv;
    }

    float o[8][4] = {};
    float m0 = -1e30f, m1 = -1e30f, l0 = 0.f, l1 = 0.f;

    // prefetch key/value tile 0
    float4 kreg[2], vreg[2];
    #pragma unroll
    for (int i = 0; i < 2; i++) {
        int fg = tid + i * 256;                 // 0..511
        int row = fg >> 4, c4 = (fg & 15) * 4;  // [32][64]
        kreg[i] = *(const float4*)(kp + (size_t)row * DKH + c4);
        vreg[i] = *(const float4*)(vp + (size_t)row * DKH + c4);
    }

    for (int t = 0; t < NN / 32; t++) {
        // store current tile (K split hi/lo, V single tf32)
        #pragma unroll
        for (int i = 0; i < 2; i++) {
            int fg = tid + i * 256;
            int row = fg >> 4, c4 = (fg & 15) * 4;
            uint4 hv, lv;
            split_tf32(kreg[i].x, hv.x, lv.x);
            split_tf32(kreg[i].y, hv.y, lv.y);
            split_tf32(kreg[i].z, hv.z, lv.z);
            split_tf32(kreg[i].w, hv.w, lv.w);
            *(uint4*)&Kh[row * 68 + c4] = hv;
            *(uint4*)&Kl[row * 68 + c4] = lv;
            uint4 vv;
            vv.x = cvt_tf32(vreg[i].x); vv.y = cvt_tf32(vreg[i].y);
            vv.z = cvt_tf32(vreg[i].z); vv.w = cvt_tf32(vreg[i].w);
            *(uint4*)&Vs[row * 72 + c4] = vv;
        }
        __syncthreads();

        // prefetch next tile
        if (t + 1 < NN / 32) {
            #pragma unroll
            for (int i = 0; i < 2; i++) {
                int fg = tid + i * 256;
                int row = fg >> 4, c4 = (fg & 15) * 4;
                kreg[i] = *(const float4*)(kp + (size_t)((t + 1) * 32 + row) * DKH + c4);
                vreg[i] = *(const float4*)(vp + (size_t)((t + 1) * 32 + row) * DKH + c4);
            }
        }

        // S = Q K^T (3xTF32): 8 k-steps x 4 key-blocks
        float s[4][4] = {};
        #pragma unroll
        for (int ks = 0; ks < 8; ks++) {
            const int r0 = wid * 16 + g, col = ks * 8 + qt;
            uint32_t ah[4], al[4];
            ah[0] = Qh[r0 * 68 + col];       ah[1] = Qh[(r0 + 8) * 68 + col];
            ah[2] = Qh[r0 * 68 + col + 4];   ah[3] = Qh[(r0 + 8) * 68 + col + 4];
            al[0] = Ql[r0 * 68 + col];       al[1] = Ql[(r0 + 8) * 68 + col];
            al[2] = Ql[r0 * 68 + col + 4];   al[3] = Ql[(r0 + 8) * 68 + col + 4];
            #pragma unroll
            for (int nb = 0; nb < 4; nb++) {
                uint32_t bh[2], bl[2];
                const int kr = (nb * 8 + g) * 68 + col;
                bh[0] = Kh[kr]; bh[1] = Kh[kr + 4];
                bl[0] = Kl[kr]; bl[1] = Kl[kr + 4];
                mma_tf32(s[nb], ah, bh);
                mma_tf32(s[nb], ah, bl);
                mma_tf32(s[nb], al, bh);
            }
        }

        // online softmax: row g uses c0,c1; row g+8 uses c2,c3
        float mx0 = fmaxf(fmaxf(fmaxf(s[0][0], s[0][1]), fmaxf(s[1][0], s[1][1])),
                          fmaxf(fmaxf(s[2][0], s[2][1]), fmaxf(s[3][0], s[3][1])));
        float mx1 = fmaxf(fmaxf(fmaxf(s[0][2], s[0][3]), fmaxf(s[1][2], s[1][3])),
                          fmaxf(fmaxf(s[2][2], s[2][3]), fmaxf(s[3][2], s[3][3])));
        mx0 = fmaxf(mx0, __shfl_xor_sync(0xffffffffu, mx0, 1));
        mx0 = fmaxf(mx0, __shfl_xor_sync(0xffffffffu, mx0, 2));
        mx1 = fmaxf(mx1, __shfl_xor_sync(0xffffffffu, mx1, 1));
        mx1 = fmaxf(mx1, __shfl_xor_sync(0xffffffffu, mx1, 2));

        float nm0 = fmaxf(m0, mx0), nm1 = fmaxf(m1, mx1);
        float sc0 = __expf(m0 - nm0), sc1 = __expf(m1 - nm1);
        float sum0 = 0.f, sum1 = 0.f;
        #pragma unroll
        for (int nb = 0; nb < 4; nb++) {
            s[nb][0] = __expf(s[nb][0] - nm0);
            s[nb][1] = __expf(s[nb][1] - nm0);
            s[nb][2] = __expf(s[nb][2] - nm1);
            s[nb][3] = __expf(s[nb][3] - nm1);
            sum0 += s[nb][0] + s[nb][1];
            sum1 += s[nb][2] + s[nb][3];
        }
        sum0 += __shfl_xor_sync(0xffffffffu, sum0, 1);
        sum0 += __shfl_xor_sync(0xffffffffu, sum0, 2);
        sum1 += __shfl_xor_sync(0xffffffffu, sum1, 1);
        sum1 += __shfl_xor_sync(0xffffffffu, sum1, 2);
        l0 = l0 * sc0 + sum0;  m0 = nm0;
        l1 = l1 * sc1 + sum1;  m1 = nm1;
        #pragma unroll
        for (int nb = 0; nb < 8; nb++) {
            o[nb][0] *= sc0; o[nb][1] *= sc0;
            o[nb][2] *= sc1; o[nb][3] *= sc1;
        }

        // O += P V : relayout P C-frags into A-frags via shuffles
        const int srcA = (lane & ~3) | (qt >> 1);
        const int srcB = srcA + 2;
        const bool odd = (qt & 1) != 0;
        #pragma unroll
        for (int c = 0; c < 4; c++) {
            float c0A = __shfl_sync(0xffffffffu, s[c][0], srcA);
            float c1A = __shfl_sync(0xffffffffu, s[c][1], srcA);
            float c2A = __shfl_sync(0xffffffffu, s[c][2], srcA);
            float c3A = __shfl_sync(0xffffffffu, s[c][3], srcA);
            float c0B = __shfl_sync(0xffffffffu, s[c][0], srcB);
            float c1B = __shfl_sync(0xffffffffu, s[c][1], srcB);
            float c2B = __shfl_sync(0xffffffffu, s[c][2], srcB);
            float c3B = __shfl_sync(0xffffffffu, s[c][3], srcB);
            uint32_t a[4];
            a[0] = cvt_tf32(odd ? c1A : c0A);
            a[1] = cvt_tf32(odd ? c3A : c2A);
            a[2] = cvt_tf32(odd ? c1B : c0B);
            a[3] = cvt_tf32(odd ? c3B : c2B);
            #pragma unroll
            for (int nb = 0; nb < 8; nb++) {
                uint32_t b[2];
                b[0] = Vs[(c * 8 + qt) * 72 + nb * 8 + g];
                b[1] = Vs[(c * 8 + qt + 4) * 72 + nb * 8 + g];
                mma_tf32(o[nb], a, b);
            }
        }
        __syncthreads();
    }

    // epilogue: normalize by l, write concat[n][h*64+k]
    const float inv0 = 1.0f / l0, inv1 = 1.0f / l1;
    const int r0 = q0 + wid * 16 + g;
    #pragma unroll
    for (int nb = 0; nb < 8; nb++) {
        int col = h * DKH + nb * 8 + 2 * qt;
        float2 v0 = make_float2(o[nb][0] * inv0, o[nb][1] * inv0);
        float2 v1 = make_float2(o[nb][2] * inv1, o[nb][3] * inv1);
        *(float2*)&concat[(size_t)r0 * DMODEL + col]       = v0;
        *(float2*)&concat[(size_t)(r0 + 8) * DMODEL + col] = v1;
    }
}

// ---------------------------------------------------------------------------
// Out projection + bias + residual (single TF32). CTA: 128 rows x 64 cols.
// smem static: Ch [128][36], Wh [32][72]  (27648 B)
// ---------------------------------------------------------------------------
__global__ void __launch_bounds__(256) outproj_mma_kernel(const float* __restrict__ concat,
                                                          const float* __restrict__ x,
                                                          const float* __restrict__ wo,
                                                          const float* __restrict__ ob,
                                                          float* __restrict__ out)
{
    __shared__ uint32_t Ch[128 * 36];
    __shared__ uint32_t Wh[32 * 72];

    const int m0 = blockIdx.x * 128;
    const int c0 = blockIdx.y * 64;
    const int tid = threadIdx.x;
    const int wid = tid >> 5, lane = tid & 31, g = lane >> 2, qt = lane & 3;

    float acc[8][4] = {};

    float4 xr[4], wr[2];
    #pragma unroll
    for (int i = 0; i < 4; i++) {
        int fg = tid + i * 256;
        int row = fg >> 3, c4 = (fg & 7) * 4;
        xr[i] = *(const float4*)(concat + (size_t)(m0 + row) * DMODEL + c4);
    }
    #pragma unroll
    for (int i = 0; i < 2; i++) {
        int fg = tid + i * 256;
        int row = fg >> 4, c4 = (fg & 15) * 4;
        wr[i] = *(const float4*)(wo + (size_t)row * DMODEL + c0 + c4);
    }

    for (int kc = 0; kc < DMODEL; kc += 32) {
        #pragma unroll
        for (int i = 0; i < 4; i++) {
            int fg = tid + i * 256;
            int row = fg >> 3, c4 = (fg & 7) * 4;
            uint4 hv;
            hv.x = cvt_tf32(xr[i].x); hv.y = cvt_tf32(xr[i].y);
            hv.z = cvt_tf32(xr[i].z); hv.w = cvt_tf32(xr[i].w);
            *(uint4*)&Ch[row * 36 + c4] = hv;
        }
        #pragma unroll
        for (int i = 0; i < 2; i++) {
            int fg = tid + i * 256;
            int row = fg >> 4, c4 = (fg & 15) * 4;
            uint4 hv;
            hv.x = cvt_tf32(wr[i].x); hv.y = cvt_tf32(wr[i].y);
            hv.z = cvt_tf32(wr[i].z); hv.w = cvt_tf32(wr[i].w);
            *(uint4*)&Wh[row * 72 + c4] = hv;
        }
        __syncthreads();

        if (kc + 32 < DMODEL) {
            #pragma unroll
            for (int i = 0; i < 4; i++) {
                int fg = tid + i * 256;
                int row = fg >> 3, c4 = (fg & 7) * 4;
                xr[i] = *(const float4*)(concat + (size_t)(m0 + row) * DMODEL + kc + 32 + c4);
            }
            #pragma unroll
            for (int i = 0; i < 2; i++) {
                int fg = tid + i * 256;
                int row = fg >> 4, c4 = (fg & 15) * 4;
                wr[i] = *(const float4*)(wo + (size_t)(kc + 32 + row) * DMODEL + c0 + c4);
            }
        }

        #pragma unroll
        for (int ks = 0; ks < 4; ks++) {
            const int r0 = wid * 16 + g, col = ks * 8 + qt;
            uint32_t a[4];
            a[0] = Ch[r0 * 36 + col];       a[1] = Ch[(r0 + 8) * 36 + col];
            a[2] = Ch[r0 * 36 + col + 4];   a[3] = Ch[(r0 + 8) * 36 + col + 4];
            #pragma unroll
            for (int nb = 0; nb < 8; nb++) {
                uint32_t b[2];
                const int kr = (ks * 8 + qt) * 72 + nb * 8 + g;
                b[0] = Wh[kr]; b[1] = Wh[kr + 4 * 72];
                mma_tf32(acc[nb], a, b);
            }
        }
        __syncthreads();
    }

    const int r0 = m0 + wid * 16 + g;
    #pragma unroll
    for (int nb = 0; nb < 8; nb++) {
        int col = c0 + nb * 8 + 2 * qt;
        float b0 = ob[col], b1 = ob[col + 1];
        const float* xr0 = &x[(size_t)r0 * DMODEL + col];
        const float* xr1 = &x[(size_t)(r0 + 8) * DMODEL + col];
        float2 v0 = make_float2(acc[nb][0] + b0 + xr0[0], acc[nb][1] + b1 + xr0[1]);
        float2 v1 = make_float2(acc[nb][2] + b0 + xr1[0], acc[nb][3] + b1 + xr1[1]);
        *(float2*)&out[(size_t)r0 * DMODEL + col]       = v0;
        *(float2*)&out[(size_t)(r0 + 8) * DMODEL + col] = v1;
    }
}

// ---------------------------------------------------------------------------
// LayerNorm, one block per row
// ---------------------------------------------------------------------------
__global__ void __launch_bounds__(256) ln_kernel(const float* __restrict__ pre,
                                                 const float* __restrict__ alpha,
                                                 const float* __restrict__ beta,
                                                 float* __restrict__ out)
{
    const int row = blockIdx.x;
    const int tid = threadIdx.x;
    const float4 v = ((const float4*)(pre + (size_t)row * DMODEL))[tid];

    float sum = v.x + v.y + v.z + v.w;
    float sq  = v.x * v.x + v.y * v.y + v.z * v.z + v.w * v.w;

    #pragma unroll
    for (int d = 16; d >= 1; d >>= 1) {
        sum += __shfl_xor_sync(0xffffffffu, sum, d);
        sq  += __shfl_xor_sync(0xffffffffu, sq,  d);
    }

    __shared__ float ssum[8], ssq[8];
    __shared__ float s_mu, s_rstd;
    int warp = tid >> 5, lane = tid & 31;
    if (lane == 0) { ssum[warp] = sum; ssq[warp] = sq; }
    __syncthreads();
    if (tid == 0) {
        float ts = 0.f, tq = 0.f;
        #pragma unroll
        for (int i = 0; i < 8; i++) { ts += ssum[i]; tq += ssq[i]; }
        float mu  = ts * (1.0f / DMODEL);
        float var = tq * (1.0f / DMODEL) - mu * mu;
        s_mu = mu;
        s_rstd = rsqrtf(var + LN_EPS);
    }
    __syncthreads();

    const float mu = s_mu, rstd = s_rstd;
    const float4 a4 = ((const float4*)alpha)[tid];
    const float4 b4 = ((const float4*)beta)[tid];
    float4 r;
    r.x = a4.x * (v.x - mu) * rstd + b4.x;
    r.y = a4.y * (v.y - mu) * rstd + b4.y;
    r.z = a4.z * (v.z - mu) * rstd + b4.z;
    r.w = a4.w * (v.w - mu) * rstd + b4.w;
    ((float4*)(out + (size_t)row * DMODEL))[tid] = r;
}

// ---------------------------------------------------------------------------
extern "C" void kernel_launch(void* const* d_in, const int* in_sizes, int n_in,
                              void* d_out, int out_size)
{
    const float* x     = (const float*)d_in[0];
    const float* wq    = (const float*)d_in[1];
    const float* qb    = (const float*)d_in[2];
    const float* wk    = (const float*)d_in[3];
    const float* kb    = (const float*)d_in[4];
    const float* wv    = (const float*)d_in[5];
    const float* vb    = (const float*)d_in[6];
    const float* wo    = (const float*)d_in[7];
    const float* ob    = (const float*)d_in[8];
    const float* alpha = (const float*)d_in[9];
    const float* beta  = (const float*)d_in[10];
    float* out = (float*)d_out;

    float *q, *k, *v, *concat, *pre;
    cudaGetSymbolAddress((void**)&q,      g_q);
    cudaGetSymbolAddress((void**)&k,      g_k);
    cudaGetSymbolAddress((void**)&v,      g_v);
    cudaGetSymbolAddress((void**)&concat, g_concat);
    cudaGetSymbolAddress((void**)&pre,    g_pre);

    cudaFuncSetAttribute(proj_mma_kernel,
                         cudaFuncAttributeMaxDynamicSharedMemorySize, PROJ_SMEM);
    cudaFuncSetAttribute(attn_mma_kernel,
                         cudaFuncAttributeMaxDynamicSharedMemorySize, ATTN_SMEM);

    dim3 gproj(NN / 128, NH);
    proj_mma_kernel<<<gproj, 256, PROJ_SMEM>>>(x, wq, qb, q, 1);
    proj_mma_kernel<<<gproj, 256, PROJ_SMEM>>>(x, wk, kb, k, 1);
    proj_mma_kernel<<<gproj, 256, PROJ_SMEM>>>(x, wv, vb, v, 0);

    attn_mma_kernel<<<dim3(NN / 128, NH), 256, ATTN_SMEM>>>(q, k, v, concat);

    outproj_mma_kernel<<<dim3(NN / 128, DMODEL / 64), 256>>>(concat, x, wo, ob, pre);

    ln_kernel<<<NN, 256>>>(pre, alpha, beta, out);
}

// round 3
// speedup vs baseline: 5.6545x; 1.3728x over previous
#include <cuda_runtime.h>
#include <cstdint>

#define NN 2048
#define DM 1024
#define NH 16
#define DK 64
#define LN_EPS 1e-5f
#define QKS 36   // u32 row stride for packed Q/K (32 pairs + 4 pad)

// Scratch (device globals)
__device__ uint32_t g_Qh[(size_t)NH * NN * QKS];
__device__ uint32_t g_Ql[(size_t)NH * NN * QKS];
__device__ uint32_t g_Kh[(size_t)NH * NN * QKS];
__device__ uint32_t g_Kl[(size_t)NH * NN * QKS];
__device__ uint32_t g_Vt[(size_t)NH * DK * (NN / 2)];   // bf16 [h][dk][key], key pairs
__device__ float    g_concat[(size_t)NN * DM];
__device__ float    g_pre[(size_t)NN * DM];

// ---------------------------------------------------------------------------
// bf16 helpers
// ---------------------------------------------------------------------------
// pack2(e0, e1): e0 -> low half (element 0), e1 -> high half
__device__ __forceinline__ uint32_t pack2(float e0, float e1) {
    uint32_t r;
    asm("cvt.rn.bf16x2.f32 %0, %1, %2;" : "=r"(r) : "f"(e1), "f"(e0));
    return r;
}
__device__ __forceinline__ uint16_t bf16bits(float v) {
    uint16_t u;
    asm("cvt.rn.bf16.f32 %0, %1;" : "=h"(u) : "f"(v));
    return u;
}
// split pair (x0,x1) into hi-bf16x2 and lo-bf16x2 (lo = residual)
__device__ __forceinline__ void split2(float x0, float x1, uint32_t& hi, uint32_t& lo) {
    uint32_t h;
    asm("cvt.rn.bf16x2.f32 %0, %1, %2;" : "=r"(h) : "f"(x1), "f"(x0));
    float h0 = __uint_as_float(h << 16);
    float h1 = __uint_as_float(h & 0xffff0000u);
    uint32_t l;
    asm("cvt.rn.bf16x2.f32 %0, %1, %2;" : "=r"(l) : "f"(x1 - h1), "f"(x0 - h0));
    hi = h; lo = l;
}
// D += A*B  (m16n8k16 bf16, fp32 accum)
__device__ __forceinline__ void mma_bf16(float* c, const uint32_t* a, const uint32_t* b) {
    asm volatile(
        "mma.sync.aligned.m16n8k16.row.col.f32.bf16.bf16.f32 "
        "{%0,%1,%2,%3}, {%4,%5,%6,%7}, {%8,%9}, {%0,%1,%2,%3};\n"
        : "+f"(c[0]), "+f"(c[1]), "+f"(c[2]), "+f"(c[3])
        : "r"(a[0]), "r"(a[1]), "r"(a[2]), "r"(a[3]), "r"(b[0]), "r"(b[1]));
}

#define CPA16(sptr, gptr) do {                                                 \
    uint32_t _s = (uint32_t)__cvta_generic_to_shared(sptr);                    \
    asm volatile("cp.async.cg.shared.global [%0], [%1], 16;" :: "r"(_s), "l"(gptr)); \
} while (0)
#define CP_COMMIT() asm volatile("cp.async.commit_group;")
#define CP_WAIT(n)  asm volatile("cp.async.wait_group %0;" :: "n"(n))

// ---------------------------------------------------------------------------
// QKV projection, bf16 3-term. CTA: 128 rows x 64 cols (one head). 8 warps.
// mode 0: Q (scale 0.125, packed hi/lo out)
// mode 1: K (packed hi/lo out)
// mode 2: V (single bf16, transposed out [dk][key])
// ---------------------------------------------------------------------------
__global__ void __launch_bounds__(256) proj_kernel(const float* __restrict__ x,
                                                   const float* __restrict__ w,
                                                   const float* __restrict__ bias,
                                                   uint32_t* __restrict__ outHi,
                                                   uint32_t* __restrict__ outLo,
                                                   int mode)
{
    __shared__ uint32_t smem[6528];
    uint32_t* sXh = smem;                 // [128][17]
    uint32_t* sXl = smem + 2176;
    uint32_t* sWh = smem + 4352;          // [64][17] transposed [n][kpair]
    uint32_t* sWl = smem + 5440;

    const int m0 = blockIdx.x * 128;
    const int h  = blockIdx.y;
    const int tid = threadIdx.x;
    const int wid = tid >> 5, lane = tid & 31, g = lane >> 2, t = lane & 3;
    const float* wp = w + (size_t)h * DM * DK;

    const int xrow = tid >> 3, xc4 = (tid & 7) * 4;
    const int wn = tid & 63, kb4 = (tid >> 6) * 4;

    float acc[8][4] = {};

    float4 xr[4];
    float  wr[2][4];
    #pragma unroll
    for (int i = 0; i < 4; i++)
        xr[i] = *(const float4*)(x + (size_t)(m0 + xrow + 32 * i) * DM + xc4);
    #pragma unroll
    for (int p = 0; p < 2; p++)
        #pragma unroll
        for (int j = 0; j < 4; j++)
            wr[p][j] = wp[(size_t)(kb4 + 16 * p + j) * DK + wn];

    for (int kc = 0; kc < DM; kc += 32) {
        #pragma unroll
        for (int i = 0; i < 4; i++) {
            int row = xrow + 32 * i;
            uint32_t h0, l0, h1, l1;
            split2(xr[i].x, xr[i].y, h0, l0);
            split2(xr[i].z, xr[i].w, h1, l1);
            sXh[row * 17 + xc4 / 2]     = h0;  sXh[row * 17 + xc4 / 2 + 1] = h1;
            sXl[row * 17 + xc4 / 2]     = l0;  sXl[row * 17 + xc4 / 2 + 1] = l1;
        }
        #pragma unroll
        for (int p = 0; p < 2; p++) {
            int kb = kb4 + 16 * p;
            uint32_t h0, l0, h1, l1;
            split2(wr[p][0], wr[p][1], h0, l0);
            split2(wr[p][2], wr[p][3], h1, l1);
            sWh[wn * 17 + kb / 2]     = h0;  sWh[wn * 17 + kb / 2 + 1] = h1;
            sWl[wn * 17 + kb / 2]     = l0;  sWl[wn * 17 + kb / 2 + 1] = l1;
        }
        __syncthreads();

        if (kc + 32 < DM) {
            #pragma unroll
            for (int i = 0; i < 4; i++)
                xr[i] = *(const float4*)(x + (size_t)(m0 + xrow + 32 * i) * DM + kc + 32 + xc4);
            #pragma unroll
            for (int p = 0; p < 2; p++)
                #pragma unroll
                for (int j = 0; j < 4; j++)
                    wr[p][j] = wp[(size_t)(kc + 32 + kb4 + 16 * p + j) * DK + wn];
        }

        #pragma unroll
        for (int ks = 0; ks < 2; ks++) {
            const int r = wid * 16 + g;
            uint32_t ah[4], al[4];
            ah[0] = sXh[r * 17 + ks * 8 + t];         ah[1] = sXh[(r + 8) * 17 + ks * 8 + t];
            ah[2] = sXh[r * 17 + ks * 8 + t + 4];     ah[3] = sXh[(r + 8) * 17 + ks * 8 + t + 4];
            al[0] = sXl[r * 17 + ks * 8 + t];         al[1] = sXl[(r + 8) * 17 + ks * 8 + t];
            al[2] = sXl[r * 17 + ks * 8 + t + 4];     al[3] = sXl[(r + 8) * 17 + ks * 8 + t + 4];
            #pragma unroll
            for (int nb = 0; nb < 8; nb++) {
                const int bn = nb * 8 + g;
                uint32_t bh[2], bl[2];
                bh[0] = sWh[bn * 17 + ks * 8 + t];  bh[1] = sWh[bn * 17 + ks * 8 + t + 4];
                bl[0] = sWl[bn * 17 + ks * 8 + t];  bl[1] = sWl[bn * 17 + ks * 8 + t + 4];
                mma_bf16(acc[nb], ah, bh);
                mma_bf16(acc[nb], al, bh);
                mma_bf16(acc[nb], ah, bl);
            }
        }
        __syncthreads();
    }

    const int r0 = wid * 16 + g;   // local row in tile
    if (mode <= 1) {
        const float sc = (mode == 0) ? 0.125f : 1.0f;
        #pragma unroll
        for (int nb = 0; nb < 8; nb++) {
            int col = nb * 8 + 2 * t;
            float b0 = bias[h * DK + col], b1 = bias[h * DK + col + 1];
            float v00 = (acc[nb][0] + b0) * sc, v01 = (acc[nb][1] + b1) * sc;
            float v10 = (acc[nb][2] + b0) * sc, v11 = (acc[nb][3] + b1) * sc;
            uint32_t h0, l0, h1, l1;
            split2(v00, v01, h0, l0);
            split2(v10, v11, h1, l1);
            size_t base = ((size_t)h * NN + m0 + r0) * QKS + nb * 4 + t;
            outHi[base] = h0;               outLo[base] = l0;
            outHi[base + 8 * QKS] = h1;     outLo[base + 8 * QKS] = l1;
        }
    } else {
        // V: single bf16, transpose through smem (loop above ended with sync)
        uint16_t* Vs16 = (uint16_t*)smem;   // [64 dk][132] bf16
        #pragma unroll
        for (int nb = 0; nb < 8; nb++) {
            int col = nb * 8 + 2 * t;
            float b0 = bias[h * DK + col], b1 = bias[h * DK + col + 1];
            Vs16[(col)     * 132 + r0]     = bf16bits(acc[nb][0] + b0);
            Vs16[(col + 1) * 132 + r0]     = bf16bits(acc[nb][1] + b1);
            Vs16[(col)     * 132 + r0 + 8] = bf16bits(acc[nb][2] + b0);
            Vs16[(col + 1) * 132 + r0 + 8] = bf16bits(acc[nb][3] + b1);
        }
        __syncthreads();
        #pragma unroll
        for (int i = 0; i < 16; i++) {
            int fg = tid + i * 256;
            int dk = fg >> 6, c = fg & 63;
            outHi[((size_t)h * DK + dk) * (NN / 2) + m0 / 2 + c] = smem[dk * 66 + c];
        }
    }
}

// ---------------------------------------------------------------------------
// Flash attention, bf16. CTA: head h, 128 queries, 8 warps.
// Q frags hoisted (LDG once). K/V tiles (64 keys) cp.async double-buffered.
// QK^T 3-term bf16, PV single bf16 (P C-frags are PV A-frags — no shuffles).
// smem dyn: 2 x { Kh[64][36], Kl[64][36], Vt[64][36] } u32 = 55296 B
// ---------------------------------------------------------------------------
#define ATTN_BUF_U32 (3 * 64 * 36)
#define ATTN_SMEM_BYTES (2 * ATTN_BUF_U32 * 4)

__device__ __forceinline__ void attn_stage(uint32_t* dst, const uint32_t* Kh,
                                           const uint32_t* Kl, const uint32_t* Vt,
                                           int h, int t0, int tid)
{
    const uint32_t* sKh = Kh + ((size_t)h * NN + t0) * QKS;
    const uint32_t* sKl = Kl + ((size_t)h * NN + t0) * QKS;
    const uint32_t* sVt = Vt + (size_t)h * DK * (NN / 2) + t0 / 2;
    // 576 uint4 chunks Kh, 576 Kl, 512 Vt
    for (int idx = tid; idx < 1664; idx += 256) {
        if (idx < 576) {
            CPA16(dst + idx * 4, sKh + idx * 4);
        } else if (idx < 1152) {
            int j = idx - 576;
            CPA16(dst + 2304 + j * 4, sKl + j * 4);
        } else {
            int j = idx - 1152;
            int dk = j >> 3, c = (j & 7) * 4;
            CPA16(dst + 4608 + dk * 36 + c, sVt + (size_t)dk * (NN / 2) + c);
        }
    }
}

__global__ void __launch_bounds__(256) attn_kernel(const uint32_t* __restrict__ Qh,
                                                   const uint32_t* __restrict__ Ql,
                                                   const uint32_t* __restrict__ Kh,
                                                   const uint32_t* __restrict__ Kl,
                                                   const uint32_t* __restrict__ Vt,
                                                   float* __restrict__ concat)
{
    extern __shared__ uint32_t sm[];
    const int h  = blockIdx.y;
    const int q0 = blockIdx.x * 128;
    const int tid = threadIdx.x;
    const int wid = tid >> 5, lane = tid & 31, g = lane >> 2, t = lane & 3;

    attn_stage(sm, Kh, Kl, Vt, h, 0, tid);
    CP_COMMIT();

    // hoisted Q fragments
    uint32_t ah[4][4], al[4][4];
    {
        const uint32_t* qh = Qh + ((size_t)h * NN + q0 + wid * 16 + g) * QKS;
        const uint32_t* ql = Ql + ((size_t)h * NN + q0 + wid * 16 + g) * QKS;
        #pragma unroll
        for (int ks = 0; ks < 4; ks++) {
            ah[ks][0] = qh[ks * 8 + t];           ah[ks][1] = qh[8 * QKS + ks * 8 + t];
            ah[ks][2] = qh[ks * 8 + t + 4];       ah[ks][3] = qh[8 * QKS + ks * 8 + t + 4];
            al[ks][0] = ql[ks * 8 + t];           al[ks][1] = ql[8 * QKS + ks * 8 + t];
            al[ks][2] = ql[ks * 8 + t + 4];       al[ks][3] = ql[8 * QKS + ks * 8 + t + 4];
        }
    }

    float o[8][4] = {};
    float m0 = -1e30f, m1 = -1e30f, l0 = 0.f, l1 = 0.f;

    for (int tt = 0; tt < NN / 64; tt++) {
        uint32_t* buf = sm + (tt & 1) * ATTN_BUF_U32;
        if (tt + 1 < NN / 64) {
            attn_stage(sm + ((tt + 1) & 1) * ATTN_BUF_U32, Kh, Kl, Vt, h, (tt + 1) * 64, tid);
            CP_COMMIT();
            CP_WAIT(1);
        } else {
            CP_WAIT(0);
        }
        __syncthreads();

        const uint32_t* kh = buf;
        const uint32_t* kl = buf + 2304;
        const uint32_t* vs = buf + 4608;

        // S = Q K^T
        float s[8][4] = {};
        #pragma unroll
        for (int ks = 0; ks < 4; ks++) {
            #pragma unroll
            for (int nb = 0; nb < 8; nb++) {
                const int bn = nb * 8 + g;
                uint32_t bh[2], bl[2];
                bh[0] = kh[bn * 36 + ks * 8 + t];  bh[1] = kh[bn * 36 + ks * 8 + t + 4];
                bl[0] = kl[bn * 36 + ks * 8 + t];  bl[1] = kl[bn * 36 + ks * 8 + t + 4];
                mma_bf16(s[nb], ah[ks], bh);
                mma_bf16(s[nb], al[ks], bh);
                mma_bf16(s[nb], ah[ks], bl);
            }
        }

        // online softmax (row g: s[nb][0..1]; row g+8: s[nb][2..3])
        float mx0 = -1e30f, mx1 = -1e30f;
        #pragma unroll
        for (int nb = 0; nb < 8; nb++) {
            mx0 = fmaxf(mx0, fmaxf(s[nb][0], s[nb][1]));
            mx1 = fmaxf(mx1, fmaxf(s[nb][2], s[nb][3]));
        }
        mx0 = fmaxf(mx0, __shfl_xor_sync(0xffffffffu, mx0, 1));
        mx0 = fmaxf(mx0, __shfl_xor_sync(0xffffffffu, mx0, 2));
        mx1 = fmaxf(mx1, __shfl_xor_sync(0xffffffffu, mx1, 1));
        mx1 = fmaxf(mx1, __shfl_xor_sync(0xffffffffu, mx1, 2));

        float nm0 = fmaxf(m0, mx0), nm1 = fmaxf(m1, mx1);
        float sc0 = __expf(m0 - nm0), sc1 = __expf(m1 - nm1);
        float sum0 = 0.f, sum1 = 0.f;
        #pragma unroll
        for (int nb = 0; nb < 8; nb++) {
            s[nb][0] = __expf(s[nb][0] - nm0);
            s[nb][1] = __expf(s[nb][1] - nm0);
            s[nb][2] = __expf(s[nb][2] - nm1);
            s[nb][3] = __expf(s[nb][3] - nm1);
            sum0 += s[nb][0] + s[nb][1];
            sum1 += s[nb][2] + s[nb][3];
        }
        sum0 += __shfl_xor_sync(0xffffffffu, sum0, 1);
        sum0 += __shfl_xor_sync(0xffffffffu, sum0, 2);
        sum1 += __shfl_xor_sync(0xffffffffu, sum1, 1);
        sum1 += __shfl_xor_sync(0xffffffffu, sum1, 2);
        l0 = l0 * sc0 + sum0;  m0 = nm0;
        l1 = l1 * sc1 + sum1;  m1 = nm1;
        #pragma unroll
        for (int nb = 0; nb < 8; nb++) {
            o[nb][0] *= sc0; o[nb][1] *= sc0;
            o[nb][2] *= sc1; o[nb][3] *= sc1;
        }

        // O += P V  (P C-frags pack directly into A-frags)
        #pragma unroll
        for (int kp = 0; kp < 4; kp++) {
            uint32_t ap[4];
            ap[0] = pack2(s[2 * kp][0],     s[2 * kp][1]);
            ap[1] = pack2(s[2 * kp][2],     s[2 * kp][3]);
            ap[2] = pack2(s[2 * kp + 1][0], s[2 * kp + 1][1]);
            ap[3] = pack2(s[2 * kp + 1][2], s[2 * kp + 1][3]);
            #pragma unroll
            for (int nb = 0; nb < 8; nb++) {
                const int bn = nb * 8 + g;
                uint32_t b[2];
                b[0] = vs[bn * 36 + kp * 8 + t];
                b[1] = vs[bn * 36 + kp * 8 + t + 4];
                mma_bf16(o[nb], ap, b);
            }
        }
        __syncthreads();
    }

    const float inv0 = 1.0f / l0, inv1 = 1.0f / l1;
    const int r0 = q0 + wid * 16 + g;
    #pragma unroll
    for (int nb = 0; nb < 8; nb++) {
        int col = h * DK + nb * 8 + 2 * t;
        float2 v0 = make_float2(o[nb][0] * inv0, o[nb][1] * inv0);
        float2 v1 = make_float2(o[nb][2] * inv1, o[nb][3] * inv1);
        *(float2*)&concat[(size_t)r0 * DM + col]       = v0;
        *(float2*)&concat[(size_t)(r0 + 8) * DM + col] = v1;
    }
}

// ---------------------------------------------------------------------------
// Out projection + bias + residual, bf16 3-term. CTA: 128 rows x 64 cols.
// ---------------------------------------------------------------------------
__global__ void __launch_bounds__(256) outproj_kernel(const float* __restrict__ concat,
                                                      const float* __restrict__ x,
                                                      const float* __restrict__ wo,
                                                      const float* __restrict__ ob,
                                                      float* __restrict__ out)
{
    __shared__ uint32_t smem[6528];
    uint32_t* sXh = smem;
    uint32_t* sXl = smem + 2176;
    uint32_t* sWh = smem + 4352;
    uint32_t* sWl = smem + 5440;

    const int m0 = blockIdx.x * 128;
    const int c0 = blockIdx.y * 64;
    const int tid = threadIdx.x;
    const int wid = tid >> 5, lane = tid & 31, g = lane >> 2, t = lane & 3;

    const int xrow = tid >> 3, xc4 = (tid & 7) * 4;
    const int wn = tid & 63, kb4 = (tid >> 6) * 4;

    float acc[8][4] = {};

    float4 xr[4];
    float  wr[2][4];
    #pragma unroll
    for (int i = 0; i < 4; i++)
        xr[i] = *(const float4*)(concat + (size_t)(m0 + xrow + 32 * i) * DM + xc4);
    #pragma unroll
    for (int p = 0; p < 2; p++)
        #pragma unroll
        for (int j = 0; j < 4; j++)
            wr[p][j] = wo[(size_t)(kb4 + 16 * p + j) * DM + c0 + wn];

    for (int kc = 0; kc < DM; kc += 32) {
        #pragma unroll
        for (int i = 0; i < 4; i++) {
            int row = xrow + 32 * i;
            uint32_t h0, l0, h1, l1;
            split2(xr[i].x, xr[i].y, h0, l0);
            split2(xr[i].z, xr[i].w, h1, l1);
            sXh[row * 17 + xc4 / 2]     = h0;  sXh[row * 17 + xc4 / 2 + 1] = h1;
            sXl[row * 17 + xc4 / 2]     = l0;  sXl[row * 17 + xc4 / 2 + 1] = l1;
        }
        #pragma unroll
        for (int p = 0; p < 2; p++) {
            int kb = kb4 + 16 * p;
            uint32_t h0, l0, h1, l1;
            split2(wr[p][0], wr[p][1], h0, l0);
            split2(wr[p][2], wr[p][3], h1, l1);
            sWh[wn * 17 + kb / 2]     = h0;  sWh[wn * 17 + kb / 2 + 1] = h1;
            sWl[wn * 17 + kb / 2]     = l0;  sWl[wn * 17 + kb / 2 + 1] = l1;
        }
        __syncthreads();

        if (kc + 32 < DM) {
            #pragma unroll
            for (int i = 0; i < 4; i++)
                xr[i] = *(const float4*)(concat + (size_t)(m0 + xrow + 32 * i) * DM + kc + 32 + xc4);
            #pragma unroll
            for (int p = 0; p < 2; p++)
                #pragma unroll
                for (int j = 0; j < 4; j++)
                    wr[p][j] = wo[(size_t)(kc + 32 + kb4 + 16 * p + j) * DM + c0 + wn];
        }

        #pragma unroll
        for (int ks = 0; ks < 2; ks++) {
            const int r = wid * 16 + g;
            uint32_t ah[4], al[4];
            ah[0] = sXh[r * 17 + ks * 8 + t];         ah[1] = sXh[(r + 8) * 17 + ks * 8 + t];
            ah[2] = sXh[r * 17 + ks * 8 + t + 4];     ah[3] = sXh[(r + 8) * 17 + ks * 8 + t + 4];
            al[0] = sXl[r * 17 + ks * 8 + t];         al[1] = sXl[(r + 8) * 17 + ks * 8 + t];
            al[2] = sXl[r * 17 + ks * 8 + t + 4];     al[3] = sXl[(r + 8) * 17 + ks * 8 + t + 4];
            #pragma unroll
            for (int nb = 0; nb < 8; nb++) {
                const int bn = nb * 8 + g;
                uint32_t bh[2], bl[2];
                bh[0] = sWh[bn * 17 + ks * 8 + t];  bh[1] = sWh[bn * 17 + ks * 8 + t + 4];
                bl[0] = sWl[bn * 17 + ks * 8 + t];  bl[1] = sWl[bn * 17 + ks * 8 + t + 4];
                mma_bf16(acc[nb], ah, bh);
                mma_bf16(acc[nb], al, bh);
                mma_bf16(acc[nb], ah, bl);
            }
        }
        __syncthreads();
    }

    const int r0 = m0 + wid * 16 + g;
    #pragma unroll
    for (int nb = 0; nb < 8; nb++) {
        int col = c0 + nb * 8 + 2 * t;
        float b0 = ob[col], b1 = ob[col + 1];
        const float* xr0 = &x[(size_t)r0 * DM + col];
        const float* xr1 = &x[(size_t)(r0 + 8) * DM + col];
        float2 v0 = make_float2(acc[nb][0] + b0 + xr0[0], acc[nb][1] + b1 + xr0[1]);
        float2 v1 = make_float2(acc[nb][2] + b0 + xr1[0], acc[nb][3] + b1 + xr1[1]);
        *(float2*)&out[(size_t)r0 * DM + col]       = v0;
        *(float2*)&out[(size_t)(r0 + 8) * DM + col] = v1;
    }
}

// ---------------------------------------------------------------------------
// LayerNorm, one block per row
// ---------------------------------------------------------------------------
__global__ void __launch_bounds__(256) ln_kernel(const float* __restrict__ pre,
                                                 const float* __restrict__ alpha,
                                                 const float* __restrict__ beta,
                                                 float* __restrict__ out)
{
    const int row = blockIdx.x;
    const int tid = threadIdx.x;
    const float4 v = ((const float4*)(pre + (size_t)row * DM))[tid];

    float sum = v.x + v.y + v.z + v.w;
    float sq  = v.x * v.x + v.y * v.y + v.z * v.z + v.w * v.w;

    #pragma unroll
    for (int d = 16; d >= 1; d >>= 1) {
        sum += __shfl_xor_sync(0xffffffffu, sum, d);
        sq  += __shfl_xor_sync(0xffffffffu, sq,  d);
    }

    __shared__ float ssum[8], ssq[8];
    __shared__ float s_mu, s_rstd;
    int warp = tid >> 5, lane = tid & 31;
    if (lane == 0) { ssum[warp] = sum; ssq[warp] = sq; }
    __syncthreads();
    if (tid == 0) {
        float ts = 0.f, tq = 0.f;
        #pragma unroll
        for (int i = 0; i < 8; i++) { ts += ssum[i]; tq += ssq[i]; }
        float mu  = ts * (1.0f / DM);
        float var = tq * (1.0f / DM) - mu * mu;
        s_mu = mu;
        s_rstd = rsqrtf(var + LN_EPS);
    }
    __syncthreads();

    const float mu = s_mu, rstd = s_rstd;
    const float4 a4 = ((const float4*)alpha)[tid];
    const float4 b4 = ((const float4*)beta)[tid];
    float4 r;
    r.x = a4.x * (v.x - mu) * rstd + b4.x;
    r.y = a4.y * (v.y - mu) * rstd + b4.y;
    r.z = a4.z * (v.z - mu) * rstd + b4.z;
    r.w = a4.w * (v.w - mu) * rstd + b4.w;
    ((float4*)(out + (size_t)row * DM))[tid] = r;
}

// ---------------------------------------------------------------------------
extern "C" void kernel_launch(void* const* d_in, const int* in_sizes, int n_in,
                              void* d_out, int out_size)
{
    const float* x     = (const float*)d_in[0];
    const float* wq    = (const float*)d_in[1];
    const float* qb    = (const float*)d_in[2];
    const float* wk    = (const float*)d_in[3];
    const float* kb    = (const float*)d_in[4];
    const float* wv    = (const float*)d_in[5];
    const float* vb    = (const float*)d_in[6];
    const float* wo    = (const float*)d_in[7];
    const float* ob    = (const float*)d_in[8];
    const float* alpha = (const float*)d_in[9];
    const float* beta  = (const float*)d_in[10];
    float* out = (float*)d_out;

    uint32_t *Qh, *Ql, *Kh, *Kl, *Vt;
    float *concat, *pre;
    cudaGetSymbolAddress((void**)&Qh, g_Qh);
    cudaGetSymbolAddress((void**)&Ql, g_Ql);
    cudaGetSymbolAddress((void**)&Kh, g_Kh);
    cudaGetSymbolAddress((void**)&Kl, g_Kl);
    cudaGetSymbolAddress((void**)&Vt, g_Vt);
    cudaGetSymbolAddress((void**)&concat, g_concat);
    cudaGetSymbolAddress((void**)&pre, g_pre);

    cudaFuncSetAttribute(attn_kernel,
                         cudaFuncAttributeMaxDynamicSharedMemorySize, ATTN_SMEM_BYTES);

    dim3 gproj(NN / 128, NH);
    proj_kernel<<<gproj, 256>>>(x, wq, qb, Qh, Ql, 0);
    proj_kernel<<<gproj, 256>>>(x, wk, kb, Kh, Kl, 1);
    proj_kernel<<<gproj, 256>>>(x, wv, vb, Vt, nullptr, 2);

    attn_kernel<<<dim3(NN / 128, NH), 256, ATTN_SMEM_BYTES>>>(Qh, Ql, Kh, Kl, Vt, concat);

    outproj_kernel<<<dim3(NN / 128, DM / 64), 256>>>(concat, x, wo, ob, pre);

    ln_kernel<<<NN, 256>>>(pre, alpha, beta, out);
}

// round 4
// speedup vs baseline: 6.7441x; 1.1927x over previous
#include <cuda_runtime.h>
#include <cstdint>

#define NN 2048
#define DM 1024
#define NH 16
#define DK 64
#define LN_EPS 1e-5f
#define QKS 36   // u32 row stride for packed Q/K (32 pairs + 4 pad)

// Scratch (device globals)
__device__ uint32_t g_Xh[(size_t)NN * 512];
__device__ uint32_t g_Xl[(size_t)NN * 512];
__device__ uint32_t g_Wqh[(size_t)NH * 192 * 512];
__device__ uint32_t g_Wql[(size_t)NH * 192 * 512];
__device__ uint32_t g_Woh[(size_t)DM * 512];
__device__ uint32_t g_Wol[(size_t)DM * 512];
__device__ uint32_t g_Qh[(size_t)NH * NN * QKS];
__device__ uint32_t g_Ql[(size_t)NH * NN * QKS];
__device__ uint32_t g_Kh[(size_t)NH * NN * QKS];
__device__ uint32_t g_Kl[(size_t)NH * NN * QKS];
__device__ uint32_t g_Vt[(size_t)NH * DK * (NN / 2)];   // fp16 [h][dk][keypair]
__device__ uint32_t g_Ch[(size_t)NN * 512];
__device__ uint32_t g_Cl[(size_t)NN * 512];
__device__ float    g_pre[(size_t)NN * DM];

// ---------------------------------------------------------------------------
// helpers
// ---------------------------------------------------------------------------
__device__ __forceinline__ uint32_t pack2(float e0, float e1) {   // bf16x2
    uint32_t r;
    asm("cvt.rn.bf16x2.f32 %0, %1, %2;" : "=r"(r) : "f"(e1), "f"(e0));
    return r;
}
__device__ __forceinline__ uint32_t pack2h(float e0, float e1) {  // f16x2
    uint32_t r;
    asm("cvt.rn.f16x2.f32 %0, %1, %2;" : "=r"(r) : "f"(e1), "f"(e0));
    return r;
}
__device__ __forceinline__ uint16_t f16bits(float v) {
    uint16_t u;
    asm("cvt.rn.f16.f32 %0, %1;" : "=h"(u) : "f"(v));
    return u;
}
// split pair (x0,x1) into hi-bf16x2 + lo-bf16x2 residual
__device__ __forceinline__ void split2(float x0, float x1, uint32_t& hi, uint32_t& lo) {
    uint32_t h;
    asm("cvt.rn.bf16x2.f32 %0, %1, %2;" : "=r"(h) : "f"(x1), "f"(x0));
    float h0 = __uint_as_float(h << 16);
    float h1 = __uint_as_float(h & 0xffff0000u);
    uint32_t l;
    asm("cvt.rn.bf16x2.f32 %0, %1, %2;" : "=r"(l) : "f"(x1 - h1), "f"(x0 - h0));
    hi = h; lo = l;
}
__device__ __forceinline__ void mma_bf16(float* c, const uint32_t* a, const uint32_t* b) {
    asm volatile(
        "mma.sync.aligned.m16n8k16.row.col.f32.bf16.bf16.f32 "
        "{%0,%1,%2,%3}, {%4,%5,%6,%7}, {%8,%9}, {%0,%1,%2,%3};\n"
        : "+f"(c[0]), "+f"(c[1]), "+f"(c[2]), "+f"(c[3])
        : "r"(a[0]), "r"(a[1]), "r"(a[2]), "r"(a[3]), "r"(b[0]), "r"(b[1]));
}
__device__ __forceinline__ void mma_f16(float* c, const uint32_t* a, const uint32_t* b) {
    asm volatile(
        "mma.sync.aligned.m16n8k16.row.col.f32.f16.f16.f32 "
        "{%0,%1,%2,%3}, {%4,%5,%6,%7}, {%8,%9}, {%0,%1,%2,%3};\n"
        : "+f"(c[0]), "+f"(c[1]), "+f"(c[2]), "+f"(c[3])
        : "r"(a[0]), "r"(a[1]), "r"(a[2]), "r"(a[3]), "r"(b[0]), "r"(b[1]));
}
#define CPA16(sptr, gptr) do {                                                 \
    uint32_t _s = (uint32_t)__cvta_generic_to_shared(sptr);                    \
    asm volatile("cp.async.cg.shared.global [%0], [%1], 16;" :: "r"(_s), "l"(gptr)); \
} while (0)
#define CP_COMMIT() asm volatile("cp.async.commit_group;")
#define CP_WAIT(n)  asm volatile("cp.async.wait_group %0;" :: "n"(n))

// ---------------------------------------------------------------------------
// conversion kernels (run once per launch)
// ---------------------------------------------------------------------------
__global__ void __launch_bounds__(256) conv_x_kernel(const float* __restrict__ x,
                                                     uint32_t* __restrict__ Xh,
                                                     uint32_t* __restrict__ Xl)
{
    const int r = blockIdx.x, t = threadIdx.x;
    float4 v = ((const float4*)x)[r * 256 + t];
    uint32_t h0, l0, h1, l1;
    split2(v.x, v.y, h0, l0);
    split2(v.z, v.w, h1, l1);
    Xh[(size_t)r * 512 + 2 * t]     = h0;  Xl[(size_t)r * 512 + 2 * t]     = l0;
    Xh[(size_t)r * 512 + 2 * t + 1] = h1;  Xl[(size_t)r * 512 + 2 * t + 1] = l1;
}

// W [K=1024][N] row-major (per z slice) -> dst[n][kpair] split bf16, dst row stride 512
__global__ void __launch_bounds__(256) conv_w_kernel(const float* __restrict__ src,
                                                     int N, size_t srcZ,
                                                     uint32_t* __restrict__ dstH,
                                                     uint32_t* __restrict__ dstL,
                                                     size_t dstZ)
{
    __shared__ float sw[64][65];
    const int k0 = blockIdx.x * 64;
    const int n0 = blockIdx.y * 64;
    const int z  = blockIdx.z;
    const int t  = threadIdx.x;
    const float* s = src + (size_t)z * srcZ;

    #pragma unroll
    for (int i = 0; i < 16; i++) {
        int idx = i * 256 + t;
        int row = idx >> 6, col = idx & 63;
        sw[row][col] = s[(size_t)(k0 + row) * N + n0 + col];
    }
    __syncthreads();
    #pragma unroll
    for (int i = 0; i < 8; i++) {
        int idx = i * 256 + t;
        int n = idx >> 5, kp = idx & 31;
        uint32_t h, l;
        split2(sw[2 * kp][n], sw[2 * kp + 1][n], h, l);
        size_t o = (size_t)z * dstZ + (size_t)(n0 + n) * 512 + k0 / 2 + kp;
        dstH[o] = h;  dstL[o] = l;
    }
}

// ---------------------------------------------------------------------------
// Fused QKV GEMM (bf16 3-term). CTA = (128-row tile, head). 8 warps.
// A = split X [128][16 u32/chunk], B = split Wqkv [192][16], k-chunk = 32.
// smem stage: Ah(2560) Al(2560) Bh(3840) Bl(3840) u32, 2 stages = 102400 B.
// Epilogue: Q/K -> packed hi/lo bf16 pairs (QKS layout), V -> fp16 transposed.
// ---------------------------------------------------------------------------
#define QKV_STAGE_U32 12800
#define QKV_SMEM (2 * QKV_STAGE_U32 * 4)

__device__ __forceinline__ void qkv_load(uint32_t* st, const uint32_t* Xh,
                                         const uint32_t* Xl, const uint32_t* Wh,
                                         const uint32_t* Wl, int m0, int h,
                                         int kc16, int tid)
{
    const uint32_t* sxh = Xh + (size_t)m0 * 512 + kc16;
    const uint32_t* sxl = Xl + (size_t)m0 * 512 + kc16;
    const uint32_t* swh = Wh + (size_t)h * (192 * 512) + kc16;
    const uint32_t* swl = Wl + (size_t)h * (192 * 512) + kc16;
    #pragma unroll
    for (int i = 0; i < 2; i++) {
        int idx = tid + i * 256;               // 0..511
        int row = idx >> 2, sg = (idx & 3) * 4;
        CPA16(st + row * 20 + sg,        sxh + (size_t)row * 512 + sg);
        CPA16(st + 2560 + row * 20 + sg, sxl + (size_t)row * 512 + sg);
    }
    #pragma unroll
    for (int i = 0; i < 3; i++) {
        int idx = tid + i * 256;               // 0..767
        int row = idx >> 2, sg = (idx & 3) * 4;
        CPA16(st + 5120 + row * 20 + sg, swh + (size_t)row * 512 + sg);
        CPA16(st + 8960 + row * 20 + sg, swl + (size_t)row * 512 + sg);
    }
}

__global__ void __launch_bounds__(256, 1) qkv_kernel(const uint32_t* __restrict__ Xh,
                                                     const uint32_t* __restrict__ Xl,
                                                     const uint32_t* __restrict__ Wh,
                                                     const uint32_t* __restrict__ Wl,
                                                     const float* __restrict__ qb,
                                                     const float* __restrict__ kb,
                                                     const float* __restrict__ vb,
                                                     uint32_t* __restrict__ oQh,
                                                     uint32_t* __restrict__ oQl,
                                                     uint32_t* __restrict__ oKh,
                                                     uint32_t* __restrict__ oKl,
                                                     uint32_t* __restrict__ oVt)
{
    extern __shared__ uint32_t sm[];
    const int m0 = blockIdx.x * 128;
    const int h  = blockIdx.y;
    const int tid = threadIdx.x;
    const int wid = tid >> 5, lane = tid & 31, g = lane >> 2, t = lane & 3;

    float acc[24][4] = {};

    qkv_load(sm, Xh, Xl, Wh, Wl, m0, h, 0, tid);
    CP_COMMIT();

    for (int c = 0; c < 32; c++) {
        if (c < 31) {
            qkv_load(sm + ((c + 1) & 1) * QKV_STAGE_U32, Xh, Xl, Wh, Wl,
                     m0, h, (c + 1) * 16, tid);
            CP_COMMIT();
            CP_WAIT(1);
        } else {
            CP_WAIT(0);
        }
        __syncthreads();

        const uint32_t* p  = sm + (c & 1) * QKV_STAGE_U32;
        const uint32_t* Ah = p;
        const uint32_t* Al = p + 2560;
        const uint32_t* Bh = p + 5120;
        const uint32_t* Bl = p + 8960;

        #pragma unroll
        for (int ks = 0; ks < 2; ks++) {
            const int ro = (wid * 16 + g) * 20 + ks * 8 + t;
            uint32_t ah[4], al[4];
            ah[0] = Ah[ro];       ah[1] = Ah[ro + 160];
            ah[2] = Ah[ro + 4];   ah[3] = Ah[ro + 164];
            al[0] = Al[ro];       al[1] = Al[ro + 160];
            al[2] = Al[ro + 4];   al[3] = Al[ro + 164];
            #pragma unroll
            for (int nb = 0; nb < 24; nb++) {
                const int bo = (nb * 8 + g) * 20 + ks * 8 + t;
                uint32_t bh[2], bl[2];
                bh[0] = Bh[bo];  bh[1] = Bh[bo + 4];
                bl[0] = Bl[bo];  bl[1] = Bl[bo + 4];
                mma_bf16(acc[nb], ah, bh);
                mma_bf16(acc[nb], al, bh);
                mma_bf16(acc[nb], ah, bl);
            }
        }
        __syncthreads();
    }

    // ---- epilogue ----
    const int r = wid * 16 + g;
    const int grow = m0 + r;

    // Q: nb 0..7, scale 0.125
    #pragma unroll
    for (int nb = 0; nb < 8; nb++) {
        int col = nb * 8 + 2 * t;
        float b0 = qb[h * DK + col], b1 = qb[h * DK + col + 1];
        uint32_t h0, l0, h1, l1;
        split2((acc[nb][0] + b0) * 0.125f, (acc[nb][1] + b1) * 0.125f, h0, l0);
        split2((acc[nb][2] + b0) * 0.125f, (acc[nb][3] + b1) * 0.125f, h1, l1);
        size_t base = ((size_t)h * NN + grow) * QKS + nb * 4 + t;
        oQh[base] = h0;            oQl[base] = l0;
        oQh[base + 8 * QKS] = h1;  oQl[base + 8 * QKS] = l1;
    }
    // K: nb 8..15
    #pragma unroll
    for (int nb = 8; nb < 16; nb++) {
        int col = (nb - 8) * 8 + 2 * t;
        float b0 = kb[h * DK + col], b1 = kb[h * DK + col + 1];
        uint32_t h0, l0, h1, l1;
        split2(acc[nb][0] + b0, acc[nb][1] + b1, h0, l0);
        split2(acc[nb][2] + b0, acc[nb][3] + b1, h1, l1);
        size_t base = ((size_t)h * NN + grow) * QKS + (nb - 8) * 4 + t;
        oKh[base] = h0;            oKl[base] = l0;
        oKh[base + 8 * QKS] = h1;  oKl[base + 8 * QKS] = l1;
    }
    // V: nb 16..23 -> fp16 transpose via smem
    uint16_t* Vs16 = (uint16_t*)sm;   // [64][132] fp16
    #pragma unroll
    for (int nb = 16; nb < 24; nb++) {
        int col = (nb - 16) * 8 + 2 * t;
        float b0 = vb[h * DK + col], b1 = vb[h * DK + col + 1];
        Vs16[(col)     * 132 + r]     = f16bits(acc[nb][0] + b0);
        Vs16[(col + 1) * 132 + r]     = f16bits(acc[nb][1] + b1);
        Vs16[(col)     * 132 + r + 8] = f16bits(acc[nb][2] + b0);
        Vs16[(col + 1) * 132 + r + 8] = f16bits(acc[nb][3] + b1);
    }
    __syncthreads();
    #pragma unroll
    for (int i = 0; i < 16; i++) {
        int idx = tid + i * 256;
        int dk = idx >> 6, cc = idx & 63;
        oVt[((size_t)h * DK + dk) * (NN / 2) + m0 / 2 + cc] = sm[dk * 66 + cc];
    }
}

// ---------------------------------------------------------------------------
// Flash attention, bf16 QK (3-term) + fp16 PV. CTA: head h, 128 queries.
// ---------------------------------------------------------------------------
#define ATTN_BUF_U32 (3 * 64 * 36)
#define ATTN_SMEM_BYTES (2 * ATTN_BUF_U32 * 4)

__device__ __forceinline__ void attn_stage(uint32_t* dst, const uint32_t* Kh,
                                           const uint32_t* Kl, const uint32_t* Vt,
                                           int h, int t0, int tid)
{
    const uint32_t* sKh = Kh + ((size_t)h * NN + t0) * QKS;
    const uint32_t* sKl = Kl + ((size_t)h * NN + t0) * QKS;
    const uint32_t* sVt = Vt + (size_t)h * DK * (NN / 2) + t0 / 2;
    for (int idx = tid; idx < 1664; idx += 256) {
        if (idx < 576) {
            CPA16(dst + idx * 4, sKh + idx * 4);
        } else if (idx < 1152) {
            int j = idx - 576;
            CPA16(dst + 2304 + j * 4, sKl + j * 4);
        } else {
            int j = idx - 1152;
            int dk = j >> 3, c = (j & 7) * 4;
            CPA16(dst + 4608 + dk * 36 + c, sVt + (size_t)dk * (NN / 2) + c);
        }
    }
}

__global__ void __launch_bounds__(256) attn_kernel(const uint32_t* __restrict__ Qh,
                                                   const uint32_t* __restrict__ Ql,
                                                   const uint32_t* __restrict__ Kh,
                                                   const uint32_t* __restrict__ Kl,
                                                   const uint32_t* __restrict__ Vt,
                                                   uint32_t* __restrict__ Ch,
                                                   uint32_t* __restrict__ Cl)
{
    extern __shared__ uint32_t sm[];
    const int h  = blockIdx.y;
    const int q0 = blockIdx.x * 128;
    const int tid = threadIdx.x;
    const int wid = tid >> 5, lane = tid & 31, g = lane >> 2, t = lane & 3;

    attn_stage(sm, Kh, Kl, Vt, h, 0, tid);
    CP_COMMIT();

    uint32_t ah[4][4], al[4][4];
    {
        const uint32_t* qh = Qh + ((size_t)h * NN + q0 + wid * 16 + g) * QKS;
        const uint32_t* ql = Ql + ((size_t)h * NN + q0 + wid * 16 + g) * QKS;
        #pragma unroll
        for (int ks = 0; ks < 4; ks++) {
            ah[ks][0] = qh[ks * 8 + t];       ah[ks][1] = qh[8 * QKS + ks * 8 + t];
            ah[ks][2] = qh[ks * 8 + t + 4];   ah[ks][3] = qh[8 * QKS + ks * 8 + t + 4];
            al[ks][0] = ql[ks * 8 + t];       al[ks][1] = ql[8 * QKS + ks * 8 + t];
            al[ks][2] = ql[ks * 8 + t + 4];   al[ks][3] = ql[8 * QKS + ks * 8 + t + 4];
        }
    }

    float o[8][4] = {};
    float m0 = -1e30f, m1 = -1e30f, l0 = 0.f, l1 = 0.f;

    for (int tt = 0; tt < NN / 64; tt++) {
        uint32_t* buf = sm + (tt & 1) * ATTN_BUF_U32;
        if (tt + 1 < NN / 64) {
            attn_stage(sm + ((tt + 1) & 1) * ATTN_BUF_U32, Kh, Kl, Vt, h, (tt + 1) * 64, tid);
            CP_COMMIT();
            CP_WAIT(1);
        } else {
            CP_WAIT(0);
        }
        __syncthreads();

        const uint32_t* kh = buf;
        const uint32_t* kl = buf + 2304;
        const uint32_t* vs = buf + 4608;

        float s[8][4] = {};
        #pragma unroll
        for (int ks = 0; ks < 4; ks++) {
            #pragma unroll
            for (int nb = 0; nb < 8; nb++) {
                const int bn = nb * 8 + g;
                uint32_t bh[2], bl[2];
                bh[0] = kh[bn * 36 + ks * 8 + t];  bh[1] = kh[bn * 36 + ks * 8 + t + 4];
                bl[0] = kl[bn * 36 + ks * 8 + t];  bl[1] = kl[bn * 36 + ks * 8 + t + 4];
                mma_bf16(s[nb], ah[ks], bh);
                mma_bf16(s[nb], al[ks], bh);
                mma_bf16(s[nb], ah[ks], bl);
            }
        }

        float mx0 = -1e30f, mx1 = -1e30f;
        #pragma unroll
        for (int nb = 0; nb < 8; nb++) {
            mx0 = fmaxf(mx0, fmaxf(s[nb][0], s[nb][1]));
            mx1 = fmaxf(mx1, fmaxf(s[nb][2], s[nb][3]));
        }
        mx0 = fmaxf(mx0, __shfl_xor_sync(0xffffffffu, mx0, 1));
        mx0 = fmaxf(mx0, __shfl_xor_sync(0xffffffffu, mx0, 2));
        mx1 = fmaxf(mx1, __shfl_xor_sync(0xffffffffu, mx1, 1));
        mx1 = fmaxf(mx1, __shfl_xor_sync(0xffffffffu, mx1, 2));

        float nm0 = fmaxf(m0, mx0), nm1 = fmaxf(m1, mx1);
        float sc0 = __expf(m0 - nm0), sc1 = __expf(m1 - nm1);
        float sum0 = 0.f, sum1 = 0.f;
        #pragma unroll
        for (int nb = 0; nb < 8; nb++) {
            s[nb][0] = __expf(s[nb][0] - nm0);
            s[nb][1] = __expf(s[nb][1] - nm0);
            s[nb][2] = __expf(s[nb][2] - nm1);
            s[nb][3] = __expf(s[nb][3] - nm1);
            sum0 += s[nb][0] + s[nb][1];
            sum1 += s[nb][2] + s[nb][3];
        }
        sum0 += __shfl_xor_sync(0xffffffffu, sum0, 1);
        sum0 += __shfl_xor_sync(0xffffffffu, sum0, 2);
        sum1 += __shfl_xor_sync(0xffffffffu, sum1, 1);
        sum1 += __shfl_xor_sync(0xffffffffu, sum1, 2);
        l0 = l0 * sc0 + sum0;  m0 = nm0;
        l1 = l1 * sc1 + sum1;  m1 = nm1;
        #pragma unroll
        for (int nb = 0; nb < 8; nb++) {
            o[nb][0] *= sc0; o[nb][1] *= sc0;
            o[nb][2] *= sc1; o[nb][3] *= sc1;
        }

        // O += P V  (fp16)
        #pragma unroll
        for (int kp = 0; kp < 4; kp++) {
            uint32_t ap[4];
            ap[0] = pack2h(s[2 * kp][0],     s[2 * kp][1]);
            ap[1] = pack2h(s[2 * kp][2],     s[2 * kp][3]);
            ap[2] = pack2h(s[2 * kp + 1][0], s[2 * kp + 1][1]);
            ap[3] = pack2h(s[2 * kp + 1][2], s[2 * kp + 1][3]);
            #pragma unroll
            for (int nb = 0; nb < 8; nb++) {
                const int bn = nb * 8 + g;
                uint32_t b[2];
                b[0] = vs[bn * 36 + kp * 8 + t];
                b[1] = vs[bn * 36 + kp * 8 + t + 4];
                mma_f16(o[nb], ap, b);
            }
        }
        __syncthreads();
    }

    // epilogue: write concat as split bf16 pairs
    const float inv0 = 1.0f / l0, inv1 = 1.0f / l1;
    const int r0 = q0 + wid * 16 + g;
    #pragma unroll
    for (int nb = 0; nb < 8; nb++) {
        int cpi = h * 32 + nb * 4 + t;
        uint32_t h0, lo0, h1, lo1;
        split2(o[nb][0] * inv0, o[nb][1] * inv0, h0, lo0);
        split2(o[nb][2] * inv1, o[nb][3] * inv1, h1, lo1);
        Ch[(size_t)r0 * 512 + cpi]       = h0;  Cl[(size_t)r0 * 512 + cpi]       = lo0;
        Ch[(size_t)(r0 + 8) * 512 + cpi] = h1;  Cl[(size_t)(r0 + 8) * 512 + cpi] = lo1;
    }
}

// ---------------------------------------------------------------------------
// Out projection + bias + residual (bf16 3-term). CTA: 128 rows x 128 cols.
// smem stage: Ah/Al/Bh/Bl each 128*20 u32 -> 10240 u32, 2 stages = 81920 B
// ---------------------------------------------------------------------------
#define OP_STAGE_U32 10240
#define OP_SMEM (2 * OP_STAGE_U32 * 4)

__device__ __forceinline__ void op_load(uint32_t* st, const uint32_t* Ahg,
                                        const uint32_t* Alg, const uint32_t* Bhg,
                                        const uint32_t* Blg, int m0, int c0,
                                        int kc16, int tid)
{
    const uint32_t* sah = Ahg + (size_t)m0 * 512 + kc16;
    const uint32_t* sal = Alg + (size_t)m0 * 512 + kc16;
    const uint32_t* sbh = Bhg + (size_t)c0 * 512 + kc16;
    const uint32_t* sbl = Blg + (size_t)c0 * 512 + kc16;
    #pragma unroll
    for (int i = 0; i < 2; i++) {
        int idx = tid + i * 256;
        int row = idx >> 2, sg = (idx & 3) * 4;
        CPA16(st + row * 20 + sg,        sah + (size_t)row * 512 + sg);
        CPA16(st + 2560 + row * 20 + sg, sal + (size_t)row * 512 + sg);
        CPA16(st + 5120 + row * 20 + sg, sbh + (size_t)row * 512 + sg);
        CPA16(st + 7680 + row * 20 + sg, sbl + (size_t)row * 512 + sg);
    }
}

__global__ void __launch_bounds__(256, 1) outproj_kernel(const uint32_t* __restrict__ Ahg,
                                                         const uint32_t* __restrict__ Alg,
                                                         const uint32_t* __restrict__ Bhg,
                                                         const uint32_t* __restrict__ Blg,
                                                         const float* __restrict__ x,
                                                         const float* __restrict__ ob,
                                                         float* __restrict__ out)
{
    extern __shared__ uint32_t sm[];
    const int m0 = blockIdx.x * 128;
    const int c0 = blockIdx.y * 128;
    const int tid = threadIdx.x;
    const int wid = tid >> 5, lane = tid & 31, g = lane >> 2, t = lane & 3;

    float acc[16][4] = {};

    op_load(sm, Ahg, Alg, Bhg, Blg, m0, c0, 0, tid);
    CP_COMMIT();

    for (int c = 0; c < 32; c++) {
        if (c < 31) {
            op_load(sm + ((c + 1) & 1) * OP_STAGE_U32, Ahg, Alg, Bhg, Blg,
                    m0, c0, (c + 1) * 16, tid);
            CP_COMMIT();
            CP_WAIT(1);
        } else {
            CP_WAIT(0);
        }
        __syncthreads();

        const uint32_t* p  = sm + (c & 1) * OP_STAGE_U32;
        const uint32_t* Ah = p;
        const uint32_t* Al = p + 2560;
        const uint32_t* Bh = p + 5120;
        const uint32_t* Bl = p + 7680;

        #pragma unroll
        for (int ks = 0; ks < 2; ks++) {
            const int ro = (wid * 16 + g) * 20 + ks * 8 + t;
            uint32_t ah[4], al[4];
            ah[0] = Ah[ro];       ah[1] = Ah[ro + 160];
            ah[2] = Ah[ro + 4];   ah[3] = Ah[ro + 164];
            al[0] = Al[ro];       al[1] = Al[ro + 160];
            al[2] = Al[ro + 4];   al[3] = Al[ro + 164];
            #pragma unroll
            for (int nb = 0; nb < 16; nb++) {
                const int bo = (nb * 8 + g) * 20 + ks * 8 + t;
                uint32_t bh[2], bl[2];
                bh[0] = Bh[bo];  bh[1] = Bh[bo + 4];
                bl[0] = Bl[bo];  bl[1] = Bl[bo + 4];
                mma_bf16(acc[nb], ah, bh);
                mma_bf16(acc[nb], al, bh);
                mma_bf16(acc[nb], ah, bl);
            }
        }
        __syncthreads();
    }

    const int r0 = m0 + wid * 16 + g;
    #pragma unroll
    for (int nb = 0; nb < 16; nb++) {
        int col = c0 + nb * 8 + 2 * t;
        float b0 = ob[col], b1 = ob[col + 1];
        const float* xr0 = &x[(size_t)r0 * DM + col];
        const float* xr1 = &x[(size_t)(r0 + 8) * DM + col];
        float2 v0 = make_float2(acc[nb][0] + b0 + xr0[0], acc[nb][1] + b1 + xr0[1]);
        float2 v1 = make_float2(acc[nb][2] + b0 + xr1[0], acc[nb][3] + b1 + xr1[1]);
        *(float2*)&out[(size_t)r0 * DM + col]       = v0;
        *(float2*)&out[(size_t)(r0 + 8) * DM + col] = v1;
    }
}

// ---------------------------------------------------------------------------
// LayerNorm, one block per row
// ---------------------------------------------------------------------------
__global__ void __launch_bounds__(256) ln_kernel(const float* __restrict__ pre,
                                                 const float* __restrict__ alpha,
                                                 const float* __restrict__ beta,
                                                 float* __restrict__ out)
{
    const int row = blockIdx.x;
    const int tid = threadIdx.x;
    const float4 v = ((const float4*)(pre + (size_t)row * DM))[tid];

    float sum = v.x + v.y + v.z + v.w;
    float sq  = v.x * v.x + v.y * v.y + v.z * v.z + v.w * v.w;

    #pragma unroll
    for (int d = 16; d >= 1; d >>= 1) {
        sum += __shfl_xor_sync(0xffffffffu, sum, d);
        sq  += __shfl_xor_sync(0xffffffffu, sq,  d);
    }

    __shared__ float ssum[8], ssq[8];
    __shared__ float s_mu, s_rstd;
    int warp = tid >> 5, lane = tid & 31;
    if (lane == 0) { ssum[warp] = sum; ssq[warp] = sq; }
    __syncthreads();
    if (tid == 0) {
        float ts = 0.f, tq = 0.f;
        #pragma unroll
        for (int i = 0; i < 8; i++) { ts += ssum[i]; tq += ssq[i]; }
        float mu  = ts * (1.0f / DM);
        float var = tq * (1.0f / DM) - mu * mu;
        s_mu = mu;
        s_rstd = rsqrtf(var + LN_EPS);
    }
    __syncthreads();

    const float mu = s_mu, rstd = s_rstd;
    const float4 a4 = ((const float4*)alpha)[tid];
    const float4 b4 = ((const float4*)beta)[tid];
    float4 r;
    r.x = a4.x * (v.x - mu) * rstd + b4.x;
    r.y = a4.y * (v.y - mu) * rstd + b4.y;
    r.z = a4.z * (v.z - mu) * rstd + b4.z;
    r.w = a4.w * (v.w - mu) * rstd + b4.w;
    ((float4*)(out + (size_t)row * DM))[tid] = r;
}

// ---------------------------------------------------------------------------
extern "C" void kernel_launch(void* const* d_in, const int* in_sizes, int n_in,
                              void* d_out, int out_size)
{
    const float* x     = (const float*)d_in[0];
    const float* wq    = (const float*)d_in[1];
    const float* qb    = (const float*)d_in[2];
    const float* wk    = (const float*)d_in[3];
    const float* kb    = (const float*)d_in[4];
    const float* wv    = (const float*)d_in[5];
    const float* vb    = (const float*)d_in[6];
    const float* wo    = (const float*)d_in[7];
    const float* ob    = (const float*)d_in[8];
    const float* alpha = (const float*)d_in[9];
    const float* beta  = (const float*)d_in[10];
    float* out = (float*)d_out;

    uint32_t *Xh, *Xl, *Wqh, *Wql, *Woh, *Wol;
    uint32_t *Qh, *Ql, *Kh, *Kl, *Vt, *Ch, *Cl;
    float *pre;
    cudaGetSymbolAddress((void**)&Xh,  g_Xh);
    cudaGetSymbolAddress((void**)&Xl,  g_Xl);
    cudaGetSymbolAddress((void**)&Wqh, g_Wqh);
    cudaGetSymbolAddress((void**)&Wql, g_Wql);
    cudaGetSymbolAddress((void**)&Woh, g_Woh);
    cudaGetSymbolAddress((void**)&Wol, g_Wol);
    cudaGetSymbolAddress((void**)&Qh,  g_Qh);
    cudaGetSymbolAddress((void**)&Ql,  g_Ql);
    cudaGetSymbolAddress((void**)&Kh,  g_Kh);
    cudaGetSymbolAddress((void**)&Kl,  g_Kl);
    cudaGetSymbolAddress((void**)&Vt,  g_Vt);
    cudaGetSymbolAddress((void**)&Ch,  g_Ch);
    cudaGetSymbolAddress((void**)&Cl,  g_Cl);
    cudaGetSymbolAddress((void**)&pre, g_pre);

    cudaFuncSetAttribute(qkv_kernel,
                         cudaFuncAttributeMaxDynamicSharedMemorySize, QKV_SMEM);
    cudaFuncSetAttribute(attn_kernel,
                         cudaFuncAttributeMaxDynamicSharedMemorySize, ATTN_SMEM_BYTES);
    cudaFuncSetAttribute(outproj_kernel,
                         cudaFuncAttributeMaxDynamicSharedMemorySize, OP_SMEM);

    // conversions
    conv_x_kernel<<<NN, 256>>>(x, Xh, Xl);
    conv_w_kernel<<<dim3(16, 1, 16), 256>>>(wq, 64, (size_t)DM * DK,
                                            Wqh,             Wql,             (size_t)192 * 512);
    conv_w_kernel<<<dim3(16, 1, 16), 256>>>(wk, 64, (size_t)DM * DK,
                                            Wqh + 64 * 512,  Wql + 64 * 512,  (size_t)192 * 512);
    conv_w_kernel<<<dim3(16, 1, 16), 256>>>(wv, 64, (size_t)DM * DK,
                                            Wqh + 128 * 512, Wql + 128 * 512, (size_t)192 * 512);
    conv_w_kernel<<<dim3(16, 16, 1), 256>>>(wo, 1024, 0, Woh, Wol, 0);

    qkv_kernel<<<dim3(NN / 128, NH), 256, QKV_SMEM>>>(Xh, Xl, Wqh, Wql,
                                                      qb, kb, vb,
                                                      Qh, Ql, Kh, Kl, Vt);

    attn_kernel<<<dim3(NN / 128, NH), 256, ATTN_SMEM_BYTES>>>(Qh, Ql, Kh, Kl, Vt, Ch, Cl);

    outproj_kernel<<<dim3(NN / 128, DM / 128), 256, OP_SMEM>>>(Ch, Cl, Woh, Wol,
                                                               x, ob, pre);

    ln_kernel<<<NN, 256>>>(pre, alpha, beta, out);
}

// round 5
// speedup vs baseline: 6.9989x; 1.0378x over previous
#include <cuda_runtime.h>
#include <cstdint>

#define NN 2048
#define DM 1024
#define NH 16
#define DK 64
#define LN_EPS 1e-5f
#define QKS 36   // u32 row stride for packed Q/K (32 pairs + 4 pad)

// Scratch (device globals)
__device__ uint32_t g_Xh[(size_t)NN * 512];
__device__ uint32_t g_Xl[(size_t)NN * 512];
__device__ uint32_t g_Wqh[(size_t)NH * 192 * 512];
__device__ uint32_t g_Wql[(size_t)NH * 192 * 512];
__device__ uint32_t g_Woh[(size_t)DM * 512];
__device__ uint32_t g_Wol[(size_t)DM * 512];
__device__ uint32_t g_Qh[(size_t)NH * NN * QKS];
__device__ uint32_t g_Ql[(size_t)NH * NN * QKS];
__device__ uint32_t g_Kh[(size_t)NH * NN * QKS];
__device__ uint32_t g_Kl[(size_t)NH * NN * QKS];
__device__ uint32_t g_Vt[(size_t)NH * DK * (NN / 2)];   // fp16 [h][dk][keypair]
__device__ uint32_t g_Ch[(size_t)NN * 512];
__device__ uint32_t g_Cl[(size_t)NN * 512];
__device__ float    g_pre[(size_t)NN * DM];

// ---------------------------------------------------------------------------
// helpers
// ---------------------------------------------------------------------------
__device__ __forceinline__ uint32_t pack2h(float e0, float e1) {  // f16x2
    uint32_t r;
    asm("cvt.rn.f16x2.f32 %0, %1, %2;" : "=r"(r) : "f"(e1), "f"(e0));
    return r;
}
__device__ __forceinline__ uint16_t f16bits(float v) {
    uint16_t u;
    asm("cvt.rn.f16.f32 %0, %1;" : "=h"(u) : "f"(v));
    return u;
}
// split pair (x0,x1) into hi-bf16x2 + lo-bf16x2 residual
__device__ __forceinline__ void split2(float x0, float x1, uint32_t& hi, uint32_t& lo) {
    uint32_t h;
    asm("cvt.rn.bf16x2.f32 %0, %1, %2;" : "=r"(h) : "f"(x1), "f"(x0));
    float h0 = __uint_as_float(h << 16);
    float h1 = __uint_as_float(h & 0xffff0000u);
    uint32_t l;
    asm("cvt.rn.bf16x2.f32 %0, %1, %2;" : "=r"(l) : "f"(x1 - h1), "f"(x0 - h0));
    hi = h; lo = l;
}
__device__ __forceinline__ void mma_bf16(float* c, const uint32_t* a, const uint32_t* b) {
    asm volatile(
        "mma.sync.aligned.m16n8k16.row.col.f32.bf16.bf16.f32 "
        "{%0,%1,%2,%3}, {%4,%5,%6,%7}, {%8,%9}, {%0,%1,%2,%3};\n"
        : "+f"(c[0]), "+f"(c[1]), "+f"(c[2]), "+f"(c[3])
        : "r"(a[0]), "r"(a[1]), "r"(a[2]), "r"(a[3]), "r"(b[0]), "r"(b[1]));
}
__device__ __forceinline__ void mma_f16(float* c, const uint32_t* a, const uint32_t* b) {
    asm volatile(
        "mma.sync.aligned.m16n8k16.row.col.f32.f16.f16.f32 "
        "{%0,%1,%2,%3}, {%4,%5,%6,%7}, {%8,%9}, {%0,%1,%2,%3};\n"
        : "+f"(c[0]), "+f"(c[1]), "+f"(c[2]), "+f"(c[3])
        : "r"(a[0]), "r"(a[1]), "r"(a[2]), "r"(a[3]), "r"(b[0]), "r"(b[1]));
}
// ldmatrix x4: each lane supplies its own row address (16B-aligned)
__device__ __forceinline__ void ldsm_x4(uint32_t* r, const uint32_t* p) {
    uint32_t addr = (uint32_t)__cvta_generic_to_shared(p);
    asm volatile("ldmatrix.sync.aligned.m8n8.x4.shared.b16 {%0,%1,%2,%3}, [%4];"
        : "=r"(r[0]), "=r"(r[1]), "=r"(r[2]), "=r"(r[3]) : "r"(addr));
}
#define CPA16(sptr, gptr) do {                                                 \
    uint32_t _s = (uint32_t)__cvta_generic_to_shared(sptr);                    \
    asm volatile("cp.async.cg.shared.global [%0], [%1], 16;" :: "r"(_s), "l"(gptr)); \
} while (0)
#define CP_COMMIT() asm volatile("cp.async.commit_group;")
#define CP_WAIT(n)  asm volatile("cp.async.wait_group %0;" :: "n"(n))

// ---------------------------------------------------------------------------
// conversion kernels
// ---------------------------------------------------------------------------
__global__ void __launch_bounds__(256) conv_x_kernel(const float* __restrict__ x,
                                                     uint32_t* __restrict__ Xh,
                                                     uint32_t* __restrict__ Xl)
{
    const int r = blockIdx.x, t = threadIdx.x;
    float4 v = ((const float4*)x)[r * 256 + t];
    uint32_t h0, l0, h1, l1;
    split2(v.x, v.y, h0, l0);
    split2(v.z, v.w, h1, l1);
    Xh[(size_t)r * 512 + 2 * t]     = h0;  Xl[(size_t)r * 512 + 2 * t]     = l0;
    Xh[(size_t)r * 512 + 2 * t + 1] = h1;  Xl[(size_t)r * 512 + 2 * t + 1] = l1;
}

// fused wq/wk/wv conversion: z in [0,48); src selected by z/16, head = z%16.
// W slice [K=1024][64] -> dst[h][section*64 + n][kpair] split bf16, row stride 512
__global__ void __launch_bounds__(256) conv_wqkv_kernel(const float* __restrict__ wq,
                                                        const float* __restrict__ wk,
                                                        const float* __restrict__ wv,
                                                        uint32_t* __restrict__ dstH,
                                                        uint32_t* __restrict__ dstL)
{
    __shared__ float sw[64][65];
    const int k0 = blockIdx.x * 64;
    const int z  = blockIdx.z;
    const int sec = z >> 4, h = z & 15;
    const int t  = threadIdx.x;
    const float* s = (sec == 0 ? wq : sec == 1 ? wk : wv) + (size_t)h * DM * DK;

    #pragma unroll
    for (int i = 0; i < 16; i++) {
        int idx = i * 256 + t;
        int row = idx >> 6, col = idx & 63;
        sw[row][col] = s[(size_t)(k0 + row) * DK + col];
    }
    __syncthreads();
    #pragma unroll
    for (int i = 0; i < 8; i++) {
        int idx = i * 256 + t;
        int n = idx >> 5, kp = idx & 31;
        uint32_t hh, ll;
        split2(sw[2 * kp][n], sw[2 * kp + 1][n], hh, ll);
        size_t o = (size_t)h * (192 * 512) + (size_t)(sec * 64 + n) * 512 + k0 / 2 + kp;
        dstH[o] = hh;  dstL[o] = ll;
    }
}

// wo [1024][1024] -> dst[n][kpair] split bf16
__global__ void __launch_bounds__(256) conv_wo_kernel(const float* __restrict__ src,
                                                      uint32_t* __restrict__ dstH,
                                                      uint32_t* __restrict__ dstL)
{
    __shared__ float sw[64][65];
    const int k0 = blockIdx.x * 64;
    const int n0 = blockIdx.y * 64;
    const int t  = threadIdx.x;

    #pragma unroll
    for (int i = 0; i < 16; i++) {
        int idx = i * 256 + t;
        int row = idx >> 6, col = idx & 63;
        sw[row][col] = src[(size_t)(k0 + row) * DM + n0 + col];
    }
    __syncthreads();
    #pragma unroll
    for (int i = 0; i < 8; i++) {
        int idx = i * 256 + t;
        int n = idx >> 5, kp = idx & 31;
        uint32_t hh, ll;
        split2(sw[2 * kp][n], sw[2 * kp + 1][n], hh, ll);
        size_t o = (size_t)(n0 + n) * 512 + k0 / 2 + kp;
        dstH[o] = hh;  dstL[o] = ll;
    }
}

// ---------------------------------------------------------------------------
// Fused QKV GEMM (bf16 3-term), LDSM fragment loads.
// CTA = (128-row tile, head). 8 warps. k-chunk = 32.
// ---------------------------------------------------------------------------
#define QKV_STAGE_U32 12800
#define QKV_SMEM (2 * QKV_STAGE_U32 * 4)

__device__ __forceinline__ void qkv_load(uint32_t* st, const uint32_t* Xh,
                                         const uint32_t* Xl, const uint32_t* Wh,
                                         const uint32_t* Wl, int m0, int h,
                                         int kc16, int tid)
{
    const uint32_t* sxh = Xh + (size_t)m0 * 512 + kc16;
    const uint32_t* sxl = Xl + (size_t)m0 * 512 + kc16;
    const uint32_t* swh = Wh + (size_t)h * (192 * 512) + kc16;
    const uint32_t* swl = Wl + (size_t)h * (192 * 512) + kc16;
    #pragma unroll
    for (int i = 0; i < 2; i++) {
        int idx = tid + i * 256;               // 0..511
        int row = idx >> 2, sg = (idx & 3) * 4;
        CPA16(st + row * 20 + sg,        sxh + (size_t)row * 512 + sg);
        CPA16(st + 2560 + row * 20 + sg, sxl + (size_t)row * 512 + sg);
    }
    #pragma unroll
    for (int i = 0; i < 3; i++) {
        int idx = tid + i * 256;               // 0..767
        int row = idx >> 2, sg = (idx & 3) * 4;
        CPA16(st + 5120 + row * 20 + sg, swh + (size_t)row * 512 + sg);
        CPA16(st + 8960 + row * 20 + sg, swl + (size_t)row * 512 + sg);
    }
}

__global__ void __launch_bounds__(256, 1) qkv_kernel(const uint32_t* __restrict__ Xh,
                                                     const uint32_t* __restrict__ Xl,
                                                     const uint32_t* __restrict__ Wh,
                                                     const uint32_t* __restrict__ Wl,
                                                     const float* __restrict__ qb,
                                                     const float* __restrict__ kb,
                                                     const float* __restrict__ vb,
                                                     uint32_t* __restrict__ oQh,
                                                     uint32_t* __restrict__ oQl,
                                                     uint32_t* __restrict__ oKh,
                                                     uint32_t* __restrict__ oKl,
                                                     uint32_t* __restrict__ oVt)
{
    extern __shared__ uint32_t sm[];
    const int m0 = blockIdx.x * 128;
    const int h  = blockIdx.y;
    const int tid = threadIdx.x;
    const int wid = tid >> 5, lane = tid & 31, g = lane >> 2, t = lane & 3;
    const int lrow = lane & 7;
    // per-lane LDSM offsets
    const int aoff = (wid * 16 + lrow + ((lane >> 3) & 1) * 8) * 20 + (lane >> 4) * 4;
    const int boff = (lrow + ((lane >> 4) & 1) * 8) * 20 + ((lane >> 3) & 1) * 4;

    float acc[24][4] = {};

    qkv_load(sm, Xh, Xl, Wh, Wl, m0, h, 0, tid);
    CP_COMMIT();

    for (int c = 0; c < 32; c++) {
        if (c < 31) {
            qkv_load(sm + ((c + 1) & 1) * QKV_STAGE_U32, Xh, Xl, Wh, Wl,
                     m0, h, (c + 1) * 16, tid);
            CP_COMMIT();
            CP_WAIT(1);
        } else {
            CP_WAIT(0);
        }
        __syncthreads();

        const uint32_t* p  = sm + (c & 1) * QKV_STAGE_U32;
        const uint32_t* Ah = p;
        const uint32_t* Al = p + 2560;
        const uint32_t* Bh = p + 5120;
        const uint32_t* Bl = p + 8960;

        #pragma unroll
        for (int ks = 0; ks < 2; ks++) {
            uint32_t ah[4], al[4];
            ldsm_x4(ah, Ah + aoff + ks * 8);
            ldsm_x4(al, Al + aoff + ks * 8);
            #pragma unroll
            for (int nbp = 0; nbp < 12; nbp++) {
                uint32_t bh[4], bl[4];
                ldsm_x4(bh, Bh + boff + nbp * 320 + ks * 8);
                ldsm_x4(bl, Bl + boff + nbp * 320 + ks * 8);
                mma_bf16(acc[2 * nbp],     ah, bh);
                mma_bf16(acc[2 * nbp],     al, bh);
                mma_bf16(acc[2 * nbp],     ah, bl);
                mma_bf16(acc[2 * nbp + 1], ah, bh + 2);
                mma_bf16(acc[2 * nbp + 1], al, bh + 2);
                mma_bf16(acc[2 * nbp + 1], ah, bl + 2);
            }
        }
        __syncthreads();
    }

    // ---- epilogue ----
    const int r = wid * 16 + g;
    const int grow = m0 + r;

    // Q: nb 0..7, scale 0.125
    #pragma unroll
    for (int nb = 0; nb < 8; nb++) {
        int col = nb * 8 + 2 * t;
        float b0 = qb[h * DK + col], b1 = qb[h * DK + col + 1];
        uint32_t h0, l0, h1, l1;
        split2((acc[nb][0] + b0) * 0.125f, (acc[nb][1] + b1) * 0.125f, h0, l0);
        split2((acc[nb][2] + b0) * 0.125f, (acc[nb][3] + b1) * 0.125f, h1, l1);
        size_t base = ((size_t)h * NN + grow) * QKS + nb * 4 + t;
        oQh[base] = h0;            oQl[base] = l0;
        oQh[base + 8 * QKS] = h1;  oQl[base + 8 * QKS] = l1;
    }
    // K: nb 8..15
    #pragma unroll
    for (int nb = 8; nb < 16; nb++) {
        int col = (nb - 8) * 8 + 2 * t;
        float b0 = kb[h * DK + col], b1 = kb[h * DK + col + 1];
        uint32_t h0, l0, h1, l1;
        split2(acc[nb][0] + b0, acc[nb][1] + b1, h0, l0);
        split2(acc[nb][2] + b0, acc[nb][3] + b1, h1, l1);
        size_t base = ((size_t)h * NN + grow) * QKS + (nb - 8) * 4 + t;
        oKh[base] = h0;            oKl[base] = l0;
        oKh[base + 8 * QKS] = h1;  oKl[base + 8 * QKS] = l1;
    }
    // V: nb 16..23 -> fp16 transpose via smem
    uint16_t* Vs16 = (uint16_t*)sm;   // [64][132] fp16
    #pragma unroll
    for (int nb = 16; nb < 24; nb++) {
        int col = (nb - 16) * 8 + 2 * t;
        float b0 = vb[h * DK + col], b1 = vb[h * DK + col + 1];
        Vs16[(col)     * 132 + r]     = f16bits(acc[nb][0] + b0);
        Vs16[(col + 1) * 132 + r]     = f16bits(acc[nb][1] + b1);
        Vs16[(col)     * 132 + r + 8] = f16bits(acc[nb][2] + b0);
        Vs16[(col + 1) * 132 + r + 8] = f16bits(acc[nb][3] + b1);
    }
    __syncthreads();
    #pragma unroll
    for (int i = 0; i < 16; i++) {
        int idx = tid + i * 256;
        int dk = idx >> 6, cc = idx & 63;
        oVt[((size_t)h * DK + dk) * (NN / 2) + m0 / 2 + cc] = sm[dk * 66 + cc];
    }
}

// ---------------------------------------------------------------------------
// Flash attention, bf16 QK (3-term) + fp16 PV, LDSM B-frag loads.
// ---------------------------------------------------------------------------
#define ATTN_BUF_U32 (3 * 64 * 36)
#define ATTN_SMEM_BYTES (2 * ATTN_BUF_U32 * 4)

__device__ __forceinline__ void attn_stage(uint32_t* dst, const uint32_t* Kh,
                                           const uint32_t* Kl, const uint32_t* Vt,
                                           int h, int t0, int tid)
{
    const uint32_t* sKh = Kh + ((size_t)h * NN + t0) * QKS;
    const uint32_t* sKl = Kl + ((size_t)h * NN + t0) * QKS;
    const uint32_t* sVt = Vt + (size_t)h * DK * (NN / 2) + t0 / 2;
    for (int idx = tid; idx < 1664; idx += 256) {
        if (idx < 576) {
            CPA16(dst + idx * 4, sKh + idx * 4);
        } else if (idx < 1152) {
            int j = idx - 576;
            CPA16(dst + 2304 + j * 4, sKl + j * 4);
        } else {
            int j = idx - 1152;
            int dk = j >> 3, c = (j & 7) * 4;
            CPA16(dst + 4608 + dk * 36 + c, sVt + (size_t)dk * (NN / 2) + c);
        }
    }
}

__global__ void __launch_bounds__(256) attn_kernel(const uint32_t* __restrict__ Qh,
                                                   const uint32_t* __restrict__ Ql,
                                                   const uint32_t* __restrict__ Kh,
                                                   const uint32_t* __restrict__ Kl,
                                                   const uint32_t* __restrict__ Vt,
                                                   uint32_t* __restrict__ Ch,
                                                   uint32_t* __restrict__ Cl)
{
    extern __shared__ uint32_t sm[];
    const int h  = blockIdx.y;
    const int q0 = blockIdx.x * 128;
    const int tid = threadIdx.x;
    const int wid = tid >> 5, lane = tid & 31, g = lane >> 2, t = lane & 3;
    const int lrow = lane & 7;
    const int boff = (lrow + ((lane >> 4) & 1) * 8) * 36 + ((lane >> 3) & 1) * 4;

    attn_stage(sm, Kh, Kl, Vt, h, 0, tid);
    CP_COMMIT();

    uint32_t ah[4][4], al[4][4];
    {
        const uint32_t* qh = Qh + ((size_t)h * NN + q0 + wid * 16 + g) * QKS;
        const uint32_t* ql = Ql + ((size_t)h * NN + q0 + wid * 16 + g) * QKS;
        #pragma unroll
        for (int ks = 0; ks < 4; ks++) {
            ah[ks][0] = qh[ks * 8 + t];       ah[ks][1] = qh[8 * QKS + ks * 8 + t];
            ah[ks][2] = qh[ks * 8 + t + 4];   ah[ks][3] = qh[8 * QKS + ks * 8 + t + 4];
            al[ks][0] = ql[ks * 8 + t];       al[ks][1] = ql[8 * QKS + ks * 8 + t];
            al[ks][2] = ql[ks * 8 + t + 4];   al[ks][3] = ql[8 * QKS + ks * 8 + t + 4];
        }
    }

    float o[8][4] = {};
    float m0 = -1e30f, m1 = -1e30f, l0 = 0.f, l1 = 0.f;

    for (int tt = 0; tt < NN / 64; tt++) {
        uint32_t* buf = sm + (tt & 1) * ATTN_BUF_U32;
        if (tt + 1 < NN / 64) {
            attn_stage(sm + ((tt + 1) & 1) * ATTN_BUF_U32, Kh, Kl, Vt, h, (tt + 1) * 64, tid);
            CP_COMMIT();
            CP_WAIT(1);
        } else {
            CP_WAIT(0);
        }
        __syncthreads();

        const uint32_t* kh = buf;
        const uint32_t* kl = buf + 2304;
        const uint32_t* vs = buf + 4608;

        float s[8][4] = {};
        #pragma unroll
        for (int ks = 0; ks < 4; ks++) {
            #pragma unroll
            for (int nbp = 0; nbp < 4; nbp++) {
                uint32_t bh[4], bl[4];
                ldsm_x4(bh, kh + boff + nbp * 576 + ks * 8);
                ldsm_x4(bl, kl + boff + nbp * 576 + ks * 8);
                mma_bf16(s[2 * nbp],     ah[ks], bh);
                mma_bf16(s[2 * nbp],     al[ks], bh);
                mma_bf16(s[2 * nbp],     ah[ks], bl);
                mma_bf16(s[2 * nbp + 1], ah[ks], bh + 2);
                mma_bf16(s[2 * nbp + 1], al[ks], bh + 2);
                mma_bf16(s[2 * nbp + 1], ah[ks], bl + 2);
            }
        }

        float mx0 = -1e30f, mx1 = -1e30f;
        #pragma unroll
        for (int nb = 0; nb < 8; nb++) {
            mx0 = fmaxf(mx0, fmaxf(s[nb][0], s[nb][1]));
            mx1 = fmaxf(mx1, fmaxf(s[nb][2], s[nb][3]));
        }
        mx0 = fmaxf(mx0, __shfl_xor_sync(0xffffffffu, mx0, 1));
        mx0 = fmaxf(mx0, __shfl_xor_sync(0xffffffffu, mx0, 2));
        mx1 = fmaxf(mx1, __shfl_xor_sync(0xffffffffu, mx1, 1));
        mx1 = fmaxf(mx1, __shfl_xor_sync(0xffffffffu, mx1, 2));

        float nm0 = fmaxf(m0, mx0), nm1 = fmaxf(m1, mx1);
        float sc0 = __expf(m0 - nm0), sc1 = __expf(m1 - nm1);
        float sum0 = 0.f, sum1 = 0.f;
        #pragma unroll
        for (int nb = 0; nb < 8; nb++) {
            s[nb][0] = __expf(s[nb][0] - nm0);
            s[nb][1] = __expf(s[nb][1] - nm0);
            s[nb][2] = __expf(s[nb][2] - nm1);
            s[nb][3] = __expf(s[nb][3] - nm1);
            sum0 += s[nb][0] + s[nb][1];
            sum1 += s[nb][2] + s[nb][3];
        }
        sum0 += __shfl_xor_sync(0xffffffffu, sum0, 1);
        sum0 += __shfl_xor_sync(0xffffffffu, sum0, 2);
        sum1 += __shfl_xor_sync(0xffffffffu, sum1, 1);
        sum1 += __shfl_xor_sync(0xffffffffu, sum1, 2);
        l0 = l0 * sc0 + sum0;  m0 = nm0;
        l1 = l1 * sc1 + sum1;  m1 = nm1;
        #pragma unroll
        for (int nb = 0; nb < 8; nb++) {
            o[nb][0] *= sc0; o[nb][1] *= sc0;
            o[nb][2] *= sc1; o[nb][3] *= sc1;
        }

        // O += P V  (fp16)
        #pragma unroll
        for (int kp = 0; kp < 4; kp++) {
            uint32_t ap[4];
            ap[0] = pack2h(s[2 * kp][0],     s[2 * kp][1]);
            ap[1] = pack2h(s[2 * kp][2],     s[2 * kp][3]);
            ap[2] = pack2h(s[2 * kp + 1][0], s[2 * kp + 1][1]);
            ap[3] = pack2h(s[2 * kp + 1][2], s[2 * kp + 1][3]);
            #pragma unroll
            for (int nbp = 0; nbp < 4; nbp++) {
                uint32_t b[4];
                ldsm_x4(b, vs + boff + nbp * 576 + kp * 8);
                mma_f16(o[2 * nbp],     ap, b);
                mma_f16(o[2 * nbp + 1], ap, b + 2);
            }
        }
        __syncthreads();
    }

    // epilogue: write concat as split bf16 pairs
    const float inv0 = 1.0f / l0, inv1 = 1.0f / l1;
    const int r0 = q0 + wid * 16 + g;
    #pragma unroll
    for (int nb = 0; nb < 8; nb++) {
        int cpi = h * 32 + nb * 4 + t;
        uint32_t h0, lo0, h1, lo1;
        split2(o[nb][0] * inv0, o[nb][1] * inv0, h0, lo0);
        split2(o[nb][2] * inv1, o[nb][3] * inv1, h1, lo1);
        Ch[(size_t)r0 * 512 + cpi]       = h0;  Cl[(size_t)r0 * 512 + cpi]       = lo0;
        Ch[(size_t)(r0 + 8) * 512 + cpi] = h1;  Cl[(size_t)(r0 + 8) * 512 + cpi] = lo1;
    }
}

// ---------------------------------------------------------------------------
// Out projection + bias + residual (bf16 3-term), LDSM loads.
// CTA: 128 rows x 128 cols.
// ---------------------------------------------------------------------------
#define OP_STAGE_U32 10240
#define OP_SMEM (2 * OP_STAGE_U32 * 4)

__device__ __forceinline__ void op_load(uint32_t* st, const uint32_t* Ahg,
                                        const uint32_t* Alg, const uint32_t* Bhg,
                                        const uint32_t* Blg, int m0, int c0,
                                        int kc16, int tid)
{
    const uint32_t* sah = Ahg + (size_t)m0 * 512 + kc16;
    const uint32_t* sal = Alg + (size_t)m0 * 512 + kc16;
    const uint32_t* sbh = Bhg + (size_t)c0 * 512 + kc16;
    const uint32_t* sbl = Blg + (size_t)c0 * 512 + kc16;
    #pragma unroll
    for (int i = 0; i < 2; i++) {
        int idx = tid + i * 256;
        int row = idx >> 2, sg = (idx & 3) * 4;
        CPA16(st + row * 20 + sg,        sah + (size_t)row * 512 + sg);
        CPA16(st + 2560 + row * 20 + sg, sal + (size_t)row * 512 + sg);
        CPA16(st + 5120 + row * 20 + sg, sbh + (size_t)row * 512 + sg);
        CPA16(st + 7680 + row * 20 + sg, sbl + (size_t)row * 512 + sg);
    }
}

__global__ void __launch_bounds__(256, 1) outproj_kernel(const uint32_t* __restrict__ Ahg,
                                                         const uint32_t* __restrict__ Alg,
                                                         const uint32_t* __restrict__ Bhg,
                                                         const uint32_t* __restrict__ Blg,
                                                         const float* __restrict__ x,
                                                         const float* __restrict__ ob,
                                                         float* __restrict__ out)
{
    extern __shared__ uint32_t sm[];
    const int m0 = blockIdx.x * 128;
    const int c0 = blockIdx.y * 128;
    const int tid = threadIdx.x;
    const int wid = tid >> 5, lane = tid & 31, g = lane >> 2, t = lane & 3;
    const int lrow = lane & 7;
    const int aoff = (wid * 16 + lrow + ((lane >> 3) & 1) * 8) * 20 + (lane >> 4) * 4;
    const int boff = (lrow + ((lane >> 4) & 1) * 8) * 20 + ((lane >> 3) & 1) * 4;

    float acc[16][4] = {};

    op_load(sm, Ahg, Alg, Bhg, Blg, m0, c0, 0, tid);
    CP_COMMIT();

    for (int c = 0; c < 32; c++) {
        if (c < 31) {
            op_load(sm + ((c + 1) & 1) * OP_STAGE_U32, Ahg, Alg, Bhg, Blg,
                    m0, c0, (c + 1) * 16, tid);
            CP_COMMIT();
            CP_WAIT(1);
        } else {
            CP_WAIT(0);
        }
        __syncthreads();

        const uint32_t* p  = sm + (c & 1) * OP_STAGE_U32;
        const uint32_t* Ah = p;
        const uint32_t* Al = p + 2560;
        const uint32_t* Bh = p + 5120;
        const uint32_t* Bl = p + 7680;

        #pragma unroll
        for (int ks = 0; ks < 2; ks++) {
            uint32_t ah[4], al[4];
            ldsm_x4(ah, Ah + aoff + ks * 8);
            ldsm_x4(al, Al + aoff + ks * 8);
            #pragma unroll
            for (int nbp = 0; nbp < 8; nbp++) {
                uint32_t bh[4], bl[4];
                ldsm_x4(bh, Bh + boff + nbp * 320 + ks * 8);
                ldsm_x4(bl, Bl + boff + nbp * 320 + ks * 8);
                mma_bf16(acc[2 * nbp],     ah, bh);
                mma_bf16(acc[2 * nbp],     al, bh);
                mma_bf16(acc[2 * nbp],     ah, bl);
                mma_bf16(acc[2 * nbp + 1], ah, bh + 2);
                mma_bf16(acc[2 * nbp + 1], al, bh + 2);
                mma_bf16(acc[2 * nbp + 1], ah, bl + 2);
            }
        }
        __syncthreads();
    }

    const int r0 = m0 + wid * 16 + g;
    #pragma unroll
    for (int nb = 0; nb < 16; nb++) {
        int col = c0 + nb * 8 + 2 * t;
        float b0 = ob[col], b1 = ob[col + 1];
        const float* xr0 = &x[(size_t)r0 * DM + col];
        const float* xr1 = &x[(size_t)(r0 + 8) * DM + col];
        float2 v0 = make_float2(acc[nb][0] + b0 + xr0[0], acc[nb][1] + b1 + xr0[1]);
        float2 v1 = make_float2(acc[nb][2] + b0 + xr1[0], acc[nb][3] + b1 + xr1[1]);
        *(float2*)&out[(size_t)r0 * DM + col]       = v0;
        *(float2*)&out[(size_t)(r0 + 8) * DM + col] = v1;
    }
}

// ---------------------------------------------------------------------------
// LayerNorm, one block per row
// ---------------------------------------------------------------------------
__global__ void __launch_bounds__(256) ln_kernel(const float* __restrict__ pre,
                                                 const float* __restrict__ alpha,
                                                 const float* __restrict__ beta,
                                                 float* __restrict__ out)
{
    const int row = blockIdx.x;
    const int tid = threadIdx.x;
    const float4 v = ((const float4*)(pre + (size_t)row * DM))[tid];

    float sum = v.x + v.y + v.z + v.w;
    float sq  = v.x * v.x + v.y * v.y + v.z * v.z + v.w * v.w;

    #pragma unroll
    for (int d = 16; d >= 1; d >>= 1) {
        sum += __shfl_xor_sync(0xffffffffu, sum, d);
        sq  += __shfl_xor_sync(0xffffffffu, sq,  d);
    }

    __shared__ float ssum[8], ssq[8];
    __shared__ float s_mu, s_rstd;
    int warp = tid >> 5, lane = tid & 31;
    if (lane == 0) { ssum[warp] = sum; ssq[warp] = sq; }
    __syncthreads();
    if (tid == 0) {
        float ts = 0.f, tq = 0.f;
        #pragma unroll
        for (int i = 0; i < 8; i++) { ts += ssum[i]; tq += ssq[i]; }
        float mu  = ts * (1.0f / DM);
        float var = tq * (1.0f / DM) - mu * mu;
        s_mu = mu;
        s_rstd = rsqrtf(var + LN_EPS);
    }
    __syncthreads();

    const float mu = s_mu, rstd = s_rstd;
    const float4 a4 = ((const float4*)alpha)[tid];
    const float4 b4 = ((const float4*)beta)[tid];
    float4 r;
    r.x = a4.x * (v.x - mu) * rstd + b4.x;
    r.y = a4.y * (v.y - mu) * rstd + b4.y;
    r.z = a4.z * (v.z - mu) * rstd + b4.z;
    r.w = a4.w * (v.w - mu) * rstd + b4.w;
    ((float4*)(out + (size_t)row * DM))[tid] = r;
}

// ---------------------------------------------------------------------------
extern "C" void kernel_launch(void* const* d_in, const int* in_sizes, int n_in,
                              void* d_out, int out_size)
{
    const float* x     = (const float*)d_in[0];
    const float* wq    = (const float*)d_in[1];
    const float* qb    = (const float*)d_in[2];
    const float* wk    = (const float*)d_in[3];
    const float* kb    = (const float*)d_in[4];
    const float* wv    = (const float*)d_in[5];
    const float* vb    = (const float*)d_in[6];
    const float* wo    = (const float*)d_in[7];
    const float* ob    = (const float*)d_in[8];
    const float* alpha = (const float*)d_in[9];
    const float* beta  = (const float*)d_in[10];
    float* out = (float*)d_out;

    uint32_t *Xh, *Xl, *Wqh, *Wql, *Woh, *Wol;
    uint32_t *Qh, *Ql, *Kh, *Kl, *Vt, *Ch, *Cl;
    float *pre;
    cudaGetSymbolAddress((void**)&Xh,  g_Xh);
    cudaGetSymbolAddress((void**)&Xl,  g_Xl);
    cudaGetSymbolAddress((void**)&Wqh, g_Wqh);
    cudaGetSymbolAddress((void**)&Wql, g_Wql);
    cudaGetSymbolAddress((void**)&Woh, g_Woh);
    cudaGetSymbolAddress((void**)&Wol, g_Wol);
    cudaGetSymbolAddress((void**)&Qh,  g_Qh);
    cudaGetSymbolAddress((void**)&Ql,  g_Ql);
    cudaGetSymbolAddress((void**)&Kh,  g_Kh);
    cudaGetSymbolAddress((void**)&Kl,  g_Kl);
    cudaGetSymbolAddress((void**)&Vt,  g_Vt);
    cudaGetSymbolAddress((void**)&Ch,  g_Ch);
    cudaGetSymbolAddress((void**)&Cl,  g_Cl);
    cudaGetSymbolAddress((void**)&pre, g_pre);

    cudaFuncSetAttribute(qkv_kernel,
                         cudaFuncAttributeMaxDynamicSharedMemorySize, QKV_SMEM);
    cudaFuncSetAttribute(attn_kernel,
                         cudaFuncAttributeMaxDynamicSharedMemorySize, ATTN_SMEM_BYTES);
    cudaFuncSetAttribute(outproj_kernel,
                         cudaFuncAttributeMaxDynamicSharedMemorySize, OP_SMEM);

    // conversions
    conv_x_kernel<<<NN, 256>>>(x, Xh, Xl);
    conv_wqkv_kernel<<<dim3(16, 1, 48), 256>>>(wq, wk, wv, Wqh, Wql);
    conv_wo_kernel<<<dim3(16, 16, 1), 256>>>(wo, Woh, Wol);

    qkv_kernel<<<dim3(NN / 128, NH), 256, QKV_SMEM>>>(Xh, Xl, Wqh, Wql,
                                                      qb, kb, vb,
                                                      Qh, Ql, Kh, Kl, Vt);

    attn_kernel<<<dim3(NN / 128, NH), 256, ATTN_SMEM_BYTES>>>(Qh, Ql, Kh, Kl, Vt, Ch, Cl);

    outproj_kernel<<<dim3(NN / 128, DM / 128), 256, OP_SMEM>>>(Ch, Cl, Woh, Wol,
                                                               x, ob, pre);

    ln_kernel<<<NN, 256>>>(pre, alpha, beta, out);
}

// round 6
// speedup vs baseline: 7.0325x; 1.0048x over previous
#include <cuda_runtime.h>
#include <cstdint>

#define NN 2048
#define DM 1024
#define NH 16
#define DK 64
#define LN_EPS 1e-5f
#define QKS 36   // u32 row stride for packed Q/K (32 pairs + 4 pad)

// Scratch (device globals)
__device__ uint32_t g_Xh[(size_t)NN * 512];
__device__ uint32_t g_Xl[(size_t)NN * 512];
__device__ uint32_t g_Wqh[(size_t)NH * 192 * 512];
__device__ uint32_t g_Wql[(size_t)NH * 192 * 512];
__device__ uint32_t g_Woh[(size_t)DM * 512];
__device__ uint32_t g_Wol[(size_t)DM * 512];
__device__ uint32_t g_Qh[(size_t)NH * NN * QKS];
__device__ uint32_t g_Ql[(size_t)NH * NN * QKS];
__device__ uint32_t g_Kh[(size_t)NH * NN * QKS];
__device__ uint32_t g_Kl[(size_t)NH * NN * QKS];
__device__ uint32_t g_Vt[(size_t)NH * DK * (NN / 2)];   // fp16 [h][dk][keypair]
__device__ uint32_t g_Ch[(size_t)NN * 512];
__device__ uint32_t g_Cl[(size_t)NN * 512];
__device__ float    g_pre[(size_t)NN * DM];

// ---------------------------------------------------------------------------
// helpers
// ---------------------------------------------------------------------------
__device__ __forceinline__ uint32_t pack2h(float e0, float e1) {  // f16x2
    uint32_t r;
    asm("cvt.rn.f16x2.f32 %0, %1, %2;" : "=r"(r) : "f"(e1), "f"(e0));
    return r;
}
__device__ __forceinline__ uint16_t f16bits(float v) {
    uint16_t u;
    asm("cvt.rn.f16.f32 %0, %1;" : "=h"(u) : "f"(v));
    return u;
}
// split pair (x0,x1) into hi-bf16x2 + lo-bf16x2 residual
__device__ __forceinline__ void split2(float x0, float x1, uint32_t& hi, uint32_t& lo) {
    uint32_t h;
    asm("cvt.rn.bf16x2.f32 %0, %1, %2;" : "=r"(h) : "f"(x1), "f"(x0));
    float h0 = __uint_as_float(h << 16);
    float h1 = __uint_as_float(h & 0xffff0000u);
    uint32_t l;
    asm("cvt.rn.bf16x2.f32 %0, %1, %2;" : "=r"(l) : "f"(x1 - h1), "f"(x0 - h0));
    hi = h; lo = l;
}
__device__ __forceinline__ void mma_bf16(float* c, const uint32_t* a, const uint32_t* b) {
    asm volatile(
        "mma.sync.aligned.m16n8k16.row.col.f32.bf16.bf16.f32 "
        "{%0,%1,%2,%3}, {%4,%5,%6,%7}, {%8,%9}, {%0,%1,%2,%3};\n"
        : "+f"(c[0]), "+f"(c[1]), "+f"(c[2]), "+f"(c[3])
        : "r"(a[0]), "r"(a[1]), "r"(a[2]), "r"(a[3]), "r"(b[0]), "r"(b[1]));
}
__device__ __forceinline__ void mma_f16(float* c, const uint32_t* a, const uint32_t* b) {
    asm volatile(
        "mma.sync.aligned.m16n8k16.row.col.f32.f16.f16.f32 "
        "{%0,%1,%2,%3}, {%4,%5,%6,%7}, {%8,%9}, {%0,%1,%2,%3};\n"
        : "+f"(c[0]), "+f"(c[1]), "+f"(c[2]), "+f"(c[3])
        : "r"(a[0]), "r"(a[1]), "r"(a[2]), "r"(a[3]), "r"(b[0]), "r"(b[1]));
}
__device__ __forceinline__ void ldsm_x4(uint32_t* r, const uint32_t* p) {
    uint32_t addr = (uint32_t)__cvta_generic_to_shared(p);
    asm volatile("ldmatrix.sync.aligned.m8n8.x4.shared.b16 {%0,%1,%2,%3}, [%4];"
        : "=r"(r[0]), "=r"(r[1]), "=r"(r[2]), "=r"(r[3]) : "r"(addr));
}
#define CPA16(sptr, gptr) do {                                                 \
    uint32_t _s = (uint32_t)__cvta_generic_to_shared(sptr);                    \
    asm volatile("cp.async.cg.shared.global [%0], [%1], 16;" :: "r"(_s), "l"(gptr)); \
} while (0)
#define CP_COMMIT() asm volatile("cp.async.commit_group;")
#define CP_WAIT(n)  asm volatile("cp.async.wait_group %0;" :: "n"(n))

// ---------------------------------------------------------------------------
// conversion kernels
// ---------------------------------------------------------------------------
__global__ void __launch_bounds__(256) conv_x_kernel(const float* __restrict__ x,
                                                     uint32_t* __restrict__ Xh,
                                                     uint32_t* __restrict__ Xl)
{
    const int r = blockIdx.x, t = threadIdx.x;
    float4 v = ((const float4*)x)[r * 256 + t];
    uint32_t h0, l0, h1, l1;
    split2(v.x, v.y, h0, l0);
    split2(v.z, v.w, h1, l1);
    Xh[(size_t)r * 512 + 2 * t]     = h0;  Xl[(size_t)r * 512 + 2 * t]     = l0;
    Xh[(size_t)r * 512 + 2 * t + 1] = h1;  Xl[(size_t)r * 512 + 2 * t + 1] = l1;
}

__global__ void __launch_bounds__(256) conv_wqkv_kernel(const float* __restrict__ wq,
                                                        const float* __restrict__ wk,
                                                        const float* __restrict__ wv,
                                                        uint32_t* __restrict__ dstH,
                                                        uint32_t* __restrict__ dstL)
{
    __shared__ float sw[64][65];
    const int k0 = blockIdx.x * 64;
    const int z  = blockIdx.z;
    const int sec = z >> 4, h = z & 15;
    const int t  = threadIdx.x;
    const float* s = (sec == 0 ? wq : sec == 1 ? wk : wv) + (size_t)h * DM * DK;

    #pragma unroll
    for (int i = 0; i < 16; i++) {
        int idx = i * 256 + t;
        int row = idx >> 6, col = idx & 63;
        sw[row][col] = s[(size_t)(k0 + row) * DK + col];
    }
    __syncthreads();
    #pragma unroll
    for (int i = 0; i < 8; i++) {
        int idx = i * 256 + t;
        int n = idx >> 5, kp = idx & 31;
        uint32_t hh, ll;
        split2(sw[2 * kp][n], sw[2 * kp + 1][n], hh, ll);
        size_t o = (size_t)h * (192 * 512) + (size_t)(sec * 64 + n) * 512 + k0 / 2 + kp;
        dstH[o] = hh;  dstL[o] = ll;
    }
}

__global__ void __launch_bounds__(256) conv_wo_kernel(const float* __restrict__ src,
                                                      uint32_t* __restrict__ dstH,
                                                      uint32_t* __restrict__ dstL)
{
    __shared__ float sw[64][65];
    const int k0 = blockIdx.x * 64;
    const int n0 = blockIdx.y * 64;
    const int t  = threadIdx.x;

    #pragma unroll
    for (int i = 0; i < 16; i++) {
        int idx = i * 256 + t;
        int row = idx >> 6, col = idx & 63;
        sw[row][col] = src[(size_t)(k0 + row) * DM + n0 + col];
    }
    __syncthreads();
    #pragma unroll
    for (int i = 0; i < 8; i++) {
        int idx = i * 256 + t;
        int n = idx >> 5, kp = idx & 31;
        uint32_t hh, ll;
        split2(sw[2 * kp][n], sw[2 * kp + 1][n], hh, ll);
        size_t o = (size_t)(n0 + n) * 512 + k0 / 2 + kp;
        dstH[o] = hh;  dstL[o] = ll;
    }
}

// ---------------------------------------------------------------------------
// GEMM tile machinery: 128 rows x 64 cols, k-chunk 32, 2-stage cp.async,
// 3-term bf16, LDSM fragment loads. Stage = Ah(2560) Al(2560) Bh(1280)
// Bl(1280) = 7680 u32 = 30720 B; 2 stages = 61440 B -> 3 CTAs/SM.
// ---------------------------------------------------------------------------
#define G_STAGE_U32 7680
#define G_SMEM (2 * G_STAGE_U32 * 4)

__device__ __forceinline__ void gemm_stage_load(uint32_t* st,
                                                const uint32_t* Ahg, const uint32_t* Alg,
                                                const uint32_t* Bhg, const uint32_t* Blg,
                                                int kc16, int tid)
{
    #pragma unroll
    for (int i = 0; i < 2; i++) {
        int idx = tid + i * 256;               // 0..511
        int row = idx >> 2, sg = (idx & 3) * 4;
        CPA16(st + row * 20 + sg,        Ahg + (size_t)row * 512 + kc16 + sg);
        CPA16(st + 2560 + row * 20 + sg, Alg + (size_t)row * 512 + kc16 + sg);
    }
    {
        int row = tid >> 2, sg = (tid & 3) * 4;  // rows 0..63
        CPA16(st + 5120 + row * 20 + sg, Bhg + (size_t)row * 512 + kc16 + sg);
        CPA16(st + 6400 + row * 20 + sg, Blg + (size_t)row * 512 + kc16 + sg);
    }
}

// core loop: accumulates acc[8][4] over K=1024
__device__ __forceinline__ void gemm_core(uint32_t* sm, float (*acc)[4],
                                          const uint32_t* Ahg, const uint32_t* Alg,
                                          const uint32_t* Bhg, const uint32_t* Blg,
                                          int tid, int aoff, int boff)
{
    gemm_stage_load(sm, Ahg, Alg, Bhg, Blg, 0, tid);
    CP_COMMIT();

    for (int c = 0; c < 32; c++) {
        if (c < 31) {
            gemm_stage_load(sm + ((c + 1) & 1) * G_STAGE_U32,
                            Ahg, Alg, Bhg, Blg, (c + 1) * 16, tid);
            CP_COMMIT();
            CP_WAIT(1);
        } else {
            CP_WAIT(0);
        }
        __syncthreads();

        const uint32_t* p  = sm + (c & 1) * G_STAGE_U32;
        const uint32_t* Ah = p;
        const uint32_t* Al = p + 2560;
        const uint32_t* Bh = p + 5120;
        const uint32_t* Bl = p + 6400;

        #pragma unroll
        for (int ks = 0; ks < 2; ks++) {
            uint32_t ah[4], al[4];
            ldsm_x4(ah, Ah + aoff + ks * 8);
            ldsm_x4(al, Al + aoff + ks * 8);
            #pragma unroll
            for (int nbp = 0; nbp < 4; nbp++) {
                uint32_t bh[4], bl[4];
                ldsm_x4(bh, Bh + boff + nbp * 320 + ks * 8);
                ldsm_x4(bl, Bl + boff + nbp * 320 + ks * 8);
                mma_bf16(acc[2 * nbp],     ah, bh);
                mma_bf16(acc[2 * nbp],     al, bh);
                mma_bf16(acc[2 * nbp],     ah, bl);
                mma_bf16(acc[2 * nbp + 1], ah, bh + 2);
                mma_bf16(acc[2 * nbp + 1], al, bh + 2);
                mma_bf16(acc[2 * nbp + 1], ah, bl + 2);
            }
        }
        __syncthreads();
    }
}

// ---------------------------------------------------------------------------
// QKV GEMM: CTA = (row-tile, head, section). section: 0=Q, 1=K, 2=V.
// ---------------------------------------------------------------------------
__global__ void __launch_bounds__(256, 3) qkv_kernel(const uint32_t* __restrict__ Xh,
                                                     const uint32_t* __restrict__ Xl,
                                                     const uint32_t* __restrict__ Wh,
                                                     const uint32_t* __restrict__ Wl,
                                                     const float* __restrict__ qb,
                                                     const float* __restrict__ kb,
                                                     const float* __restrict__ vb,
                                                     uint32_t* __restrict__ oQh,
                                                     uint32_t* __restrict__ oQl,
                                                     uint32_t* __restrict__ oKh,
                                                     uint32_t* __restrict__ oKl,
                                                     uint32_t* __restrict__ oVt)
{
    extern __shared__ uint32_t sm[];
    const int m0  = blockIdx.x * 128;
    const int h   = blockIdx.y;
    const int sec = blockIdx.z;
    const int tid = threadIdx.x;
    const int wid = tid >> 5, lane = tid & 31, g = lane >> 2, t = lane & 3;
    const int lrow = lane & 7;
    const int aoff = (wid * 16 + lrow + ((lane >> 3) & 1) * 8) * 20 + (lane >> 4) * 4;
    const int boff = (lrow + ((lane >> 4) & 1) * 8) * 20 + ((lane >> 3) & 1) * 4;

    float acc[8][4] = {};

    gemm_core(sm, acc,
              Xh + (size_t)m0 * 512, Xl + (size_t)m0 * 512,
              Wh + ((size_t)h * 192 + sec * 64) * 512,
              Wl + ((size_t)h * 192 + sec * 64) * 512,
              tid, aoff, boff);

    const int r = wid * 16 + g;
    const int grow = m0 + r;

    if (sec <= 1) {
        const float scl = (sec == 0) ? 0.125f : 1.0f;
        const float* bias = (sec == 0) ? qb : kb;
        uint32_t* oH = (sec == 0) ? oQh : oKh;
        uint32_t* oL = (sec == 0) ? oQl : oKl;
        #pragma unroll
        for (int nb = 0; nb < 8; nb++) {
            int col = nb * 8 + 2 * t;
            float b0 = bias[h * DK + col], b1 = bias[h * DK + col + 1];
            uint32_t h0, l0, h1, l1;
            split2((acc[nb][0] + b0) * scl, (acc[nb][1] + b1) * scl, h0, l0);
            split2((acc[nb][2] + b0) * scl, (acc[nb][3] + b1) * scl, h1, l1);
            size_t base = ((size_t)h * NN + grow) * QKS + nb * 4 + t;
            oH[base] = h0;            oL[base] = l0;
            oH[base + 8 * QKS] = h1;  oL[base + 8 * QKS] = l1;
        }
    } else {
        // V: fp16 transpose via smem  ([64 dk][132] fp16 = stride 66 u32)
        uint16_t* Vs16 = (uint16_t*)sm;
        #pragma unroll
        for (int nb = 0; nb < 8; nb++) {
            int col = nb * 8 + 2 * t;
            float b0 = vb[h * DK + col], b1 = vb[h * DK + col + 1];
            Vs16[(col)     * 132 + r]     = f16bits(acc[nb][0] + b0);
            Vs16[(col + 1) * 132 + r]     = f16bits(acc[nb][1] + b1);
            Vs16[(col)     * 132 + r + 8] = f16bits(acc[nb][2] + b0);
            Vs16[(col + 1) * 132 + r + 8] = f16bits(acc[nb][3] + b1);
        }
        __syncthreads();
        #pragma unroll
        for (int i = 0; i < 16; i++) {
            int idx = tid + i * 256;
            int dk = idx >> 6, cc = idx & 63;
            oVt[((size_t)h * DK + dk) * (NN / 2) + m0 / 2 + cc] = sm[dk * 66 + cc];
        }
    }
}

// ---------------------------------------------------------------------------
// Out projection + bias + residual: CTA = (row-tile, 64-col tile).
// ---------------------------------------------------------------------------
__global__ void __launch_bounds__(256, 3) outproj_kernel(const uint32_t* __restrict__ Ahg,
                                                         const uint32_t* __restrict__ Alg,
                                                         const uint32_t* __restrict__ Bhg,
                                                         const uint32_t* __restrict__ Blg,
                                                         const float* __restrict__ x,
                                                         const float* __restrict__ ob,
                                                         float* __restrict__ out)
{
    extern __shared__ uint32_t sm[];
    const int m0 = blockIdx.x * 128;
    const int c0 = blockIdx.y * 64;
    const int tid = threadIdx.x;
    const int wid = tid >> 5, lane = tid & 31, g = lane >> 2, t = lane & 3;
    const int lrow = lane & 7;
    const int aoff = (wid * 16 + lrow + ((lane >> 3) & 1) * 8) * 20 + (lane >> 4) * 4;
    const int boff = (lrow + ((lane >> 4) & 1) * 8) * 20 + ((lane >> 3) & 1) * 4;

    float acc[8][4] = {};

    gemm_core(sm, acc,
              Ahg + (size_t)m0 * 512, Alg + (size_t)m0 * 512,
              Bhg + (size_t)c0 * 512, Blg + (size_t)c0 * 512,
              tid, aoff, boff);

    const int r0 = m0 + wid * 16 + g;
    #pragma unroll
    for (int nb = 0; nb < 8; nb++) {
        int col = c0 + nb * 8 + 2 * t;
        float b0 = ob[col], b1 = ob[col + 1];
        const float* xr0 = &x[(size_t)r0 * DM + col];
        const float* xr1 = &x[(size_t)(r0 + 8) * DM + col];
        float2 v0 = make_float2(acc[nb][0] + b0 + xr0[0], acc[nb][1] + b1 + xr0[1]);
        float2 v1 = make_float2(acc[nb][2] + b0 + xr1[0], acc[nb][3] + b1 + xr1[1]);
        *(float2*)&out[(size_t)r0 * DM + col]       = v0;
        *(float2*)&out[(size_t)(r0 + 8) * DM + col] = v1;
    }
}

// ---------------------------------------------------------------------------
// Flash attention, bf16 QK (3-term) + fp16 PV, LDSM B-frag loads.
// ---------------------------------------------------------------------------
#define ATTN_BUF_U32 (3 * 64 * 36)
#define ATTN_SMEM_BYTES (2 * ATTN_BUF_U32 * 4)

__device__ __forceinline__ void attn_stage(uint32_t* dst, const uint32_t* Kh,
                                           const uint32_t* Kl, const uint32_t* Vt,
                                           int h, int t0, int tid)
{
    const uint32_t* sKh = Kh + ((size_t)h * NN + t0) * QKS;
    const uint32_t* sKl = Kl + ((size_t)h * NN + t0) * QKS;
    const uint32_t* sVt = Vt + (size_t)h * DK * (NN / 2) + t0 / 2;
    for (int idx = tid; idx < 1664; idx += 256) {
        if (idx < 576) {
            CPA16(dst + idx * 4, sKh + idx * 4);
        } else if (idx < 1152) {
            int j = idx - 576;
            CPA16(dst + 2304 + j * 4, sKl + j * 4);
        } else {
            int j = idx - 1152;
            int dk = j >> 3, c = (j & 7) * 4;
            CPA16(dst + 4608 + dk * 36 + c, sVt + (size_t)dk * (NN / 2) + c);
        }
    }
}

__global__ void __launch_bounds__(256) attn_kernel(const uint32_t* __restrict__ Qh,
                                                   const uint32_t* __restrict__ Ql,
                                                   const uint32_t* __restrict__ Kh,
                                                   const uint32_t* __restrict__ Kl,
                                                   const uint32_t* __restrict__ Vt,
                                                   uint32_t* __restrict__ Ch,
                                                   uint32_t* __restrict__ Cl)
{
    extern __shared__ uint32_t sm[];
    const int h  = blockIdx.y;
    const int q0 = blockIdx.x * 128;
    const int tid = threadIdx.x;
    const int wid = tid >> 5, lane = tid & 31, g = lane >> 2, t = lane & 3;
    const int lrow = lane & 7;
    const int boff = (lrow + ((lane >> 4) & 1) * 8) * 36 + ((lane >> 3) & 1) * 4;

    attn_stage(sm, Kh, Kl, Vt, h, 0, tid);
    CP_COMMIT();

    uint32_t ah[4][4], al[4][4];
    {
        const uint32_t* qh = Qh + ((size_t)h * NN + q0 + wid * 16 + g) * QKS;
        const uint32_t* ql = Ql + ((size_t)h * NN + q0 + wid * 16 + g) * QKS;
        #pragma unroll
        for (int ks = 0; ks < 4; ks++) {
            ah[ks][0] = qh[ks * 8 + t];       ah[ks][1] = qh[8 * QKS + ks * 8 + t];
            ah[ks][2] = qh[ks * 8 + t + 4];   ah[ks][3] = qh[8 * QKS + ks * 8 + t + 4];
            al[ks][0] = ql[ks * 8 + t];       al[ks][1] = ql[8 * QKS + ks * 8 + t];
            al[ks][2] = ql[ks * 8 + t + 4];   al[ks][3] = ql[8 * QKS + ks * 8 + t + 4];
        }
    }

    float o[8][4] = {};
    float m0 = -1e30f, m1 = -1e30f, l0 = 0.f, l1 = 0.f;

    for (int tt = 0; tt < NN / 64; tt++) {
        uint32_t* buf = sm + (tt & 1) * ATTN_BUF_U32;
        if (tt + 1 < NN / 64) {
            attn_stage(sm + ((tt + 1) & 1) * ATTN_BUF_U32, Kh, Kl, Vt, h, (tt + 1) * 64, tid);
            CP_COMMIT();
            CP_WAIT(1);
        } else {
            CP_WAIT(0);
        }
        __syncthreads();

        const uint32_t* kh = buf;
        const uint32_t* kl = buf + 2304;
        const uint32_t* vs = buf + 4608;

        float s[8][4] = {};
        #pragma unroll
        for (int ks = 0; ks < 4; ks++) {
            #pragma unroll
            for (int nbp = 0; nbp < 4; nbp++) {
                uint32_t bh[4], bl[4];
                ldsm_x4(bh, kh + boff + nbp * 576 + ks * 8);
                ldsm_x4(bl, kl + boff + nbp * 576 + ks * 8);
                mma_bf16(s[2 * nbp],     ah[ks], bh);
                mma_bf16(s[2 * nbp],     al[ks], bh);
                mma_bf16(s[2 * nbp],     ah[ks], bl);
                mma_bf16(s[2 * nbp + 1], ah[ks], bh + 2);
                mma_bf16(s[2 * nbp + 1], al[ks], bh + 2);
                mma_bf16(s[2 * nbp + 1], ah[ks], bl + 2);
            }
        }

        float mx0 = -1e30f, mx1 = -1e30f;
        #pragma unroll
        for (int nb = 0; nb < 8; nb++) {
            mx0 = fmaxf(mx0, fmaxf(s[nb][0], s[nb][1]));
            mx1 = fmaxf(mx1, fmaxf(s[nb][2], s[nb][3]));
        }
        mx0 = fmaxf(mx0, __shfl_xor_sync(0xffffffffu, mx0, 1));
        mx0 = fmaxf(mx0, __shfl_xor_sync(0xffffffffu, mx0, 2));
        mx1 = fmaxf(mx1, __shfl_xor_sync(0xffffffffu, mx1, 1));
        mx1 = fmaxf(mx1, __shfl_xor_sync(0xffffffffu, mx1, 2));

        float nm0 = fmaxf(m0, mx0), nm1 = fmaxf(m1, mx1);
        float sc0 = __expf(m0 - nm0), sc1 = __expf(m1 - nm1);
        float sum0 = 0.f, sum1 = 0.f;
        #pragma unroll
        for (int nb = 0; nb < 8; nb++) {
            s[nb][0] = __expf(s[nb][0] - nm0);
            s[nb][1] = __expf(s[nb][1] - nm0);
            s[nb][2] = __expf(s[nb][2] - nm1);
            s[nb][3] = __expf(s[nb][3] - nm1);
            sum0 += s[nb][0] + s[nb][1];
            sum1 += s[nb][2] + s[nb][3];
        }
        sum0 += __shfl_xor_sync(0xffffffffu, sum0, 1);
        sum0 += __shfl_xor_sync(0xffffffffu, sum0, 2);
        sum1 += __shfl_xor_sync(0xffffffffu, sum1, 1);
        sum1 += __shfl_xor_sync(0xffffffffu, sum1, 2);
        l0 = l0 * sc0 + sum0;  m0 = nm0;
        l1 = l1 * sc1 + sum1;  m1 = nm1;
        #pragma unroll
        for (int nb = 0; nb < 8; nb++) {
            o[nb][0] *= sc0; o[nb][1] *= sc0;
            o[nb][2] *= sc1; o[nb][3] *= sc1;
        }

        // O += P V  (fp16)
        #pragma unroll
        for (int kp = 0; kp < 4; kp++) {
            uint32_t ap[4];
            ap[0] = pack2h(s[2 * kp][0],     s[2 * kp][1]);
            ap[1] = pack2h(s[2 * kp][2],     s[2 * kp][3]);
            ap[2] = pack2h(s[2 * kp + 1][0], s[2 * kp + 1][1]);
            ap[3] = pack2h(s[2 * kp + 1][2], s[2 * kp + 1][3]);
            #pragma unroll
            for (int nbp = 0; nbp < 4; nbp++) {
                uint32_t b[4];
                ldsm_x4(b, vs + boff + nbp * 576 + kp * 8);
                mma_f16(o[2 * nbp],     ap, b);
                mma_f16(o[2 * nbp + 1], ap, b + 2);
            }
        }
        __syncthreads();
    }

    // epilogue: write concat as split bf16 pairs
    const float inv0 = 1.0f / l0, inv1 = 1.0f / l1;
    const int r0 = q0 + wid * 16 + g;
    #pragma unroll
    for (int nb = 0; nb < 8; nb++) {
        int cpi = h * 32 + nb * 4 + t;
        uint32_t h0, lo0, h1, lo1;
        split2(o[nb][0] * inv0, o[nb][1] * inv0, h0, lo0);
        split2(o[nb][2] * inv1, o[nb][3] * inv1, h1, lo1);
        Ch[(size_t)r0 * 512 + cpi]       = h0;  Cl[(size_t)r0 * 512 + cpi]       = lo0;
        Ch[(size_t)(r0 + 8) * 512 + cpi] = h1;  Cl[(size_t)(r0 + 8) * 512 + cpi] = lo1;
    }
}

// ---------------------------------------------------------------------------
// LayerNorm, one block per row
// ---------------------------------------------------------------------------
__global__ void __launch_bounds__(256) ln_kernel(const float* __restrict__ pre,
                                                 const float* __restrict__ alpha,
                                                 const float* __restrict__ beta,
                                                 float* __restrict__ out)
{
    const int row = blockIdx.x;
    const int tid = threadIdx.x;
    const float4 v = ((const float4*)(pre + (size_t)row * DM))[tid];

    float sum = v.x + v.y + v.z + v.w;
    float sq  = v.x * v.x + v.y * v.y + v.z * v.z + v.w * v.w;

    #pragma unroll
    for (int d = 16; d >= 1; d >>= 1) {
        sum += __shfl_xor_sync(0xffffffffu, sum, d);
        sq  += __shfl_xor_sync(0xffffffffu, sq,  d);
    }

    __shared__ float ssum[8], ssq[8];
    __shared__ float s_mu, s_rstd;
    int warp = tid >> 5, lane = tid & 31;
    if (lane == 0) { ssum[warp] = sum; ssq[warp] = sq; }
    __syncthreads();
    if (tid == 0) {
        float ts = 0.f, tq = 0.f;
        #pragma unroll
        for (int i = 0; i < 8; i++) { ts += ssum[i]; tq += ssq[i]; }
        float mu  = ts * (1.0f / DM);
        float var = tq * (1.0f / DM) - mu * mu;
        s_mu = mu;
        s_rstd = rsqrtf(var + LN_EPS);
    }
    __syncthreads();

    const float mu = s_mu, rstd = s_rstd;
    const float4 a4 = ((const float4*)alpha)[tid];
    const float4 b4 = ((const float4*)beta)[tid];
    float4 r;
    r.x = a4.x * (v.x - mu) * rstd + b4.x;
    r.y = a4.y * (v.y - mu) * rstd + b4.y;
    r.z = a4.z * (v.z - mu) * rstd + b4.z;
    r.w = a4.w * (v.w - mu) * rstd + b4.w;
    ((float4*)(out + (size_t)row * DM))[tid] = r;
}

// ---------------------------------------------------------------------------
extern "C" void kernel_launch(void* const* d_in, const int* in_sizes, int n_in,
                              void* d_out, int out_size)
{
    const float* x     = (const float*)d_in[0];
    const float* wq    = (const float*)d_in[1];
    const float* qb    = (const float*)d_in[2];
    const float* wk    = (const float*)d_in[3];
    const float* kb    = (const float*)d_in[4];
    const float* wv    = (const float*)d_in[5];
    const float* vb    = (const float*)d_in[6];
    const float* wo    = (const float*)d_in[7];
    const float* ob    = (const float*)d_in[8];
    const float* alpha = (const float*)d_in[9];
    const float* beta  = (const float*)d_in[10];
    float* out = (float*)d_out;

    uint32_t *Xh, *Xl, *Wqh, *Wql, *Woh, *Wol;
    uint32_t *Qh, *Ql, *Kh, *Kl, *Vt, *Ch, *Cl;
    float *pre;
    cudaGetSymbolAddress((void**)&Xh,  g_Xh);
    cudaGetSymbolAddress((void**)&Xl,  g_Xl);
    cudaGetSymbolAddress((void**)&Wqh, g_Wqh);
    cudaGetSymbolAddress((void**)&Wql, g_Wql);
    cudaGetSymbolAddress((void**)&Woh, g_Woh);
    cudaGetSymbolAddress((void**)&Wol, g_Wol);
    cudaGetSymbolAddress((void**)&Qh,  g_Qh);
    cudaGetSymbolAddress((void**)&Ql,  g_Ql);
    cudaGetSymbolAddress((void**)&Kh,  g_Kh);
    cudaGetSymbolAddress((void**)&Kl,  g_Kl);
    cudaGetSymbolAddress((void**)&Vt,  g_Vt);
    cudaGetSymbolAddress((void**)&Ch,  g_Ch);
    cudaGetSymbolAddress((void**)&Cl,  g_Cl);
    cudaGetSymbolAddress((void**)&pre, g_pre);

    cudaFuncSetAttribute(qkv_kernel,
                         cudaFuncAttributeMaxDynamicSharedMemorySize, G_SMEM);
    cudaFuncSetAttribute(outproj_kernel,
                         cudaFuncAttributeMaxDynamicSharedMemorySize, G_SMEM);
    cudaFuncSetAttribute(attn_kernel,
                         cudaFuncAttributeMaxDynamicSharedMemorySize, ATTN_SMEM_BYTES);

    // conversions
    conv_x_kernel<<<NN, 256>>>(x, Xh, Xl);
    conv_wqkv_kernel<<<dim3(16, 1, 48), 256>>>(wq, wk, wv, Wqh, Wql);
    conv_wo_kernel<<<dim3(16, 16, 1), 256>>>(wo, Woh, Wol);

    qkv_kernel<<<dim3(NN / 128, NH, 3), 256, G_SMEM>>>(Xh, Xl, Wqh, Wql,
                                                       qb, kb, vb,
                                                       Qh, Ql, Kh, Kl, Vt);

    attn_kernel<<<dim3(NN / 128, NH), 256, ATTN_SMEM_BYTES>>>(Qh, Ql, Kh, Kl, Vt, Ch, Cl);

    outproj_kernel<<<dim3(NN / 128, DM / 64), 256, G_SMEM>>>(Ch, Cl, Woh, Wol,
                                                             x, ob, pre);

    ln_kernel<<<NN, 256>>>(pre, alpha, beta, out);
}

// round 7
// speedup vs baseline: 7.0614x; 1.0041x over previous
#include <cuda_runtime.h>
#include <cstdint>

#define NN 2048
#define DM 1024
#define NH 16
#define DK 64
#define LN_EPS 1e-5f
#define QKS 36   // u32 row stride for packed Q/K (32 pairs + 4 pad)

// Scratch (device globals)
__device__ uint32_t g_Xh[(size_t)NN * 512];
__device__ uint32_t g_Xl[(size_t)NN * 512];
__device__ uint32_t g_Wqh[(size_t)NH * 192 * 512];
__device__ uint32_t g_Wql[(size_t)NH * 192 * 512];
__device__ uint32_t g_Woh[(size_t)DM * 512];
__device__ uint32_t g_Wol[(size_t)DM * 512];
__device__ uint32_t g_Qh[(size_t)NH * NN * QKS];
__device__ uint32_t g_Ql[(size_t)NH * NN * QKS];
__device__ uint32_t g_Kh[(size_t)NH * NN * QKS];
__device__ uint32_t g_Kl[(size_t)NH * NN * QKS];
__device__ uint32_t g_Vt[(size_t)NH * DK * (NN / 2)];   // fp16 [h][dk][keypair]
__device__ uint32_t g_Ch[(size_t)NN * 512];
__device__ uint32_t g_Cl[(size_t)NN * 512];
__device__ float    g_pre[(size_t)NN * DM];

// ---------------------------------------------------------------------------
// helpers
// ---------------------------------------------------------------------------
__device__ __forceinline__ uint32_t pack2h(float e0, float e1) {  // f16x2
    uint32_t r;
    asm("cvt.rn.f16x2.f32 %0, %1, %2;" : "=r"(r) : "f"(e1), "f"(e0));
    return r;
}
__device__ __forceinline__ uint16_t f16bits(float v) {
    uint16_t u;
    asm("cvt.rn.f16.f32 %0, %1;" : "=h"(u) : "f"(v));
    return u;
}
// split pair (x0,x1) into hi-bf16x2 + lo-bf16x2 residual
__device__ __forceinline__ void split2(float x0, float x1, uint32_t& hi, uint32_t& lo) {
    uint32_t h;
    asm("cvt.rn.bf16x2.f32 %0, %1, %2;" : "=r"(h) : "f"(x1), "f"(x0));
    float h0 = __uint_as_float(h << 16);
    float h1 = __uint_as_float(h & 0xffff0000u);
    uint32_t l;
    asm("cvt.rn.bf16x2.f32 %0, %1, %2;" : "=r"(l) : "f"(x1 - h1), "f"(x0 - h0));
    hi = h; lo = l;
}
// NOTE: non-volatile — data deps enforce order; lets ptxas interleave mmas
__device__ __forceinline__ void mma_bf16(float* c, const uint32_t* a, const uint32_t* b) {
    asm("mma.sync.aligned.m16n8k16.row.col.f32.bf16.bf16.f32 "
        "{%0,%1,%2,%3}, {%4,%5,%6,%7}, {%8,%9}, {%0,%1,%2,%3};\n"
        : "+f"(c[0]), "+f"(c[1]), "+f"(c[2]), "+f"(c[3])
        : "r"(a[0]), "r"(a[1]), "r"(a[2]), "r"(a[3]), "r"(b[0]), "r"(b[1]));
}
__device__ __forceinline__ void mma_f16(float* c, const uint32_t* a, const uint32_t* b) {
    asm("mma.sync.aligned.m16n8k16.row.col.f32.f16.f16.f32 "
        "{%0,%1,%2,%3}, {%4,%5,%6,%7}, {%8,%9}, {%0,%1,%2,%3};\n"
        : "+f"(c[0]), "+f"(c[1]), "+f"(c[2]), "+f"(c[3])
        : "r"(a[0]), "r"(a[1]), "r"(a[2]), "r"(a[3]), "r"(b[0]), "r"(b[1]));
}
__device__ __forceinline__ void ldsm_x4(uint32_t* r, const uint32_t* p) {
    uint32_t addr = (uint32_t)__cvta_generic_to_shared(p);
    asm volatile("ldmatrix.sync.aligned.m8n8.x4.shared.b16 {%0,%1,%2,%3}, [%4];"
        : "=r"(r[0]), "=r"(r[1]), "=r"(r[2]), "=r"(r[3]) : "r"(addr));
}
#define CPA16(sptr, gptr) do {                                                 \
    uint32_t _s = (uint32_t)__cvta_generic_to_shared(sptr);                    \
    asm volatile("cp.async.cg.shared.global [%0], [%1], 16;" :: "r"(_s), "l"(gptr)); \
} while (0)
#define CP_COMMIT() asm volatile("cp.async.commit_group;")
#define CP_WAIT(n)  asm volatile("cp.async.wait_group %0;" :: "n"(n))

// ---------------------------------------------------------------------------
// conversion kernels
// ---------------------------------------------------------------------------
__global__ void __launch_bounds__(256) conv_x_kernel(const float* __restrict__ x,
                                                     uint32_t* __restrict__ Xh,
                                                     uint32_t* __restrict__ Xl)
{
    const int r = blockIdx.x, t = threadIdx.x;
    float4 v = ((const float4*)x)[r * 256 + t];
    uint32_t h0, l0, h1, l1;
    split2(v.x, v.y, h0, l0);
    split2(v.z, v.w, h1, l1);
    Xh[(size_t)r * 512 + 2 * t]     = h0;  Xl[(size_t)r * 512 + 2 * t]     = l0;
    Xh[(size_t)r * 512 + 2 * t + 1] = h1;  Xl[(size_t)r * 512 + 2 * t + 1] = l1;
}

__global__ void __launch_bounds__(256) conv_wqkv_kernel(const float* __restrict__ wq,
                                                        const float* __restrict__ wk,
                                                        const float* __restrict__ wv,
                                                        uint32_t* __restrict__ dstH,
                                                        uint32_t* __restrict__ dstL)
{
    __shared__ float sw[64][65];
    const int k0 = blockIdx.x * 64;
    const int z  = blockIdx.z;
    const int sec = z >> 4, h = z & 15;
    const int t  = threadIdx.x;
    const float* s = (sec == 0 ? wq : sec == 1 ? wk : wv) + (size_t)h * DM * DK;

    #pragma unroll
    for (int i = 0; i < 16; i++) {
        int idx = i * 256 + t;
        int row = idx >> 6, col = idx & 63;
        sw[row][col] = s[(size_t)(k0 + row) * DK + col];
    }
    __syncthreads();
    #pragma unroll
    for (int i = 0; i < 8; i++) {
        int idx = i * 256 + t;
        int n = idx >> 5, kp = idx & 31;
        uint32_t hh, ll;
        split2(sw[2 * kp][n], sw[2 * kp + 1][n], hh, ll);
        size_t o = (size_t)h * (192 * 512) + (size_t)(sec * 64 + n) * 512 + k0 / 2 + kp;
        dstH[o] = hh;  dstL[o] = ll;
    }
}

__global__ void __launch_bounds__(256) conv_wo_kernel(const float* __restrict__ src,
                                                      uint32_t* __restrict__ dstH,
                                                      uint32_t* __restrict__ dstL)
{
    __shared__ float sw[64][65];
    const int k0 = blockIdx.x * 64;
    const int n0 = blockIdx.y * 64;
    const int t  = threadIdx.x;

    #pragma unroll
    for (int i = 0; i < 16; i++) {
        int idx = i * 256 + t;
        int row = idx >> 6, col = idx & 63;
        sw[row][col] = src[(size_t)(k0 + row) * DM + n0 + col];
    }
    __syncthreads();
    #pragma unroll
    for (int i = 0; i < 8; i++) {
        int idx = i * 256 + t;
        int n = idx >> 5, kp = idx & 31;
        uint32_t hh, ll;
        split2(sw[2 * kp][n], sw[2 * kp + 1][n], hh, ll);
        size_t o = (size_t)(n0 + n) * 512 + k0 / 2 + kp;
        dstH[o] = hh;  dstL[o] = ll;
    }
}

// ---------------------------------------------------------------------------
// GEMM tile machinery: 128 rows x 64 cols, k-chunk 32, 2-stage cp.async,
// 3-term bf16, LDSM loads, TERM-MAJOR mma order (RAW spacing = 8 mmas).
// ---------------------------------------------------------------------------
#define G_STAGE_U32 7680
#define G_SMEM (2 * G_STAGE_U32 * 4)

__device__ __forceinline__ void gemm_stage_load(uint32_t* st,
                                                const uint32_t* Ahg, const uint32_t* Alg,
                                                const uint32_t* Bhg, const uint32_t* Blg,
                                                int kc16, int tid)
{
    #pragma unroll
    for (int i = 0; i < 2; i++) {
        int idx = tid + i * 256;               // 0..511
        int row = idx >> 2, sg = (idx & 3) * 4;
        CPA16(st + row * 20 + sg,        Ahg + (size_t)row * 512 + kc16 + sg);
        CPA16(st + 2560 + row * 20 + sg, Alg + (size_t)row * 512 + kc16 + sg);
    }
    {
        int row = tid >> 2, sg = (tid & 3) * 4;  // rows 0..63
        CPA16(st + 5120 + row * 20 + sg, Bhg + (size_t)row * 512 + kc16 + sg);
        CPA16(st + 6400 + row * 20 + sg, Blg + (size_t)row * 512 + kc16 + sg);
    }
}

__device__ __forceinline__ void gemm_core(uint32_t* sm, float (*acc)[4],
                                          const uint32_t* Ahg, const uint32_t* Alg,
                                          const uint32_t* Bhg, const uint32_t* Blg,
                                          int tid, int aoff, int boff)
{
    gemm_stage_load(sm, Ahg, Alg, Bhg, Blg, 0, tid);
    CP_COMMIT();

    for (int c = 0; c < 32; c++) {
        if (c < 31) {
            gemm_stage_load(sm + ((c + 1) & 1) * G_STAGE_U32,
                            Ahg, Alg, Bhg, Blg, (c + 1) * 16, tid);
            CP_COMMIT();
            CP_WAIT(1);
        } else {
            CP_WAIT(0);
        }
        __syncthreads();

        const uint32_t* p  = sm + (c & 1) * G_STAGE_U32;
        const uint32_t* Ah = p;
        const uint32_t* Al = p + 2560;
        const uint32_t* Bh = p + 5120;
        const uint32_t* Bl = p + 6400;

        #pragma unroll
        for (int ks = 0; ks < 2; ks++) {
            uint32_t ah[4], al[4];
            ldsm_x4(ah, Ah + aoff + ks * 8);
            ldsm_x4(al, Al + aoff + ks * 8);
            // term 1: hh across all accumulators
            #pragma unroll
            for (int nbp = 0; nbp < 4; nbp++) {
                uint32_t bh[4];
                ldsm_x4(bh, Bh + boff + nbp * 320 + ks * 8);
                mma_bf16(acc[2 * nbp],     ah, bh);
                mma_bf16(acc[2 * nbp + 1], ah, bh + 2);
            }
            // term 2: lh
            #pragma unroll
            for (int nbp = 0; nbp < 4; nbp++) {
                uint32_t bh[4];
                ldsm_x4(bh, Bh + boff + nbp * 320 + ks * 8);
                mma_bf16(acc[2 * nbp],     al, bh);
                mma_bf16(acc[2 * nbp + 1], al, bh + 2);
            }
            // term 3: hl
            #pragma unroll
            for (int nbp = 0; nbp < 4; nbp++) {
                uint32_t bl[4];
                ldsm_x4(bl, Bl + boff + nbp * 320 + ks * 8);
                mma_bf16(acc[2 * nbp],     ah, bl);
                mma_bf16(acc[2 * nbp + 1], ah, bl + 2);
            }
        }
        __syncthreads();
    }
}

// ---------------------------------------------------------------------------
// QKV GEMM: CTA = (row-tile, head, section). section: 0=Q, 1=K, 2=V.
// ---------------------------------------------------------------------------
__global__ void __launch_bounds__(256, 3) qkv_kernel(const uint32_t* __restrict__ Xh,
                                                     const uint32_t* __restrict__ Xl,
                                                     const uint32_t* __restrict__ Wh,
                                                     const uint32_t* __restrict__ Wl,
                                                     const float* __restrict__ qb,
                                                     const float* __restrict__ kb,
                                                     const float* __restrict__ vb,
                                                     uint32_t* __restrict__ oQh,
                                                     uint32_t* __restrict__ oQl,
                                                     uint32_t* __restrict__ oKh,
                                                     uint32_t* __restrict__ oKl,
                                                     uint32_t* __restrict__ oVt)
{
    extern __shared__ uint32_t sm[];
    const int m0  = blockIdx.x * 128;
    const int h   = blockIdx.y;
    const int sec = blockIdx.z;
    const int tid = threadIdx.x;
    const int wid = tid >> 5, lane = tid & 31, g = lane >> 2, t = lane & 3;
    const int lrow = lane & 7;
    const int aoff = (wid * 16 + lrow + ((lane >> 3) & 1) * 8) * 20 + (lane >> 4) * 4;
    const int boff = (lrow + ((lane >> 4) & 1) * 8) * 20 + ((lane >> 3) & 1) * 4;

    float acc[8][4] = {};

    gemm_core(sm, acc,
              Xh + (size_t)m0 * 512, Xl + (size_t)m0 * 512,
              Wh + ((size_t)h * 192 + sec * 64) * 512,
              Wl + ((size_t)h * 192 + sec * 64) * 512,
              tid, aoff, boff);

    const int r = wid * 16 + g;
    const int grow = m0 + r;

    if (sec <= 1) {
        const float scl = (sec == 0) ? 0.125f : 1.0f;
        const float* bias = (sec == 0) ? qb : kb;
        uint32_t* oH = (sec == 0) ? oQh : oKh;
        uint32_t* oL = (sec == 0) ? oQl : oKl;
        #pragma unroll
        for (int nb = 0; nb < 8; nb++) {
            int col = nb * 8 + 2 * t;
            float b0 = bias[h * DK + col], b1 = bias[h * DK + col + 1];
            uint32_t h0, l0, h1, l1;
            split2((acc[nb][0] + b0) * scl, (acc[nb][1] + b1) * scl, h0, l0);
            split2((acc[nb][2] + b0) * scl, (acc[nb][3] + b1) * scl, h1, l1);
            size_t base = ((size_t)h * NN + grow) * QKS + nb * 4 + t;
            oH[base] = h0;            oL[base] = l0;
            oH[base + 8 * QKS] = h1;  oL[base + 8 * QKS] = l1;
        }
    } else {
        // V: fp16 transpose via smem  ([64 dk][132] fp16 = stride 66 u32)
        uint16_t* Vs16 = (uint16_t*)sm;
        #pragma unroll
        for (int nb = 0; nb < 8; nb++) {
            int col = nb * 8 + 2 * t;
            float b0 = vb[h * DK + col], b1 = vb[h * DK + col + 1];
            Vs16[(col)     * 132 + r]     = f16bits(acc[nb][0] + b0);
            Vs16[(col + 1) * 132 + r]     = f16bits(acc[nb][1] + b1);
            Vs16[(col)     * 132 + r + 8] = f16bits(acc[nb][2] + b0);
            Vs16[(col + 1) * 132 + r + 8] = f16bits(acc[nb][3] + b1);
        }
        __syncthreads();
        #pragma unroll
        for (int i = 0; i < 16; i++) {
            int idx = tid + i * 256;
            int dk = idx >> 6, cc = idx & 63;
            oVt[((size_t)h * DK + dk) * (NN / 2) + m0 / 2 + cc] = sm[dk * 66 + cc];
        }
    }
}

// ---------------------------------------------------------------------------
// Out projection + bias + residual: CTA = (row-tile, 64-col tile).
// ---------------------------------------------------------------------------
__global__ void __launch_bounds__(256, 3) outproj_kernel(const uint32_t* __restrict__ Ahg,
                                                         const uint32_t* __restrict__ Alg,
                                                         const uint32_t* __restrict__ Bhg,
                                                         const uint32_t* __restrict__ Blg,
                                                         const float* __restrict__ x,
                                                         const float* __restrict__ ob,
                                                         float* __restrict__ out)
{
    extern __shared__ uint32_t sm[];
    const int m0 = blockIdx.x * 128;
    const int c0 = blockIdx.y * 64;
    const int tid = threadIdx.x;
    const int wid = tid >> 5, lane = tid & 31, g = lane >> 2, t = lane & 3;
    const int lrow = lane & 7;
    const int aoff = (wid * 16 + lrow + ((lane >> 3) & 1) * 8) * 20 + (lane >> 4) * 4;
    const int boff = (lrow + ((lane >> 4) & 1) * 8) * 20 + ((lane >> 3) & 1) * 4;

    float acc[8][4] = {};

    gemm_core(sm, acc,
              Ahg + (size_t)m0 * 512, Alg + (size_t)m0 * 512,
              Bhg + (size_t)c0 * 512, Blg + (size_t)c0 * 512,
              tid, aoff, boff);

    const int r0 = m0 + wid * 16 + g;
    #pragma unroll
    for (int nb = 0; nb < 8; nb++) {
        int col = c0 + nb * 8 + 2 * t;
        float b0 = ob[col], b1 = ob[col + 1];
        const float* xr0 = &x[(size_t)r0 * DM + col];
        const float* xr1 = &x[(size_t)(r0 + 8) * DM + col];
        float2 v0 = make_float2(acc[nb][0] + b0 + xr0[0], acc[nb][1] + b1 + xr0[1]);
        float2 v1 = make_float2(acc[nb][2] + b0 + xr1[0], acc[nb][3] + b1 + xr1[1]);
        *(float2*)&out[(size_t)r0 * DM + col]       = v0;
        *(float2*)&out[(size_t)(r0 + 8) * DM + col] = v1;
    }
}

// ---------------------------------------------------------------------------
// Flash attention, bf16 QK (3-term, term-major) + fp16 PV.
// ---------------------------------------------------------------------------
#define ATTN_BUF_U32 (3 * 64 * 36)
#define ATTN_SMEM_BYTES (2 * ATTN_BUF_U32 * 4)

__device__ __forceinline__ void attn_stage(uint32_t* dst, const uint32_t* Kh,
                                           const uint32_t* Kl, const uint32_t* Vt,
                                           int h, int t0, int tid)
{
    const uint32_t* sKh = Kh + ((size_t)h * NN + t0) * QKS;
    const uint32_t* sKl = Kl + ((size_t)h * NN + t0) * QKS;
    const uint32_t* sVt = Vt + (size_t)h * DK * (NN / 2) + t0 / 2;
    for (int idx = tid; idx < 1664; idx += 256) {
        if (idx < 576) {
            CPA16(dst + idx * 4, sKh + idx * 4);
        } else if (idx < 1152) {
            int j = idx - 576;
            CPA16(dst + 2304 + j * 4, sKl + j * 4);
        } else {
            int j = idx - 1152;
            int dk = j >> 3, c = (j & 7) * 4;
            CPA16(dst + 4608 + dk * 36 + c, sVt + (size_t)dk * (NN / 2) + c);
        }
    }
}

__global__ void __launch_bounds__(256, 2) attn_kernel(const uint32_t* __restrict__ Qh,
                                                      const uint32_t* __restrict__ Ql,
                                                      const uint32_t* __restrict__ Kh,
                                                      const uint32_t* __restrict__ Kl,
                                                      const uint32_t* __restrict__ Vt,
                                                      uint32_t* __restrict__ Ch,
                                                      uint32_t* __restrict__ Cl)
{
    extern __shared__ uint32_t sm[];
    const int h  = blockIdx.y;
    const int q0 = blockIdx.x * 128;
    const int tid = threadIdx.x;
    const int wid = tid >> 5, lane = tid & 31, g = lane >> 2, t = lane & 3;
    const int lrow = lane & 7;
    const int boff = (lrow + ((lane >> 4) & 1) * 8) * 36 + ((lane >> 3) & 1) * 4;

    attn_stage(sm, Kh, Kl, Vt, h, 0, tid);
    CP_COMMIT();

    uint32_t ah[4][4], al[4][4];
    {
        const uint32_t* qh = Qh + ((size_t)h * NN + q0 + wid * 16 + g) * QKS;
        const uint32_t* ql = Ql + ((size_t)h * NN + q0 + wid * 16 + g) * QKS;
        #pragma unroll
        for (int ks = 0; ks < 4; ks++) {
            ah[ks][0] = qh[ks * 8 + t];       ah[ks][1] = qh[8 * QKS + ks * 8 + t];
            ah[ks][2] = qh[ks * 8 + t + 4];   ah[ks][3] = qh[8 * QKS + ks * 8 + t + 4];
            al[ks][0] = ql[ks * 8 + t];       al[ks][1] = ql[8 * QKS + ks * 8 + t];
            al[ks][2] = ql[ks * 8 + t + 4];   al[ks][3] = ql[8 * QKS + ks * 8 + t + 4];
        }
    }

    float o[8][4] = {};
    float m0 = -1e30f, m1 = -1e30f, l0 = 0.f, l1 = 0.f;

    for (int tt = 0; tt < NN / 64; tt++) {
        uint32_t* buf = sm + (tt & 1) * ATTN_BUF_U32;
        if (tt + 1 < NN / 64) {
            attn_stage(sm + ((tt + 1) & 1) * ATTN_BUF_U32, Kh, Kl, Vt, h, (tt + 1) * 64, tid);
            CP_COMMIT();
            CP_WAIT(1);
        } else {
            CP_WAIT(0);
        }
        __syncthreads();

        const uint32_t* kh = buf;
        const uint32_t* kl = buf + 2304;
        const uint32_t* vs = buf + 4608;

        float s[8][4] = {};
        #pragma unroll
        for (int ks = 0; ks < 4; ks++) {
            // term 1: hh
            #pragma unroll
            for (int nbp = 0; nbp < 4; nbp++) {
                uint32_t bh[4];
                ldsm_x4(bh, kh + boff + nbp * 576 + ks * 8);
                mma_bf16(s[2 * nbp],     ah[ks], bh);
                mma_bf16(s[2 * nbp + 1], ah[ks], bh + 2);
            }
            // term 2: lh
            #pragma unroll
            for (int nbp = 0; nbp < 4; nbp++) {
                uint32_t bh[4];
                ldsm_x4(bh, kh + boff + nbp * 576 + ks * 8);
                mma_bf16(s[2 * nbp],     al[ks], bh);
                mma_bf16(s[2 * nbp + 1], al[ks], bh + 2);
            }
            // term 3: hl
            #pragma unroll
            for (int nbp = 0; nbp < 4; nbp++) {
                uint32_t bl[4];
                ldsm_x4(bl, kl + boff + nbp * 576 + ks * 8);
                mma_bf16(s[2 * nbp],     ah[ks], bl);
                mma_bf16(s[2 * nbp + 1], ah[ks], bl + 2);
            }
        }

        float mx0 = -1e30f, mx1 = -1e30f;
        #pragma unroll
        for (int nb = 0; nb < 8; nb++) {
            mx0 = fmaxf(mx0, fmaxf(s[nb][0], s[nb][1]));
            mx1 = fmaxf(mx1, fmaxf(s[nb][2], s[nb][3]));
        }
        mx0 = fmaxf(mx0, __shfl_xor_sync(0xffffffffu, mx0, 1));
        mx0 = fmaxf(mx0, __shfl_xor_sync(0xffffffffu, mx0, 2));
        mx1 = fmaxf(mx1, __shfl_xor_sync(0xffffffffu, mx1, 1));
        mx1 = fmaxf(mx1, __shfl_xor_sync(0xffffffffu, mx1, 2));

        float nm0 = fmaxf(m0, mx0), nm1 = fmaxf(m1, mx1);
        float sc0 = __expf(m0 - nm0), sc1 = __expf(m1 - nm1);
        float sum0 = 0.f, sum1 = 0.f;
        #pragma unroll
        for (int nb = 0; nb < 8; nb++) {
            s[nb][0] = __expf(s[nb][0] - nm0);
            s[nb][1] = __expf(s[nb][1] - nm0);
            s[nb][2] = __expf(s[nb][2] - nm1);
            s[nb][3] = __expf(s[nb][3] - nm1);
            sum0 += s[nb][0] + s[nb][1];
            sum1 += s[nb][2] + s[nb][3];
        }
        sum0 += __shfl_xor_sync(0xffffffffu, sum0, 1);
        sum0 += __shfl_xor_sync(0xffffffffu, sum0, 2);
        sum1 += __shfl_xor_sync(0xffffffffu, sum1, 1);
        sum1 += __shfl_xor_sync(0xffffffffu, sum1, 2);
        l0 = l0 * sc0 + sum0;  m0 = nm0;
        l1 = l1 * sc1 + sum1;  m1 = nm1;
        #pragma unroll
        for (int nb = 0; nb < 8; nb++) {
            o[nb][0] *= sc0; o[nb][1] *= sc0;
            o[nb][2] *= sc1; o[nb][3] *= sc1;
        }

        // O += P V  (fp16; acc reuse spacing already 8)
        #pragma unroll
        for (int kp = 0; kp < 4; kp++) {
            uint32_t ap[4];
            ap[0] = pack2h(s[2 * kp][0],     s[2 * kp][1]);
            ap[1] = pack2h(s[2 * kp][2],     s[2 * kp][3]);
            ap[2] = pack2h(s[2 * kp + 1][0], s[2 * kp + 1][1]);
            ap[3] = pack2h(s[2 * kp + 1][2], s[2 * kp + 1][3]);
            #pragma unroll
            for (int nbp = 0; nbp < 4; nbp++) {
                uint32_t b[4];
                ldsm_x4(b, vs + boff + nbp * 576 + kp * 8);
                mma_f16(o[2 * nbp],     ap, b);
                mma_f16(o[2 * nbp + 1], ap, b + 2);
            }
        }
        __syncthreads();
    }

    // epilogue: write concat as split bf16 pairs
    const float inv0 = 1.0f / l0, inv1 = 1.0f / l1;
    const int r0 = q0 + wid * 16 + g;
    #pragma unroll
    for (int nb = 0; nb < 8; nb++) {
        int cpi = h * 32 + nb * 4 + t;
        uint32_t h0, lo0, h1, lo1;
        split2(o[nb][0] * inv0, o[nb][1] * inv0, h0, lo0);
        split2(o[nb][2] * inv1, o[nb][3] * inv1, h1, lo1);
        Ch[(size_t)r0 * 512 + cpi]       = h0;  Cl[(size_t)r0 * 512 + cpi]       = lo0;
        Ch[(size_t)(r0 + 8) * 512 + cpi] = h1;  Cl[(size_t)(r0 + 8) * 512 + cpi] = lo1;
    }
}

// ---------------------------------------------------------------------------
// LayerNorm, one block per row
// ---------------------------------------------------------------------------
__global__ void __launch_bounds__(256) ln_kernel(const float* __restrict__ pre,
                                                 const float* __restrict__ alpha,
                                                 const float* __restrict__ beta,
                                                 float* __restrict__ out)
{
    const int row = blockIdx.x;
    const int tid = threadIdx.x;
    const float4 v = ((const float4*)(pre + (size_t)row * DM))[tid];

    float sum = v.x + v.y + v.z + v.w;
    float sq  = v.x * v.x + v.y * v.y + v.z * v.z + v.w * v.w;

    #pragma unroll
    for (int d = 16; d >= 1; d >>= 1) {
        sum += __shfl_xor_sync(0xffffffffu, sum, d);
        sq  += __shfl_xor_sync(0xffffffffu, sq,  d);
    }

    __shared__ float ssum[8], ssq[8];
    __shared__ float s_mu, s_rstd;
    int warp = tid >> 5, lane = tid & 31;
    if (lane == 0) { ssum[warp] = sum; ssq[warp] = sq; }
    __syncthreads();
    if (tid == 0) {
        float ts = 0.f, tq = 0.f;
        #pragma unroll
        for (int i = 0; i < 8; i++) { ts += ssum[i]; tq += ssq[i]; }
        float mu  = ts * (1.0f / DM);
        float var = tq * (1.0f / DM) - mu * mu;
        s_mu = mu;
        s_rstd = rsqrtf(var + LN_EPS);
    }
    __syncthreads();

    const float mu = s_mu, rstd = s_rstd;
    const float4 a4 = ((const float4*)alpha)[tid];
    const float4 b4 = ((const float4*)beta)[tid];
    float4 r;
    r.x = a4.x * (v.x - mu) * rstd + b4.x;
    r.y = a4.y * (v.y - mu) * rstd + b4.y;
    r.z = a4.z * (v.z - mu) * rstd + b4.z;
    r.w = a4.w * (v.w - mu) * rstd + b4.w;
    ((float4*)(out + (size_t)row * DM))[tid] = r;
}

// ---------------------------------------------------------------------------
extern "C" void kernel_launch(void* const* d_in, const int* in_sizes, int n_in,
                              void* d_out, int out_size)
{
    const float* x     = (const float*)d_in[0];
    const float* wq    = (const float*)d_in[1];
    const float* qb    = (const float*)d_in[2];
    const float* wk    = (const float*)d_in[3];
    const float* kb    = (const float*)d_in[4];
    const float* wv    = (const float*)d_in[5];
    const float* vb    = (const float*)d_in[6];
    const float* wo    = (const float*)d_in[7];
    const float* ob    = (const float*)d_in[8];
    const float* alpha = (const float*)d_in[9];
    const float* beta  = (const float*)d_in[10];
    float* out = (float*)d_out;

    uint32_t *Xh, *Xl, *Wqh, *Wql, *Woh, *Wol;
    uint32_t *Qh, *Ql, *Kh, *Kl, *Vt, *Ch, *Cl;
    float *pre;
    cudaGetSymbolAddress((void**)&Xh,  g_Xh);
    cudaGetSymbolAddress((void**)&Xl,  g_Xl);
    cudaGetSymbolAddress((void**)&Wqh, g_Wqh);
    cudaGetSymbolAddress((void**)&Wql, g_Wql);
    cudaGetSymbolAddress((void**)&Woh, g_Woh);
    cudaGetSymbolAddress((void**)&Wol, g_Wol);
    cudaGetSymbolAddress((void**)&Qh,  g_Qh);
    cudaGetSymbolAddress((void**)&Ql,  g_Ql);
    cudaGetSymbolAddress((void**)&Kh,  g_Kh);
    cudaGetSymbolAddress((void**)&Kl,  g_Kl);
    cudaGetSymbolAddress((void**)&Vt,  g_Vt);
    cudaGetSymbolAddress((void**)&Ch,  g_Ch);
    cudaGetSymbolAddress((void**)&Cl,  g_Cl);
    cudaGetSymbolAddress((void**)&pre, g_pre);

    cudaFuncSetAttribute(qkv_kernel,
                         cudaFuncAttributeMaxDynamicSharedMemorySize, G_SMEM);
    cudaFuncSetAttribute(outproj_kernel,
                         cudaFuncAttributeMaxDynamicSharedMemorySize, G_SMEM);
    cudaFuncSetAttribute(attn_kernel,
                         cudaFuncAttributeMaxDynamicSharedMemorySize, ATTN_SMEM_BYTES);

    // conversions
    conv_x_kernel<<<NN, 256>>>(x, Xh, Xl);
    conv_wqkv_kernel<<<dim3(16, 1, 48), 256>>>(wq, wk, wv, Wqh, Wql);
    conv_wo_kernel<<<dim3(16, 16, 1), 256>>>(wo, Woh, Wol);

    qkv_kernel<<<dim3(NN / 128, NH, 3), 256, G_SMEM>>>(Xh, Xl, Wqh, Wql,
                                                       qb, kb, vb,
                                                       Qh, Ql, Kh, Kl, Vt);

    attn_kernel<<<dim3(NN / 128, NH), 256, ATTN_SMEM_BYTES>>>(Qh, Ql, Kh, Kl, Vt, Ch, Cl);

    outproj_kernel<<<dim3(NN / 128, DM / 64), 256, G_SMEM>>>(Ch, Cl, Woh, Wol,
                                                             x, ob, pre);

    ln_kernel<<<NN, 256>>>(pre, alpha, beta, out);
}

// round 9
// speedup vs baseline: 9.2146x; 1.3049x over previous
#include <cuda_runtime.h>
#include <cuda_fp16.h>
#include <cstdint>

#define NN 2048
#define DM 1024
#define NH 16
#define DK 64
#define LN_EPS 1e-5f
#define QKS 36   // u32 row stride for packed Q/K (32 pairs + 4 pad)

// Scratch (device globals) — fp16 pair arrays (u32 = f16x2)
__device__ uint32_t g_Xh[(size_t)NN * 512];
__device__ uint32_t g_Xl[(size_t)NN * 512];
__device__ uint32_t g_Wq[(size_t)NH * 192 * 512];     // single fp16
__device__ uint32_t g_Wo[(size_t)DM * 512];           // single fp16
__device__ uint32_t g_Qh[(size_t)NH * NN * QKS];
__device__ uint32_t g_Ql[(size_t)NH * NN * QKS];
__device__ uint32_t g_Kh[(size_t)NH * NN * QKS];      // single fp16
__device__ uint32_t g_Vt[(size_t)NH * DK * (NN / 2)]; // fp16 [h][dk][keypair]
__device__ uint32_t g_Ch[(size_t)NN * 512];
__device__ uint32_t g_Cl[(size_t)NN * 512];
__device__ float    g_pre[(size_t)NN * DM];

// ---------------------------------------------------------------------------
// helpers
// ---------------------------------------------------------------------------
__device__ __forceinline__ uint32_t pack2h(float e0, float e1) {  // f16x2: e0 low
    uint32_t r;
    asm("cvt.rn.f16x2.f32 %0, %1, %2;" : "=r"(r) : "f"(e1), "f"(e0));
    return r;
}
__device__ __forceinline__ uint16_t f16bits(float v) {
    uint16_t u;
    asm("cvt.rn.f16.f32 %0, %1;" : "=h"(u) : "f"(v));
    return u;
}
// split pair (x0,x1) into hi-f16x2 + lo-f16x2 residual
__device__ __forceinline__ void split2h(float x0, float x1, uint32_t& hi, uint32_t& lo) {
    __half2 h = __floats2half2_rn(x0, x1);
    float2 hf = __half22float2(h);
    __half2 l = __floats2half2_rn(x0 - hf.x, x1 - hf.y);
    hi = *(uint32_t*)&h;
    lo = *(uint32_t*)&l;
}
__device__ __forceinline__ void mma_f16(float* c, const uint32_t* a, const uint32_t* b) {
    asm("mma.sync.aligned.m16n8k16.row.col.f32.f16.f16.f32 "
        "{%0,%1,%2,%3}, {%4,%5,%6,%7}, {%8,%9}, {%0,%1,%2,%3};\n"
        : "+f"(c[0]), "+f"(c[1]), "+f"(c[2]), "+f"(c[3])
        : "r"(a[0]), "r"(a[1]), "r"(a[2]), "r"(a[3]), "r"(b[0]), "r"(b[1]));
}
__device__ __forceinline__ void ldsm_x4(uint32_t* r, const uint32_t* p) {
    uint32_t addr = (uint32_t)__cvta_generic_to_shared(p);
    asm volatile("ldmatrix.sync.aligned.m8n8.x4.shared.b16 {%0,%1,%2,%3}, [%4];"
        : "=r"(r[0]), "=r"(r[1]), "=r"(r[2]), "=r"(r[3]) : "r"(addr));
}
#define CPA16(sptr, gptr) do {                                                 \
    uint32_t _s = (uint32_t)__cvta_generic_to_shared(sptr);                    \
    asm volatile("cp.async.cg.shared.global [%0], [%1], 16;" :: "r"(_s), "l"(gptr)); \
} while (0)
#define CP_COMMIT() asm volatile("cp.async.commit_group;")
#define CP_WAIT(n)  asm volatile("cp.async.wait_group %0;" :: "n"(n))

// ---------------------------------------------------------------------------
// conversion kernels
// ---------------------------------------------------------------------------
__global__ void __launch_bounds__(256) conv_x_kernel(const float* __restrict__ x,
                                                     uint32_t* __restrict__ Xh,
                                                     uint32_t* __restrict__ Xl)
{
    const int r = blockIdx.x, t = threadIdx.x;
    float4 v = ((const float4*)x)[r * 256 + t];
    uint32_t h0, l0, h1, l1;
    split2h(v.x, v.y, h0, l0);
    split2h(v.z, v.w, h1, l1);
    Xh[(size_t)r * 512 + 2 * t]     = h0;  Xl[(size_t)r * 512 + 2 * t]     = l0;
    Xh[(size_t)r * 512 + 2 * t + 1] = h1;  Xl[(size_t)r * 512 + 2 * t + 1] = l1;
}

// fused wq/wk/wv: single fp16, [h][sec*64+n][kpair], row stride 512 u32
__global__ void __launch_bounds__(256) conv_wqkv_kernel(const float* __restrict__ wq,
                                                        const float* __restrict__ wk,
                                                        const float* __restrict__ wv,
                                                        uint32_t* __restrict__ dst)
{
    __shared__ float sw[64][65];
    const int k0 = blockIdx.x * 64;
    const int z  = blockIdx.z;
    const int sec = z >> 4, h = z & 15;
    const int t  = threadIdx.x;
    const float* s = (sec == 0 ? wq : sec == 1 ? wk : wv) + (size_t)h * DM * DK;

    #pragma unroll
    for (int i = 0; i < 16; i++) {
        int idx = i * 256 + t;
        int row = idx >> 6, col = idx & 63;
        sw[row][col] = s[(size_t)(k0 + row) * DK + col];
    }
    __syncthreads();
    #pragma unroll
    for (int i = 0; i < 8; i++) {
        int idx = i * 256 + t;
        int n = idx >> 5, kp = idx & 31;
        size_t o = (size_t)h * (192 * 512) + (size_t)(sec * 64 + n) * 512 + k0 / 2 + kp;
        dst[o] = pack2h(sw[2 * kp][n], sw[2 * kp + 1][n]);
    }
}

__global__ void __launch_bounds__(256) conv_wo_kernel(const float* __restrict__ src,
                                                      uint32_t* __restrict__ dst)
{
    __shared__ float sw[64][65];
    const int k0 = blockIdx.x * 64;
    const int n0 = blockIdx.y * 64;
    const int t  = threadIdx.x;

    #pragma unroll
    for (int i = 0; i < 16; i++) {
        int idx = i * 256 + t;
        int row = idx >> 6, col = idx & 63;
        sw[row][col] = src[(size_t)(k0 + row) * DM + n0 + col];
    }
    __syncthreads();
    #pragma unroll
    for (int i = 0; i < 8; i++) {
        int idx = i * 256 + t;
        int n = idx >> 5, kp = idx & 31;
        size_t o = (size_t)(n0 + n) * 512 + k0 / 2 + kp;
        dst[o] = pack2h(sw[2 * kp][n], sw[2 * kp + 1][n]);
    }
}

// ---------------------------------------------------------------------------
// GEMM tile machinery: 128 rows x 64 cols, k-chunk 32, 2-stage cp.async.
// 2-term fp16: A split (Ah+Al), B single. LDSM loads, term-major order.
// Stage = Ah(2560) + Al(2560) + B(1280) = 6400 u32 = 25600 B; 2 stages = 51200 B.
// ---------------------------------------------------------------------------
#define G_STAGE_U32 6400
#define G_SMEM (2 * G_STAGE_U32 * 4)

__device__ __forceinline__ void gemm_stage_load(uint32_t* st,
                                                const uint32_t* Ahg, const uint32_t* Alg,
                                                const uint32_t* Bg,
                                                int kc16, int tid)
{
    #pragma unroll
    for (int i = 0; i < 2; i++) {
        int idx = tid + i * 256;               // 0..511
        int row = idx >> 2, sg = (idx & 3) * 4;
        CPA16(st + row * 20 + sg,        Ahg + (size_t)row * 512 + kc16 + sg);
        CPA16(st + 2560 + row * 20 + sg, Alg + (size_t)row * 512 + kc16 + sg);
    }
    {
        int row = tid >> 2, sg = (tid & 3) * 4;  // rows 0..63
        CPA16(st + 5120 + row * 20 + sg, Bg + (size_t)row * 512 + kc16 + sg);
    }
}

__device__ __forceinline__ void gemm_core(uint32_t* sm, float (*acc)[4],
                                          const uint32_t* Ahg, const uint32_t* Alg,
                                          const uint32_t* Bg,
                                          int tid, int aoff, int boff)
{
    gemm_stage_load(sm, Ahg, Alg, Bg, 0, tid);
    CP_COMMIT();

    for (int c = 0; c < 32; c++) {
        if (c < 31) {
            gemm_stage_load(sm + ((c + 1) & 1) * G_STAGE_U32,
                            Ahg, Alg, Bg, (c + 1) * 16, tid);
            CP_COMMIT();
            CP_WAIT(1);
        } else {
            CP_WAIT(0);
        }
        __syncthreads();

        const uint32_t* p  = sm + (c & 1) * G_STAGE_U32;
        const uint32_t* Ah = p;
        const uint32_t* Al = p + 2560;
        const uint32_t* Bs = p + 5120;

        #pragma unroll
        for (int ks = 0; ks < 2; ks++) {
            uint32_t ah[4], al[4];
            ldsm_x4(ah, Ah + aoff + ks * 8);
            ldsm_x4(al, Al + aoff + ks * 8);
            // term 1: hi
            #pragma unroll
            for (int nbp = 0; nbp < 4; nbp++) {
                uint32_t b[4];
                ldsm_x4(b, Bs + boff + nbp * 320 + ks * 8);
                mma_f16(acc[2 * nbp],     ah, b);
                mma_f16(acc[2 * nbp + 1], ah, b + 2);
            }
            // term 2: lo
            #pragma unroll
            for (int nbp = 0; nbp < 4; nbp++) {
                uint32_t b[4];
                ldsm_x4(b, Bs + boff + nbp * 320 + ks * 8);
                mma_f16(acc[2 * nbp],     al, b);
                mma_f16(acc[2 * nbp + 1], al, b + 2);
            }
        }
        __syncthreads();
    }
}

// ---------------------------------------------------------------------------
// QKV GEMM: CTA = (row-tile, head, section). section: 0=Q, 1=K, 2=V.
// ---------------------------------------------------------------------------
__global__ void __launch_bounds__(256, 3) qkv_kernel(const uint32_t* __restrict__ Xh,
                                                     const uint32_t* __restrict__ Xl,
                                                     const uint32_t* __restrict__ W,
                                                     const float* __restrict__ qb,
                                                     const float* __restrict__ kb,
                                                     const float* __restrict__ vb,
                                                     uint32_t* __restrict__ oQh,
                                                     uint32_t* __restrict__ oQl,
                                                     uint32_t* __restrict__ oKh,
                                                     uint32_t* __restrict__ oVt)
{
    extern __shared__ uint32_t sm[];
    const int m0  = blockIdx.x * 128;
    const int h   = blockIdx.y;
    const int sec = blockIdx.z;
    const int tid = threadIdx.x;
    const int wid = tid >> 5, lane = tid & 31, g = lane >> 2, t = lane & 3;
    const int lrow = lane & 7;
    const int aoff = (wid * 16 + lrow + ((lane >> 3) & 1) * 8) * 20 + (lane >> 4) * 4;
    const int boff = (lrow + ((lane >> 4) & 1) * 8) * 20 + ((lane >> 3) & 1) * 4;

    float acc[8][4] = {};

    gemm_core(sm, acc,
              Xh + (size_t)m0 * 512, Xl + (size_t)m0 * 512,
              W + ((size_t)h * 192 + sec * 64) * 512,
              tid, aoff, boff);

    const int r = wid * 16 + g;
    const int grow = m0 + r;

    if (sec == 0) {
        // Q: split fp16, pre-scaled 0.125
        #pragma unroll
        for (int nb = 0; nb < 8; nb++) {
            int col = nb * 8 + 2 * t;
            float b0 = qb[h * DK + col], b1 = qb[h * DK + col + 1];
            uint32_t h0, l0, h1, l1;
            split2h((acc[nb][0] + b0) * 0.125f, (acc[nb][1] + b1) * 0.125f, h0, l0);
            split2h((acc[nb][2] + b0) * 0.125f, (acc[nb][3] + b1) * 0.125f, h1, l1);
            size_t base = ((size_t)h * NN + grow) * QKS + nb * 4 + t;
            oQh[base] = h0;            oQl[base] = l0;
            oQh[base + 8 * QKS] = h1;  oQl[base + 8 * QKS] = l1;
        }
    } else if (sec == 1) {
        // K: single fp16
        #pragma unroll
        for (int nb = 0; nb < 8; nb++) {
            int col = nb * 8 + 2 * t;
            float b0 = kb[h * DK + col], b1 = kb[h * DK + col + 1];
            size_t base = ((size_t)h * NN + grow) * QKS + nb * 4 + t;
            oKh[base]           = pack2h(acc[nb][0] + b0, acc[nb][1] + b1);
            oKh[base + 8 * QKS] = pack2h(acc[nb][2] + b0, acc[nb][3] + b1);
        }
    } else {
        // V: fp16 transpose via smem ([64 dk][132 fp16] = stride 66 u32)
        uint16_t* Vs16 = (uint16_t*)sm;
        #pragma unroll
        for (int nb = 0; nb < 8; nb++) {
            int col = nb * 8 + 2 * t;
            float b0 = vb[h * DK + col], b1 = vb[h * DK + col + 1];
            Vs16[(col)     * 132 + r]     = f16bits(acc[nb][0] + b0);
            Vs16[(col + 1) * 132 + r]     = f16bits(acc[nb][1] + b1);
            Vs16[(col)     * 132 + r + 8] = f16bits(acc[nb][2] + b0);
            Vs16[(col + 1) * 132 + r + 8] = f16bits(acc[nb][3] + b1);
        }
        __syncthreads();
        #pragma unroll
        for (int i = 0; i < 16; i++) {
            int idx = tid + i * 256;
            int dk = idx >> 6, cc = idx & 63;
            oVt[((size_t)h * DK + dk) * (NN / 2) + m0 / 2 + cc] = sm[dk * 66 + cc];
        }
    }
}

// ---------------------------------------------------------------------------
// Out projection + bias + residual: CTA = (row-tile, 64-col tile).
// A = split concat (Ch+Cl), B = Wo single fp16.
// ---------------------------------------------------------------------------
__global__ void __launch_bounds__(256, 3) outproj_kernel(const uint32_t* __restrict__ Ahg,
                                                         const uint32_t* __restrict__ Alg,
                                                         const uint32_t* __restrict__ Bg,
                                                         const float* __restrict__ x,
                                                         const float* __restrict__ ob,
                                                         float* __restrict__ out)
{
    extern __shared__ uint32_t sm[];
    const int m0 = blockIdx.x * 128;
    const int c0 = blockIdx.y * 64;
    const int tid = threadIdx.x;
    const int wid = tid >> 5, lane = tid & 31, g = lane >> 2, t = lane & 3;
    const int lrow = lane & 7;
    const int aoff = (wid * 16 + lrow + ((lane >> 3) & 1) * 8) * 20 + (lane >> 4) * 4;
    const int boff = (lrow + ((lane >> 4) & 1) * 8) * 20 + ((lane >> 3) & 1) * 4;

    float acc[8][4] = {};

    gemm_core(sm, acc,
              Ahg + (size_t)m0 * 512, Alg + (size_t)m0 * 512,
              Bg + (size_t)c0 * 512,
              tid, aoff, boff);

    const int r0 = m0 + wid * 16 + g;
    #pragma unroll
    for (int nb = 0; nb < 8; nb++) {
        int col = c0 + nb * 8 + 2 * t;
        float b0 = ob[col], b1 = ob[col + 1];
        const float* xr0 = &x[(size_t)r0 * DM + col];
        const float* xr1 = &x[(size_t)(r0 + 8) * DM + col];
        float2 v0 = make_float2(acc[nb][0] + b0 + xr0[0], acc[nb][1] + b1 + xr0[1]);
        float2 v1 = make_float2(acc[nb][2] + b0 + xr1[0], acc[nb][3] + b1 + xr1[1]);
        *(float2*)&out[(size_t)r0 * DM + col]       = v0;
        *(float2*)&out[(size_t)(r0 + 8) * DM + col] = v1;
    }
}

// ---------------------------------------------------------------------------
// Flash attention: fp16 QK (2-term, Q split / K single) + fp16 PV.
// buf = Kh[64][36] + Vt[64][36] = 4608 u32 per stage.
// ---------------------------------------------------------------------------
#define ATTN_BUF_U32 (2 * 64 * 36)
#define ATTN_SMEM_BYTES (2 * ATTN_BUF_U32 * 4)

__device__ __forceinline__ void attn_stage(uint32_t* dst, const uint32_t* Kh,
                                           const uint32_t* Vt,
                                           int h, int t0, int tid)
{
    const uint32_t* sKh = Kh + ((size_t)h * NN + t0) * QKS;
    const uint32_t* sVt = Vt + (size_t)h * DK * (NN / 2) + t0 / 2;
    for (int idx = tid; idx < 1088; idx += 256) {
        if (idx < 576) {
            CPA16(dst + idx * 4, sKh + idx * 4);
        } else {
            int j = idx - 576;
            int dk = j >> 3, c = (j & 7) * 4;
            CPA16(dst + 2304 + dk * 36 + c, sVt + (size_t)dk * (NN / 2) + c);
        }
    }
}

__global__ void __launch_bounds__(256, 2) attn_kernel(const uint32_t* __restrict__ Qh,
                                                      const uint32_t* __restrict__ Ql,
                                                      const uint32_t* __restrict__ Kh,
                                                      const uint32_t* __restrict__ Vt,
                                                      uint32_t* __restrict__ Ch,
                                                      uint32_t* __restrict__ Cl)
{
    extern __shared__ uint32_t sm[];
    const int h  = blockIdx.y;
    const int q0 = blockIdx.x * 128;
    const int tid = threadIdx.x;
    const int wid = tid >> 5, lane = tid & 31, g = lane >> 2, t = lane & 3;
    const int lrow = lane & 7;
    const int boff = (lrow + ((lane >> 4) & 1) * 8) * 36 + ((lane >> 3) & 1) * 4;

    attn_stage(sm, Kh, Vt, h, 0, tid);
    CP_COMMIT();

    uint32_t ah[4][4], al[4][4];
    {
        const uint32_t* qh = Qh + ((size_t)h * NN + q0 + wid * 16 + g) * QKS;
        const uint32_t* ql = Ql + ((size_t)h * NN + q0 + wid * 16 + g) * QKS;
        #pragma unroll
        for (int ks = 0; ks < 4; ks++) {
            ah[ks][0] = qh[ks * 8 + t];       ah[ks][1] = qh[8 * QKS + ks * 8 + t];
            ah[ks][2] = qh[ks * 8 + t + 4];   ah[ks][3] = qh[8 * QKS + ks * 8 + t + 4];
            al[ks][0] = ql[ks * 8 + t];       al[ks][1] = ql[8 * QKS + ks * 8 + t];
            al[ks][2] = ql[ks * 8 + t + 4];   al[ks][3] = ql[8 * QKS + ks * 8 + t + 4];
        }
    }

    float o[8][4] = {};
    float m0 = -1e30f, m1 = -1e30f, l0 = 0.f, l1 = 0.f;

    for (int tt = 0; tt < NN / 64; tt++) {
        uint32_t* buf = sm + (tt & 1) * ATTN_BUF_U32;
        if (tt + 1 < NN / 64) {
            attn_stage(sm + ((tt + 1) & 1) * ATTN_BUF_U32, Kh, Vt, h, (tt + 1) * 64, tid);
            CP_COMMIT();
            CP_WAIT(1);
        } else {
            CP_WAIT(0);
        }
        __syncthreads();

        const uint32_t* kh = buf;
        const uint32_t* vs = buf + 2304;

        float s[8][4] = {};
        #pragma unroll
        for (int ks = 0; ks < 4; ks++) {
            // term 1: Q-hi
            #pragma unroll
            for (int nbp = 0; nbp < 4; nbp++) {
                uint32_t b[4];
                ldsm_x4(b, kh + boff + nbp * 576 + ks * 8);
                mma_f16(s[2 * nbp],     ah[ks], b);
                mma_f16(s[2 * nbp + 1], ah[ks], b + 2);
            }
            // term 2: Q-lo
            #pragma unroll
            for (int nbp = 0; nbp < 4; nbp++) {
                uint32_t b[4];
                ldsm_x4(b, kh + boff + nbp * 576 + ks * 8);
                mma_f16(s[2 * nbp],     al[ks], b);
                mma_f16(s[2 * nbp + 1], al[ks], b + 2);
            }
        }

        float mx0 = -1e30f, mx1 = -1e30f;
        #pragma unroll
        for (int nb = 0; nb < 8; nb++) {
            mx0 = fmaxf(mx0, fmaxf(s[nb][0], s[nb][1]));
            mx1 = fmaxf(mx1, fmaxf(s[nb][2], s[nb][3]));
        }
        mx0 = fmaxf(mx0, __shfl_xor_sync(0xffffffffu, mx0, 1));
        mx0 = fmaxf(mx0, __shfl_xor_sync(0xffffffffu, mx0, 2));
        mx1 = fmaxf(mx1, __shfl_xor_sync(0xffffffffu, mx1, 1));
        mx1 = fmaxf(mx1, __shfl_xor_sync(0xffffffffu, mx1, 2));

        float nm0 = fmaxf(m0, mx0), nm1 = fmaxf(m1, mx1);
        float sc0 = __expf(m0 - nm0), sc1 = __expf(m1 - nm1);
        float sum0 = 0.f, sum1 = 0.f;
        #pragma unroll
        for (int nb = 0; nb < 8; nb++) {
            s[nb][0] = __expf(s[nb][0] - nm0);
            s[nb][1] = __expf(s[nb][1] - nm0);
            s[nb][2] = __expf(s[nb][2] - nm1);
            s[nb][3] = __expf(s[nb][3] - nm1);
            sum0 += s[nb][0] + s[nb][1];
            sum1 += s[nb][2] + s[nb][3];
        }
        sum0 += __shfl_xor_sync(0xffffffffu, sum0, 1);
        sum0 += __shfl_xor_sync(0xffffffffu, sum0, 2);
        sum1 += __shfl_xor_sync(0xffffffffu, sum1, 1);
        sum1 += __shfl_xor_sync(0xffffffffu, sum1, 2);
        l0 = l0 * sc0 + sum0;  m0 = nm0;
        l1 = l1 * sc1 + sum1;  m1 = nm1;
        #pragma unroll
        for (int nb = 0; nb < 8; nb++) {
            o[nb][0] *= sc0; o[nb][1] *= sc0;
            o[nb][2] *= sc1; o[nb][3] *= sc1;
        }

        // O += P V (fp16)
        #pragma unroll
        for (int kp = 0; kp < 4; kp++) {
            uint32_t ap[4];
            ap[0] = pack2h(s[2 * kp][0],     s[2 * kp][1]);
            ap[1] = pack2h(s[2 * kp][2],     s[2 * kp][3]);
            ap[2] = pack2h(s[2 * kp + 1][0], s[2 * kp + 1][1]);
            ap[3] = pack2h(s[2 * kp + 1][2], s[2 * kp + 1][3]);
            #pragma unroll
            for (int nbp = 0; nbp < 4; nbp++) {
                uint32_t b[4];
                ldsm_x4(b, vs + boff + nbp * 576 + kp * 8);
                mma_f16(o[2 * nbp],     ap, b);
                mma_f16(o[2 * nbp + 1], ap, b + 2);
            }
        }
        __syncthreads();
    }

    // epilogue: write concat as split fp16 pairs
    const float inv0 = 1.0f / l0, inv1 = 1.0f / l1;
    const int r0 = q0 + wid * 16 + g;
    #pragma unroll
    for (int nb = 0; nb < 8; nb++) {
        int cpi = h * 32 + nb * 4 + t;
        uint32_t h0, lo0, h1, lo1;
        split2h(o[nb][0] * inv0, o[nb][1] * inv0, h0, lo0);
        split2h(o[nb][2] * inv1, o[nb][3] * inv1, h1, lo1);
        Ch[(size_t)r0 * 512 + cpi]       = h0;  Cl[(size_t)r0 * 512 + cpi]       = lo0;
        Ch[(size_t)(r0 + 8) * 512 + cpi] = h1;  Cl[(size_t)(r0 + 8) * 512 + cpi] = lo1;
    }
}

// ---------------------------------------------------------------------------
// LayerNorm, one block per row
// ---------------------------------------------------------------------------
__global__ void __launch_bounds__(256) ln_kernel(const float* __restrict__ pre,
                                                 const float* __restrict__ alpha,
                                                 const float* __restrict__ beta,
                                                 float* __restrict__ out)
{
    const int row = blockIdx.x;
    const int tid = threadIdx.x;
    const float4 v = ((const float4*)(pre + (size_t)row * DM))[tid];

    float sum = v.x + v.y + v.z + v.w;
    float sq  = v.x * v.x + v.y * v.y + v.z * v.z + v.w * v.w;

    #pragma unroll
    for (int d = 16; d >= 1; d >>= 1) {
        sum += __shfl_xor_sync(0xffffffffu, sum, d);
        sq  += __shfl_xor_sync(0xffffffffu, sq,  d);
    }

    __shared__ float ssum[8], ssq[8];
    __shared__ float s_mu, s_rstd;
    int warp = tid >> 5, lane = tid & 31;
    if (lane == 0) { ssum[warp] = sum; ssq[warp] = sq; }
    __syncthreads();
    if (tid == 0) {
        float ts = 0.f, tq = 0.f;
        #pragma unroll
        for (int i = 0; i < 8; i++) { ts += ssum[i]; tq += ssq[i]; }
        float mu  = ts * (1.0f / DM);
        float var = tq * (1.0f / DM) - mu * mu;
        s_mu = mu;
        s_rstd = rsqrtf(var + LN_EPS);
    }
    __syncthreads();

    const float mu = s_mu, rstd = s_rstd;
    const float4 a4 = ((const float4*)alpha)[tid];
    const float4 b4 = ((const float4*)beta)[tid];
    float4 r;
    r.x = a4.x * (v.x - mu) * rstd + b4.x;
    r.y = a4.y * (v.y - mu) * rstd + b4.y;
    r.z = a4.z * (v.z - mu) * rstd + b4.z;
    r.w = a4.w * (v.w - mu) * rstd + b4.w;
    ((float4*)(out + (size_t)row * DM))[tid] = r;
}

// ---------------------------------------------------------------------------
extern "C" void kernel_launch(void* const* d_in, const int* in_sizes, int n_in,
                              void* d_out, int out_size)
{
    const float* x     = (const float*)d_in[0];
    const float* wq    = (const float*)d_in[1];
    const float* qb    = (const float*)d_in[2];
    const float* wk    = (const float*)d_in[3];
    const float* kb    = (const float*)d_in[4];
    const float* wv    = (const float*)d_in[5];
    const float* vb    = (const float*)d_in[6];
    const float* wo    = (const float*)d_in[7];
    const float* ob    = (const float*)d_in[8];
    const float* alpha = (const float*)d_in[9];
    const float* beta  = (const float*)d_in[10];
    float* out = (float*)d_out;

    uint32_t *Xh, *Xl, *Wq, *Wo;
    uint32_t *Qh, *Ql, *Kh, *Vt, *Ch, *Cl;
    float *pre;
    cudaGetSymbolAddress((void**)&Xh,  g_Xh);
    cudaGetSymbolAddress((void**)&Xl,  g_Xl);
    cudaGetSymbolAddress((void**)&Wq,  g_Wq);
    cudaGetSymbolAddress((void**)&Wo,  g_Wo);
    cudaGetSymbolAddress((void**)&Qh,  g_Qh);
    cudaGetSymbolAddress((void**)&Ql,  g_Ql);
    cudaGetSymbolAddress((void**)&Kh,  g_Kh);
    cudaGetSymbolAddress((void**)&Vt,  g_Vt);
    cudaGetSymbolAddress((void**)&Ch,  g_Ch);
    cudaGetSymbolAddress((void**)&Cl,  g_Cl);
    cudaGetSymbolAddress((void**)&pre, g_pre);

    cudaFuncSetAttribute(qkv_kernel,
                         cudaFuncAttributeMaxDynamicSharedMemorySize, G_SMEM);
    cudaFuncSetAttribute(outproj_kernel,
                         cudaFuncAttributeMaxDynamicSharedMemorySize, G_SMEM);
    cudaFuncSetAttribute(attn_kernel,
                         cudaFuncAttributeMaxDynamicSharedMemorySize, ATTN_SMEM_BYTES);

    // conversions
    conv_x_kernel<<<NN, 256>>>(x, Xh, Xl);
    conv_wqkv_kernel<<<dim3(16, 1, 48), 256>>>(wq, wk, wv, Wq);
    conv_wo_kernel<<<dim3(16, 16, 1), 256>>>(wo, Wo);

    qkv_kernel<<<dim3(NN / 128, NH, 3), 256, G_SMEM>>>(Xh, Xl, Wq,
                                                       qb, kb, vb,
                                                       Qh, Ql, Kh, Vt);

    attn_kernel<<<dim3(NN / 128, NH), 256, ATTN_SMEM_BYTES>>>(Qh, Ql, Kh, Vt, Ch, Cl);

    outproj_kernel<<<dim3(NN / 128, DM / 64), 256, G_SMEM>>>(Ch, Cl, Wo,
                                                             x, ob, pre);

    ln_kernel<<<NN, 256>>>(pre, alpha, beta, out);
}